// round 8
// baseline (speedup 1.0000x reference)
#include <cuda_runtime.h>
#include <cuda_fp16.h>
#include <math.h>
#include <stdint.h>

#define S_LEN  2048
#define DMODEL 4096
#define NHEADS 32
#define NKVH   8
#define HDIM   128
#define DFFN   16384

#define LO_SCALE 1024.0f
#define INV_LO   0.0009765625f

// ================= low-level helpers (base sm_103 ISA: ldmatrix/mma/cp.async) =================
__device__ __forceinline__ uint32_t smem_u32(const void* p) {
    uint32_t a;
    asm("{ .reg .u64 t; cvta.to.shared.u64 t, %1; cvt.u32.u64 %0, t; }" : "=r"(a) : "l"(p));
    return a;
}
__device__ __forceinline__ void cp_async16(uint32_t dst, const void* src) {
    asm volatile("cp.async.cg.shared.global [%0], [%1], 16;" :: "r"(dst), "l"(src));
}
#define CP_COMMIT() asm volatile("cp.async.commit_group;" ::: "memory")
#define CP_WAIT1()  asm volatile("cp.async.wait_group 1;" ::: "memory")

__device__ __forceinline__ void ldsm4(uint32_t* r, uint32_t addr) {
    asm volatile("ldmatrix.sync.aligned.m8n8.x4.shared.b16 {%0,%1,%2,%3}, [%4];"
        : "=r"(r[0]), "=r"(r[1]), "=r"(r[2]), "=r"(r[3]) : "r"(addr));
}
__device__ __forceinline__ void ldsm4t(uint32_t* r, uint32_t addr) {
    asm volatile("ldmatrix.sync.aligned.m8n8.x4.trans.shared.b16 {%0,%1,%2,%3}, [%4];"
        : "=r"(r[0]), "=r"(r[1]), "=r"(r[2]), "=r"(r[3]) : "r"(addr));
}
// fp16 inputs, fp32 accumulator
__device__ __forceinline__ void mmaF32(float* d, const uint32_t* a, uint32_t b0, uint32_t b1) {
    asm volatile("mma.sync.aligned.m16n8k16.row.col.f32.f16.f16.f32 "
        "{%0,%1,%2,%3}, {%4,%5,%6,%7}, {%8,%9}, {%0,%1,%2,%3};"
        : "+f"(d[0]), "+f"(d[1]), "+f"(d[2]), "+f"(d[3])
        : "r"(a[0]), "r"(a[1]), "r"(a[2]), "r"(a[3]), "r"(b0), "r"(b1));
}
// fp16 inputs, fp16 accumulator (2 packed regs)
__device__ __forceinline__ void mmaF16(uint32_t* d, const uint32_t* a, uint32_t b0, uint32_t b1) {
    asm volatile("mma.sync.aligned.m16n8k16.row.col.f16.f16.f16.f16 "
        "{%0,%1}, {%2,%3,%4,%5}, {%6,%7}, {%0,%1};"
        : "+r"(d[0]), "+r"(d[1])
        : "r"(a[0]), "r"(a[1]), "r"(a[2]), "r"(a[3]), "r"(b0), "r"(b1));
}

__device__ __forceinline__ uint32_t packh(__half a, __half b) {
    __half2 t = __halves2half2(a, b);
    return *(uint32_t*)&t;
}
// fp16 hi/lo split; lo scaled by ls
__device__ __forceinline__ void split2h(float a, float b, uint32_t& hi, uint32_t& lo, float ls) {
    __half ha = __float2half_rn(a), hb = __float2half_rn(b);
    __half la = __float2half_rn((a - __half2float(ha)) * ls);
    __half lb = __float2half_rn((b - __half2float(hb)) * ls);
    hi = packh(ha, hb);
    lo = packh(la, lb);
}

// ================= scratch (device globals; no allocation allowed) =================
__device__ float g_q   [S_LEN * DMODEL];
__device__ float g_k   [S_LEN * NKVH * HDIM];
__device__ float g_h   [S_LEN * DMODEL];
__device__ float g_gate[S_LEN * DFFN];

// fp16 hi/lo transposed weights: W^T [N, K]  (lo scaled x1024)
__device__ __half g_wqT_h[DMODEL * DMODEL],        g_wqT_l[DMODEL * DMODEL];
__device__ __half g_wkT_h[NKVH * HDIM * DMODEL],   g_wkT_l[NKVH * HDIM * DMODEL];
__device__ __half g_wvT_h[NKVH * HDIM * DMODEL],   g_wvT_l[NKVH * HDIM * DMODEL];
__device__ __half g_woT_h[DMODEL * DMODEL],        g_woT_l[DMODEL * DMODEL];
__device__ __half g_gwT_h[DFFN * DMODEL],          g_gwT_l[DFFN * DMODEL];
__device__ __half g_uwT_h[DFFN * DMODEL],          g_uwT_l[DFFN * DMODEL];
__device__ __half g_dwT_h[DMODEL * DFFN],          g_dwT_l[DMODEL * DFFN];

// fp16 hi/lo activations (GEMM operands lo x1024; attention operands unscaled)
__device__ __half g_xn_h [S_LEN * DMODEL],       g_xn_l [S_LEN * DMODEL];
__device__ __half g_qh  [S_LEN * DMODEL],        g_ql  [S_LEN * DMODEL];
__device__ __half g_kh  [S_LEN * NKVH * HDIM],   g_kl  [S_LEN * NKVH * HDIM];
__device__ __half g_vh  [S_LEN * NKVH * HDIM],   g_vl  [S_LEN * NKVH * HDIM];
__device__ __half g_at_h[S_LEN * DMODEL],        g_at_l[S_LEN * DMODEL];
__device__ __half g_x2_h[S_LEN * DMODEL],        g_x2_l[S_LEN * DMODEL];
__device__ __half g_ga_h[S_LEN * DFFN],          g_ga_l[S_LEN * DFFN];

// ================= RMSNorm -> fp16 hi/lo (scaled) =================
__global__ __launch_bounds__(256) void rmsnorm_split_kernel(
    const float* __restrict__ x, const float* __restrict__ w,
    __half* __restrict__ yh, __half* __restrict__ yl)
{
    int row = blockIdx.x;
    const float* xr = x + (size_t)row * DMODEL;

    float4 vals[4];
    float ss = 0.f;
#pragma unroll
    for (int it = 0; it < 4; it++) {
        int idx = (threadIdx.x + it * 256) * 4;
        float4 v = *(const float4*)(xr + idx);
        vals[it] = v;
        ss += v.x*v.x + v.y*v.y + v.z*v.z + v.w*v.w;
    }
#pragma unroll
    for (int o = 16; o; o >>= 1) ss += __shfl_xor_sync(0xffffffffu, ss, o);

    __shared__ float red[8];
    if ((threadIdx.x & 31) == 0) red[threadIdx.x >> 5] = ss;
    __syncthreads();
    float tot = 0.f;
#pragma unroll
    for (int i = 0; i < 8; i++) tot += red[i];
    float inv = rsqrtf(tot * (1.f / DMODEL) + 1e-5f);

#pragma unroll
    for (int it = 0; it < 4; it++) {
        int idx = (threadIdx.x + it * 256) * 4;
        float4 v  = vals[it];
        float4 wv = *(const float4*)(w + idx);
        float r0 = v.x * inv * wv.x, r1 = v.y * inv * wv.y;
        float r2 = v.z * inv * wv.z, r3 = v.w * inv * wv.w;
        uint2 hv, lv;
        split2h(r0, r1, hv.x, lv.x, LO_SCALE);
        split2h(r2, r3, hv.y, lv.y, LO_SCALE);
        *(uint2*)(yh + (size_t)row * DMODEL + idx) = hv;
        *(uint2*)(yl + (size_t)row * DMODEL + idx) = lv;
    }
}

// ================= RoPE + L2-norm -> fp16 hi/lo (unscaled; feeds attention) =================
__global__ __launch_bounds__(256) void rope_l2_split_kernel(
    const float* __restrict__ in, __half* __restrict__ outh, __half* __restrict__ outl,
    int nheads, const float* __restrict__ cosb, const float* __restrict__ sinb, float scale)
{
    int wid  = (blockIdx.x * 256 + threadIdx.x) >> 5;
    int lane = threadIdx.x & 31;
    int s  = wid / nheads;
    int hh = wid % nheads;
    size_t base = (size_t)s * nheads * HDIM + hh * HDIM + lane * 4;
    float4 vv = *(const float4*)(in + base);

    float c0 = cosb[s * 64 + lane * 2],     s0 = sinb[s * 64 + lane * 2];
    float c1 = cosb[s * 64 + lane * 2 + 1], s1 = sinb[s * 64 + lane * 2 + 1];
    float o0 = vv.x * c0 - vv.y * s0;
    float o1 = vv.x * s0 + vv.y * c0;
    float o2 = vv.z * c1 - vv.w * s1;
    float o3 = vv.z * s1 + vv.w * c1;

    float ss = o0*o0 + o1*o1 + o2*o2 + o3*o3;
#pragma unroll
    for (int o = 16; o; o >>= 1) ss += __shfl_xor_sync(0xffffffffu, ss, o);
    float rr = rsqrtf(ss * (1.f / HDIM) + 1e-5f) * scale;
    o0 *= rr; o1 *= rr; o2 *= rr; o3 *= rr;

    uint2 hv, lv;
    split2h(o0, o1, hv.x, lv.x, 1.f);
    split2h(o2, o3, hv.y, lv.y, 1.f);
    *(uint2*)(outh + base) = hv;
    *(uint2*)(outl + base) = lv;
}

// ================= transpose + fp16 hi/lo split (scaled): in[K,N] fp32 -> [N,K] =================
__global__ __launch_bounds__(256) void transpose_split_kernel(
    const float* __restrict__ in, __half* __restrict__ hi, __half* __restrict__ lo,
    int K, int N)
{
    __shared__ float s[64][65];
    int r0 = blockIdx.y * 64, c0 = blockIdx.x * 64;
#pragma unroll
    for (int i = 0; i < 8; i++) {
        int idx = threadIdx.x + i * 256;
        int lr = idx >> 5, p = idx & 31;
        float2 v = *(const float2*)(in + (size_t)(r0 + lr) * N + c0 + 2 * p);
        s[lr][2 * p]     = v.x;
        s[lr][2 * p + 1] = v.y;
    }
    __syncthreads();
#pragma unroll
    for (int i = 0; i < 8; i++) {
        int idx = threadIdx.x + i * 256;
        int lr = idx >> 5, p = idx & 31;
        float a = s[2 * p][lr];
        float b = s[2 * p + 1][lr];
        uint32_t hv, lv;
        split2h(a, b, hv, lv, LO_SCALE);
        size_t o = (size_t)(c0 + lr) * K + (r0 + 2 * p);
        *(uint32_t*)(hi + o) = hv;
        *(uint32_t*)(lo + o) = lv;
    }
}

// ================= HMMA split-fp16 GEMM =================
// C = A @ B^T; main Ah.Bh (f32 acc) + corrections (Ah.Bl + Al.Bh) in f16 acc (x1024 scale),
// promoted to fp32 per K=64 chunk. CTA 128x128, 3-stage cp.async, 8 warps @64x32.
#define TCG_STAGE_BYTES 65536
#define TCG_NSTAGE 3
#define TCG_SMEM (TCG_NSTAGE * TCG_STAGE_BYTES)

__global__ __launch_bounds__(256, 1) void tc_gemm_kernel(
    const __half* __restrict__ Ahi, const __half* __restrict__ Alo,
    const __half* __restrict__ Bhi, const __half* __restrict__ Blo,
    float* __restrict__ C, const float* __restrict__ addend,
    __half* __restrict__ outHi, __half* __restrict__ outLo, float outLoScale,
    const float* __restrict__ gateMul,
    int M, int N, int K)
{
    extern __shared__ char sm[];
    uint32_t sbase = smem_u32(sm);
    int tid = threadIdx.x, lane = tid & 31, wid = tid >> 5;
    int warp_m = wid & 1, warp_n = wid >> 1;
    int by = blockIdx.x, bx = blockIdx.y;   // M-block fastest

    const __half* srcA[2] = { Ahi + (size_t)(by * 128) * K, Alo + (size_t)(by * 128) * K };
    const __half* srcB[2] = { Bhi + (size_t)(bx * 128) * K, Blo + (size_t)(bx * 128) * K };

    int nchunk = K >> 6;
    int ldrow = tid >> 3;
    int ldc16 = tid & 7;

    auto load_stage = [&](int stg, int c) {
        uint32_t dst0 = sbase + stg * TCG_STAGE_BYTES;
        int kc = c << 6;
#pragma unroll
        for (int hl = 0; hl < 2; hl++) {
            const __half* sa = srcA[hl] + kc;
            const __half* sb = srcB[hl] + kc;
            uint32_t da = dst0 + hl * 16384;
            uint32_t db = dst0 + 32768 + hl * 16384;
#pragma unroll
            for (int i = 0; i < 4; i++) {
                int row = ldrow + i * 32;
                uint32_t sw = row * 128 + ((ldc16 ^ (row & 7)) << 4);
                cp_async16(da + sw, sa + (size_t)row * K + ldc16 * 8);
                cp_async16(db + sw, sb + (size_t)row * K + ldc16 * 8);
            }
        }
    };

    load_stage(0, 0); CP_COMMIT();
    load_stage(1, 1); CP_COMMIT();

    float acc[4][4][4];
    uint32_t cacc[4][4][2];
#pragma unroll
    for (int a = 0; a < 4; a++)
#pragma unroll
        for (int b = 0; b < 4; b++) {
#pragma unroll
            for (int f = 0; f < 4; f++) acc[a][b][f] = 0.f;
            cacc[a][b][0] = 0u; cacc[a][b][1] = 0u;
        }

    int a_r   = warp_m * 64 + (lane & 15);
    int a_kh  = lane >> 4;
    int b_r   = warp_n * 32 + (lane & 7) + ((lane >> 4) << 3);
    int b_kh  = (lane >> 3) & 1;

    for (int c = 0; c < nchunk; c++) {
        CP_WAIT1();
        __syncthreads();
        if (c + 2 < nchunk) load_stage((c + 2) % TCG_NSTAGE, c + 2);
        CP_COMMIT();

        uint32_t st = sbase + (c % TCG_NSTAGE) * TCG_STAGE_BYTES;
#pragma unroll
        for (int kk = 0; kk < 4; kk++) {
            int c16 = kk * 2;
            uint32_t ah[4][4], al[4][4], bh[2][4], bl[2][4];
#pragma unroll
            for (int mb = 0; mb < 4; mb++) {
                int r = a_r + mb * 16;
                uint32_t off = r * 128 + (((c16 + a_kh) ^ (r & 7)) << 4);
                ldsm4(ah[mb], st + off);
                ldsm4(al[mb], st + 16384 + off);
            }
#pragma unroll
            for (int nb = 0; nb < 2; nb++) {
                int r = b_r + nb * 16;
                uint32_t off = r * 128 + (((c16 + b_kh) ^ (r & 7)) << 4);
                ldsm4(bh[nb], st + 32768 + off);
                ldsm4(bl[nb], st + 49152 + off);
            }
#pragma unroll
            for (int mb = 0; mb < 4; mb++)
#pragma unroll
                for (int nb = 0; nb < 4; nb++) {
                    uint32_t b0h = bh[nb >> 1][(nb & 1) * 2], b1h = bh[nb >> 1][(nb & 1) * 2 + 1];
                    uint32_t b0l = bl[nb >> 1][(nb & 1) * 2], b1l = bl[nb >> 1][(nb & 1) * 2 + 1];
                    mmaF32(acc[mb][nb], ah[mb], b0h, b1h);
                    mmaF16(cacc[mb][nb], ah[mb], b0l, b1l);
                    mmaF16(cacc[mb][nb], al[mb], b0h, b1h);
                }
        }
        // promote f16 corrections into fp32 accumulators (x 1/1024)
#pragma unroll
        for (int mb = 0; mb < 4; mb++)
#pragma unroll
            for (int nb = 0; nb < 4; nb++) {
                __half2 h01 = *(__half2*)&cacc[mb][nb][0];
                __half2 h23 = *(__half2*)&cacc[mb][nb][1];
                float2 f01 = __half22float2(h01);
                float2 f23 = __half22float2(h23);
                acc[mb][nb][0] = fmaf(f01.x, INV_LO, acc[mb][nb][0]);
                acc[mb][nb][1] = fmaf(f01.y, INV_LO, acc[mb][nb][1]);
                acc[mb][nb][2] = fmaf(f23.x, INV_LO, acc[mb][nb][2]);
                acc[mb][nb][3] = fmaf(f23.y, INV_LO, acc[mb][nb][3]);
                cacc[mb][nb][0] = 0u; cacc[mb][nb][1] = 0u;
            }
        __syncthreads();
    }

#pragma unroll
    for (int mb = 0; mb < 4; mb++) {
        int mrow = by * 128 + warp_m * 64 + mb * 16 + (lane >> 2);
#pragma unroll
        for (int nb = 0; nb < 4; nb++) {
            int ncol = bx * 128 + warp_n * 32 + nb * 8 + (lane & 3) * 2;
            size_t i0 = (size_t)mrow * N + ncol;
            size_t i1 = (size_t)(mrow + 8) * N + ncol;
            float2 r0 = make_float2(acc[mb][nb][0], acc[mb][nb][1]);
            float2 r1 = make_float2(acc[mb][nb][2], acc[mb][nb][3]);
            if (addend) {
                float2 a0 = *(const float2*)(addend + i0);
                float2 a1 = *(const float2*)(addend + i1);
                r0.x += a0.x; r0.y += a0.y;
                r1.x += a1.x; r1.y += a1.y;
            }
            if (gateMul) {
                float2 g0 = *(const float2*)(gateMul + i0);
                float2 g1 = *(const float2*)(gateMul + i1);
                r0.x *= g0.x / (1.f + __expf(-g0.x));
                r0.y *= g0.y / (1.f + __expf(-g0.y));
                r1.x *= g1.x / (1.f + __expf(-g1.x));
                r1.y *= g1.y / (1.f + __expf(-g1.y));
            }
            if (C) {
                *(float2*)(C + i0) = r0;
                *(float2*)(C + i1) = r1;
            }
            if (outHi) {
                uint32_t h0, l0, h1, l1;
                split2h(r0.x, r0.y, h0, l0, outLoScale);
                split2h(r1.x, r1.y, h1, l1, outLoScale);
                *(uint32_t*)(outHi + i0) = h0;
                *(uint32_t*)(outLo + i0) = l0;
                *(uint32_t*)(outHi + i1) = h1;
                *(uint32_t*)(outLo + i1) = l1;
            }
        }
    }
}

// ================= HMMA causal flash attention, GQA, split-fp16 =================
#define FA_STAGE_OFF 32768
#define FA_STAGE_BYTES 65536
#define FA_SMEM (FA_STAGE_OFF + 2 * FA_STAGE_BYTES)   // 160KB

__global__ __launch_bounds__(128, 1) void flash_attn_kernel(
    const __half* __restrict__ qh, const __half* __restrict__ ql,
    const __half* __restrict__ kh, const __half* __restrict__ kl,
    const __half* __restrict__ vh, const __half* __restrict__ vl,
    __half* __restrict__ oh, __half* __restrict__ ol)
{
    extern __shared__ char sm[];
    uint32_t sbase = smem_u32(sm);
    int qb = blockIdx.x, h = blockIdx.y, kvh = h >> 2;
    int tid = threadIdx.x, lane = tid & 31, w = tid >> 5;

#pragma unroll
    for (int i = 0; i < 8; i++) {
        int u = tid + i * 128;
        int row = u >> 4, c16 = u & 15;
        uint32_t dst = sbase + row * 256 + ((c16 ^ (row & 7)) << 4);
        size_t srco = (size_t)(qb * 64 + row) * DMODEL + h * HDIM + c16 * 8;
        cp_async16(dst,         qh + srco);
        cp_async16(dst + 16384, ql + srco);
    }

    auto load_kv = [&](int stg, int kb) {
        uint32_t dst0 = sbase + FA_STAGE_OFF + stg * FA_STAGE_BYTES;
        const __half* srcs[4] = { kh, kl, vh, vl };
#pragma unroll
        for (int b = 0; b < 4; b++) {
            const __half* s = srcs[b];
#pragma unroll
            for (int i = 0; i < 8; i++) {
                int u = tid + i * 128;
                int row = u >> 4, c16 = u & 15;
                uint32_t dst = dst0 + b * 16384 + row * 256 + ((c16 ^ (row & 7)) << 4);
                cp_async16(dst, s + (size_t)(kb * 64 + row) * (NKVH * HDIM) + kvh * HDIM + c16 * 8);
            }
        }
    };

    load_kv(0, 0); CP_COMMIT();
    if (qb >= 1) load_kv(1, 1);
    CP_COMMIT();

    float O[16][4];
#pragma unroll
    for (int i = 0; i < 16; i++)
#pragma unroll
        for (int f = 0; f < 4; f++) O[i][f] = 0.f;
    float m_lo = -1e30f, m_hi = -1e30f, l_lo = 0.f, l_hi = 0.f;

    int r_loc = w * 16 + (lane >> 2);

    for (int kb = 0; kb <= qb; kb++) {
        CP_WAIT1();
        __syncthreads();
        uint32_t kbase = sbase + FA_STAGE_OFF + (kb & 1) * FA_STAGE_BYTES;

        float S[8][4];
#pragma unroll
        for (int i = 0; i < 8; i++)
#pragma unroll
            for (int f = 0; f < 4; f++) S[i][f] = 0.f;

#pragma unroll
        for (int kk = 0; kk < 8; kk++) {
            uint32_t aqh[4], aql[4];
            int ar = w * 16 + (lane & 15);
            int ac = kk * 2 + (lane >> 4);
            uint32_t aoff = ar * 256 + ((ac ^ (ar & 7)) << 4);
            ldsm4(aqh, sbase + aoff);
            ldsm4(aql, sbase + 16384 + aoff);
#pragma unroll
            for (int nblk = 0; nblk < 4; nblk++) {
                int br = nblk * 16 + (lane & 7) + ((lane >> 4) << 3);
                int bc = kk * 2 + ((lane >> 3) & 1);
                uint32_t boff = br * 256 + ((bc ^ (br & 7)) << 4);
                uint32_t bh4[4], bl4[4];
                ldsm4(bh4, kbase + boff);
                ldsm4(bl4, kbase + 16384 + boff);
                mmaF32(S[2*nblk],   aqh, bh4[0], bh4[1]);
                mmaF32(S[2*nblk],   aqh, bl4[0], bl4[1]);
                mmaF32(S[2*nblk],   aql, bh4[0], bh4[1]);
                mmaF32(S[2*nblk+1], aqh, bh4[2], bh4[3]);
                mmaF32(S[2*nblk+1], aqh, bl4[2], bl4[3]);
                mmaF32(S[2*nblk+1], aql, bh4[2], bh4[3]);
            }
        }

        if (kb == qb) {
#pragma unroll
            for (int nt = 0; nt < 8; nt++) {
                int c = nt * 8 + (lane & 3) * 2;
                if (c     > r_loc)     S[nt][0] = -1e30f;
                if (c + 1 > r_loc)     S[nt][1] = -1e30f;
                if (c     > r_loc + 8) S[nt][2] = -1e30f;
                if (c + 1 > r_loc + 8) S[nt][3] = -1e30f;
            }
        }

        float rm_lo = -1e30f, rm_hi = -1e30f;
#pragma unroll
        for (int nt = 0; nt < 8; nt++) {
            rm_lo = fmaxf(rm_lo, fmaxf(S[nt][0], S[nt][1]));
            rm_hi = fmaxf(rm_hi, fmaxf(S[nt][2], S[nt][3]));
        }
        rm_lo = fmaxf(rm_lo, __shfl_xor_sync(0xffffffffu, rm_lo, 1));
        rm_lo = fmaxf(rm_lo, __shfl_xor_sync(0xffffffffu, rm_lo, 2));
        rm_hi = fmaxf(rm_hi, __shfl_xor_sync(0xffffffffu, rm_hi, 1));
        rm_hi = fmaxf(rm_hi, __shfl_xor_sync(0xffffffffu, rm_hi, 2));
        float mn_lo = fmaxf(m_lo, rm_lo), mn_hi = fmaxf(m_hi, rm_hi);
        float corr_lo = __expf(m_lo - mn_lo), corr_hi = __expf(m_hi - mn_hi);

        uint32_t ph[8][2], pl[8][2];
        float sum_lo = 0.f, sum_hi = 0.f;
#pragma unroll
        for (int nt = 0; nt < 8; nt++) {
            float p0 = __expf(S[nt][0] - mn_lo);
            float p1 = __expf(S[nt][1] - mn_lo);
            float p2 = __expf(S[nt][2] - mn_hi);
            float p3 = __expf(S[nt][3] - mn_hi);
            sum_lo += p0 + p1; sum_hi += p2 + p3;
            split2h(p0, p1, ph[nt][0], pl[nt][0], 1.f);
            split2h(p2, p3, ph[nt][1], pl[nt][1], 1.f);
        }
        sum_lo += __shfl_xor_sync(0xffffffffu, sum_lo, 1);
        sum_lo += __shfl_xor_sync(0xffffffffu, sum_lo, 2);
        sum_hi += __shfl_xor_sync(0xffffffffu, sum_hi, 1);
        sum_hi += __shfl_xor_sync(0xffffffffu, sum_hi, 2);
        l_lo = l_lo * corr_lo + sum_lo;
        l_hi = l_hi * corr_hi + sum_hi;
        m_lo = mn_lo; m_hi = mn_hi;
#pragma unroll
        for (int ot = 0; ot < 16; ot++) {
            O[ot][0] *= corr_lo; O[ot][1] *= corr_lo;
            O[ot][2] *= corr_hi; O[ot][3] *= corr_hi;
        }

        uint32_t vbase = kbase + 32768;
#pragma unroll
        for (int kt = 0; kt < 4; kt++) {
            uint32_t aH[4] = { ph[2*kt][0], ph[2*kt][1], ph[2*kt+1][0], ph[2*kt+1][1] };
            uint32_t aL[4] = { pl[2*kt][0], pl[2*kt][1], pl[2*kt+1][0], pl[2*kt+1][1] };
            int krow = kt * 16 + (lane & 7) + ((lane >> 3) & 1) * 8;
#pragma unroll
            for (int ob = 0; ob < 8; ob++) {
                int cu = ob * 2 + (lane >> 4);
                uint32_t off = krow * 256 + ((cu ^ (krow & 7)) << 4);
                uint32_t bvh[4], bvl[4];
                ldsm4t(bvh, vbase + off);
                ldsm4t(bvl, vbase + 16384 + off);
                mmaF32(O[2*ob],   aH, bvh[0], bvh[1]);
                mmaF32(O[2*ob],   aH, bvl[0], bvl[1]);
                mmaF32(O[2*ob],   aL, bvh[0], bvh[1]);
                mmaF32(O[2*ob+1], aH, bvh[2], bvh[3]);
                mmaF32(O[2*ob+1], aH, bvl[2], bvl[3]);
                mmaF32(O[2*ob+1], aL, bvh[2], bvh[3]);
            }
        }

        __syncthreads();
        if (kb + 2 <= qb) load_kv(kb & 1, kb + 2);
        CP_COMMIT();
    }

    float il_lo = 1.f / l_lo, il_hi = 1.f / l_hi;
    int row0 = qb * 64 + r_loc;
#pragma unroll
    for (int ot = 0; ot < 16; ot++) {
        int col = h * HDIM + ot * 8 + (lane & 3) * 2;
        float o0 = O[ot][0] * il_lo, o1 = O[ot][1] * il_lo;
        float o2 = O[ot][2] * il_hi, o3 = O[ot][3] * il_hi;
        uint32_t h0, l0, h1, l1;
        split2h(o0, o1, h0, l0, LO_SCALE);
        split2h(o2, o3, h1, l1, LO_SCALE);
        size_t i0 = (size_t)row0 * DMODEL + col;
        size_t i1 = (size_t)(row0 + 8) * DMODEL + col;
        *(uint32_t*)(oh + i0) = h0;
        *(uint32_t*)(ol + i0) = l0;
        *(uint32_t*)(oh + i1) = h1;
        *(uint32_t*)(ol + i1) = l1;
    }
}

// ================= host launcher =================
extern "C" void kernel_launch(void* const* d_in, const int* in_sizes, int n_in,
                              void* d_out, int out_size)
{
    const float* hidden = (const float*)d_in[0];
    const float* cosb  = (const float*)d_in[2];
    const float* sinb  = (const float*)d_in[3];
    const float* ln1   = (const float*)d_in[4];
    const float* wq    = (const float*)d_in[5];
    const float* wk    = (const float*)d_in[6];
    const float* wv    = (const float*)d_in[7];
    const float* wo    = (const float*)d_in[8];
    const float* ln2   = (const float*)d_in[9];
    const float* gatew = (const float*)d_in[10];
    const float* upw   = (const float*)d_in[11];
    const float* downw = (const float*)d_in[12];
    float* out = (float*)d_out;

    float *q, *k, *h, *gate;
    cudaGetSymbolAddress((void**)&q,    g_q);
    cudaGetSymbolAddress((void**)&k,    g_k);
    cudaGetSymbolAddress((void**)&h,    g_h);
    cudaGetSymbolAddress((void**)&gate, g_gate);

    __half *wqTh,*wqTl,*wkTh,*wkTl,*wvTh,*wvTl,*woTh,*woTl,*gwTh,*gwTl,*uwTh,*uwTl,*dwTh,*dwTl;
    cudaGetSymbolAddress((void**)&wqTh, g_wqT_h); cudaGetSymbolAddress((void**)&wqTl, g_wqT_l);
    cudaGetSymbolAddress((void**)&wkTh, g_wkT_h); cudaGetSymbolAddress((void**)&wkTl, g_wkT_l);
    cudaGetSymbolAddress((void**)&wvTh, g_wvT_h); cudaGetSymbolAddress((void**)&wvTl, g_wvT_l);
    cudaGetSymbolAddress((void**)&woTh, g_woT_h); cudaGetSymbolAddress((void**)&woTl, g_woT_l);
    cudaGetSymbolAddress((void**)&gwTh, g_gwT_h); cudaGetSymbolAddress((void**)&gwTl, g_gwT_l);
    cudaGetSymbolAddress((void**)&uwTh, g_uwT_h); cudaGetSymbolAddress((void**)&uwTl, g_uwT_l);
    cudaGetSymbolAddress((void**)&dwTh, g_dwT_h); cudaGetSymbolAddress((void**)&dwTl, g_dwT_l);

    __half *xnh,*xnl,*qhp,*qlp,*khp,*klp,*vhp,*vlp,*ath,*atl,*x2h,*x2l,*gah,*gal;
    cudaGetSymbolAddress((void**)&xnh, g_xn_h); cudaGetSymbolAddress((void**)&xnl, g_xn_l);
    cudaGetSymbolAddress((void**)&qhp, g_qh);   cudaGetSymbolAddress((void**)&qlp, g_ql);
    cudaGetSymbolAddress((void**)&khp, g_kh);   cudaGetSymbolAddress((void**)&klp, g_kl);
    cudaGetSymbolAddress((void**)&vhp, g_vh);   cudaGetSymbolAddress((void**)&vlp, g_vl);
    cudaGetSymbolAddress((void**)&ath, g_at_h); cudaGetSymbolAddress((void**)&atl, g_at_l);
    cudaGetSymbolAddress((void**)&x2h, g_x2_h); cudaGetSymbolAddress((void**)&x2l, g_x2_l);
    cudaGetSymbolAddress((void**)&gah, g_ga_h); cudaGetSymbolAddress((void**)&gal, g_ga_l);

    cudaFuncSetAttribute(tc_gemm_kernel, cudaFuncAttributeMaxDynamicSharedMemorySize, TCG_SMEM);
    cudaFuncSetAttribute(flash_attn_kernel, cudaFuncAttributeMaxDynamicSharedMemorySize, FA_SMEM);

    // ---- weight transposes + fp16 hi/lo splits ----
    transpose_split_kernel<<<dim3(DMODEL/64, DMODEL/64), 256>>>(wq, wqTh, wqTl, DMODEL, DMODEL);
    transpose_split_kernel<<<dim3(NKVH*HDIM/64, DMODEL/64), 256>>>(wk, wkTh, wkTl, DMODEL, NKVH*HDIM);
    transpose_split_kernel<<<dim3(NKVH*HDIM/64, DMODEL/64), 256>>>(wv, wvTh, wvTl, DMODEL, NKVH*HDIM);
    transpose_split_kernel<<<dim3(DMODEL/64, DMODEL/64), 256>>>(wo, woTh, woTl, DMODEL, DMODEL);
    transpose_split_kernel<<<dim3(DFFN/64, DMODEL/64), 256>>>(gatew, gwTh, gwTl, DMODEL, DFFN);
    transpose_split_kernel<<<dim3(DFFN/64, DMODEL/64), 256>>>(upw,   uwTh, uwTl, DMODEL, DFFN);
    transpose_split_kernel<<<dim3(DMODEL/64, DFFN/64), 256>>>(downw, dwTh, dwTl, DFFN, DMODEL);

    // 1) x = rmsnorm(hidden, ln1) -> fp16 hi/lo (scaled)
    rmsnorm_split_kernel<<<S_LEN, 256>>>(hidden, ln1, xnh, xnl);

    // 2) q/k fp32 (for rope); v -> fp16 hi/lo UNscaled (feeds attention)
    tc_gemm_kernel<<<dim3(S_LEN/128, DMODEL/128), 256, TCG_SMEM>>>(xnh, xnl, wqTh, wqTl, q, nullptr, nullptr, nullptr, 1.f, nullptr, S_LEN, DMODEL, DMODEL);
    tc_gemm_kernel<<<dim3(S_LEN/128, NKVH*HDIM/128), 256, TCG_SMEM>>>(xnh, xnl, wkTh, wkTl, k, nullptr, nullptr, nullptr, 1.f, nullptr, S_LEN, NKVH*HDIM, DMODEL);
    tc_gemm_kernel<<<dim3(S_LEN/128, NKVH*HDIM/128), 256, TCG_SMEM>>>(xnh, xnl, wvTh, wvTl, nullptr, nullptr, vhp, vlp, 1.f, nullptr, S_LEN, NKVH*HDIM, DMODEL);

    // 3) RoPE + L2-norm -> fp16 hi/lo unscaled; fold HD^-0.5 into q
    const float qscale = 0.08838834764831845f;
    rope_l2_split_kernel<<<S_LEN * NHEADS / 8, 256>>>(q, qhp, qlp, NHEADS, cosb, sinb, qscale);
    rope_l2_split_kernel<<<S_LEN * NKVH  / 8, 256>>>(k, khp, klp, NKVH,  cosb, sinb, 1.f);

    // 4) HMMA causal flash attention -> attn fp16 hi/lo (lo scaled: feeds wo GEMM)
    flash_attn_kernel<<<dim3(S_LEN / 64, NHEADS), 128, FA_SMEM>>>(qhp, qlp, khp, klp, vhp, vlp, ath, atl);

    // 5) h = hidden + attn @ wo (fp32)
    tc_gemm_kernel<<<dim3(S_LEN/128, DMODEL/128), 256, TCG_SMEM>>>(ath, atl, woTh, woTl, h, hidden, nullptr, nullptr, 1.f, nullptr, S_LEN, DMODEL, DMODEL);

    // 6) x2 = rmsnorm(h, ln2) -> fp16 hi/lo (scaled)
    rmsnorm_split_kernel<<<S_LEN, 256>>>(h, ln2, x2h, x2l);

    // 7) FFN: gate fp32; up with fused silu(gate)*up -> fp16 hi/lo (scaled: feeds down GEMM)
    tc_gemm_kernel<<<dim3(S_LEN/128, DFFN/128), 256, TCG_SMEM>>>(x2h, x2l, gwTh, gwTl, gate, nullptr, nullptr, nullptr, 1.f, nullptr, S_LEN, DFFN, DMODEL);
    tc_gemm_kernel<<<dim3(S_LEN/128, DFFN/128), 256, TCG_SMEM>>>(x2h, x2l, uwTh, uwTl, nullptr, nullptr, gah, gal, LO_SCALE, gate, S_LEN, DFFN, DMODEL);

    // 8) out = h + act @ down
    tc_gemm_kernel<<<dim3(S_LEN/128, DMODEL/128), 256, TCG_SMEM>>>(gah, gal, dwTh, dwTl, out, h, nullptr, nullptr, 1.f, nullptr, S_LEN, DMODEL, DFFN);
}

// round 9
// speedup vs baseline: 1.3073x; 1.3073x over previous
#include <cuda_runtime.h>
#include <cuda_fp16.h>
#include <math.h>
#include <stdint.h>

#define S_LEN  2048
#define DMODEL 4096
#define NHEADS 32
#define NKVH   8
#define HDIM   128
#define DFFN   16384

#define LO_SCALE 1024.0f
#define INV_LO   0.0009765625f

// ================= low-level helpers (base sm_103 ISA: ldmatrix/mma/cp.async) =================
__device__ __forceinline__ uint32_t smem_u32(const void* p) {
    uint32_t a;
    asm("{ .reg .u64 t; cvta.to.shared.u64 t, %1; cvt.u32.u64 %0, t; }" : "=r"(a) : "l"(p));
    return a;
}
__device__ __forceinline__ void cp_async16(uint32_t dst, const void* src) {
    asm volatile("cp.async.cg.shared.global [%0], [%1], 16;" :: "r"(dst), "l"(src));
}
#define CP_COMMIT() asm volatile("cp.async.commit_group;" ::: "memory")
#define CP_WAIT1()  asm volatile("cp.async.wait_group 1;" ::: "memory")

__device__ __forceinline__ void ldsm4(uint32_t* r, uint32_t addr) {
    asm volatile("ldmatrix.sync.aligned.m8n8.x4.shared.b16 {%0,%1,%2,%3}, [%4];"
        : "=r"(r[0]), "=r"(r[1]), "=r"(r[2]), "=r"(r[3]) : "r"(addr));
}
__device__ __forceinline__ void ldsm4t(uint32_t* r, uint32_t addr) {
    asm volatile("ldmatrix.sync.aligned.m8n8.x4.trans.shared.b16 {%0,%1,%2,%3}, [%4];"
        : "=r"(r[0]), "=r"(r[1]), "=r"(r[2]), "=r"(r[3]) : "r"(addr));
}
__device__ __forceinline__ void mmaF32(float* d, const uint32_t* a, uint32_t b0, uint32_t b1) {
    asm volatile("mma.sync.aligned.m16n8k16.row.col.f32.f16.f16.f32 "
        "{%0,%1,%2,%3}, {%4,%5,%6,%7}, {%8,%9}, {%0,%1,%2,%3};"
        : "+f"(d[0]), "+f"(d[1]), "+f"(d[2]), "+f"(d[3])
        : "r"(a[0]), "r"(a[1]), "r"(a[2]), "r"(a[3]), "r"(b0), "r"(b1));
}
__device__ __forceinline__ void mmaF16(uint32_t* d, const uint32_t* a, uint32_t b0, uint32_t b1) {
    asm volatile("mma.sync.aligned.m16n8k16.row.col.f16.f16.f16.f16 "
        "{%0,%1}, {%2,%3,%4,%5}, {%6,%7}, {%0,%1};"
        : "+r"(d[0]), "+r"(d[1])
        : "r"(a[0]), "r"(a[1]), "r"(a[2]), "r"(a[3]), "r"(b0), "r"(b1));
}

__device__ __forceinline__ uint32_t packh(__half a, __half b) {
    __half2 t = __halves2half2(a, b);
    return *(uint32_t*)&t;
}
__device__ __forceinline__ void split2h(float a, float b, uint32_t& hi, uint32_t& lo, float ls) {
    __half ha = __float2half_rn(a), hb = __float2half_rn(b);
    __half la = __float2half_rn((a - __half2float(ha)) * ls);
    __half lb = __float2half_rn((b - __half2float(hb)) * ls);
    hi = packh(ha, hb);
    lo = packh(la, lb);
}

// ================= scratch (device globals; no allocation allowed) =================
__device__ float g_q   [S_LEN * DMODEL];
__device__ float g_k   [S_LEN * NKVH * HDIM];
__device__ float g_h   [S_LEN * DMODEL];
__device__ float g_gate[S_LEN * DFFN];

// fp16 hi/lo transposed weights: W^T [N, K] (lo x1024)
__device__ __half g_wqT_h[DMODEL * DMODEL],        g_wqT_l[DMODEL * DMODEL];
__device__ __half g_wkT_h[NKVH * HDIM * DMODEL],   g_wkT_l[NKVH * HDIM * DMODEL];
__device__ __half g_wvT_h[NKVH * HDIM * DMODEL],   g_wvT_l[NKVH * HDIM * DMODEL];
__device__ __half g_woT_h[DMODEL * DMODEL],        g_woT_l[DMODEL * DMODEL];
__device__ __half g_gwT_h[DFFN * DMODEL],          g_gwT_l[DFFN * DMODEL];
__device__ __half g_uwT_h[DFFN * DMODEL],          g_uwT_l[DFFN * DMODEL];
__device__ __half g_dwT_h[DMODEL * DFFN],          g_dwT_l[DMODEL * DFFN];

// activations: single fp16 (GEMM A operands)
__device__ __half g_xn[S_LEN * DMODEL];
__device__ __half g_at[S_LEN * DMODEL];
__device__ __half g_x2[S_LEN * DMODEL];
__device__ __half g_ga[S_LEN * DFFN];

// attention operands: fp16 hi/lo (unscaled lo)
__device__ __half g_qh[S_LEN * DMODEL],      g_ql[S_LEN * DMODEL];
__device__ __half g_kh[S_LEN * NKVH * HDIM], g_kl[S_LEN * NKVH * HDIM];
__device__ __half g_vh[S_LEN * NKVH * HDIM], g_vl[S_LEN * NKVH * HDIM];

// ================= RMSNorm -> single fp16 =================
__global__ __launch_bounds__(256) void rmsnorm_h_kernel(
    const float* __restrict__ x, const float* __restrict__ w, __half* __restrict__ y)
{
    int row = blockIdx.x;
    const float* xr = x + (size_t)row * DMODEL;

    float4 vals[4];
    float ss = 0.f;
#pragma unroll
    for (int it = 0; it < 4; it++) {
        int idx = (threadIdx.x + it * 256) * 4;
        float4 v = *(const float4*)(xr + idx);
        vals[it] = v;
        ss += v.x*v.x + v.y*v.y + v.z*v.z + v.w*v.w;
    }
#pragma unroll
    for (int o = 16; o; o >>= 1) ss += __shfl_xor_sync(0xffffffffu, ss, o);

    __shared__ float red[8];
    if ((threadIdx.x & 31) == 0) red[threadIdx.x >> 5] = ss;
    __syncthreads();
    float tot = 0.f;
#pragma unroll
    for (int i = 0; i < 8; i++) tot += red[i];
    float inv = rsqrtf(tot * (1.f / DMODEL) + 1e-5f);

#pragma unroll
    for (int it = 0; it < 4; it++) {
        int idx = (threadIdx.x + it * 256) * 4;
        float4 v  = vals[it];
        float4 wv = *(const float4*)(w + idx);
        uint2 hv;
        hv.x = packh(__float2half_rn(v.x * inv * wv.x), __float2half_rn(v.y * inv * wv.y));
        hv.y = packh(__float2half_rn(v.z * inv * wv.z), __float2half_rn(v.w * inv * wv.w));
        *(uint2*)(y + (size_t)row * DMODEL + idx) = hv;
    }
}

// ================= RoPE + L2-norm -> fp16 hi/lo (unscaled; feeds attention) =================
__global__ __launch_bounds__(256) void rope_l2_split_kernel(
    const float* __restrict__ in, __half* __restrict__ outh, __half* __restrict__ outl,
    int nheads, const float* __restrict__ cosb, const float* __restrict__ sinb, float scale)
{
    int wid  = (blockIdx.x * 256 + threadIdx.x) >> 5;
    int lane = threadIdx.x & 31;
    int s  = wid / nheads;
    int hh = wid % nheads;
    size_t base = (size_t)s * nheads * HDIM + hh * HDIM + lane * 4;
    float4 vv = *(const float4*)(in + base);

    float c0 = cosb[s * 64 + lane * 2],     s0 = sinb[s * 64 + lane * 2];
    float c1 = cosb[s * 64 + lane * 2 + 1], s1 = sinb[s * 64 + lane * 2 + 1];
    float o0 = vv.x * c0 - vv.y * s0;
    float o1 = vv.x * s0 + vv.y * c0;
    float o2 = vv.z * c1 - vv.w * s1;
    float o3 = vv.z * s1 + vv.w * c1;

    float ss = o0*o0 + o1*o1 + o2*o2 + o3*o3;
#pragma unroll
    for (int o = 16; o; o >>= 1) ss += __shfl_xor_sync(0xffffffffu, ss, o);
    float rr = rsqrtf(ss * (1.f / HDIM) + 1e-5f) * scale;
    o0 *= rr; o1 *= rr; o2 *= rr; o3 *= rr;

    uint2 hv, lv;
    split2h(o0, o1, hv.x, lv.x, 1.f);
    split2h(o2, o3, hv.y, lv.y, 1.f);
    *(uint2*)(outh + base) = hv;
    *(uint2*)(outl + base) = lv;
}

// ================= transpose + fp16 hi/lo split (lo x1024): in[K,N] fp32 -> [N,K] =================
__global__ __launch_bounds__(256) void transpose_split_kernel(
    const float* __restrict__ in, __half* __restrict__ hi, __half* __restrict__ lo,
    int K, int N)
{
    __shared__ float s[64][65];
    int r0 = blockIdx.y * 64, c0 = blockIdx.x * 64;
#pragma unroll
    for (int i = 0; i < 8; i++) {
        int idx = threadIdx.x + i * 256;
        int lr = idx >> 5, p = idx & 31;
        float2 v = *(const float2*)(in + (size_t)(r0 + lr) * N + c0 + 2 * p);
        s[lr][2 * p]     = v.x;
        s[lr][2 * p + 1] = v.y;
    }
    __syncthreads();
#pragma unroll
    for (int i = 0; i < 8; i++) {
        int idx = threadIdx.x + i * 256;
        int lr = idx >> 5, p = idx & 31;
        float a = s[2 * p][lr];
        float b = s[2 * p + 1][lr];
        uint32_t hv, lv;
        split2h(a, b, hv, lv, LO_SCALE);
        size_t o = (size_t)(c0 + lr) * K + (r0 + 2 * p);
        *(uint32_t*)(hi + o) = hv;
        *(uint32_t*)(lo + o) = lv;
    }
}

// ================= HMMA 2-term GEMM: A fp16 x W(hi+lo/1024) =================
// CTA 128x128, K-chunk 64, 3-stage cp.async; stage = A(16K) Bh(16K) Bl(16K).
// Main A.Bh in f32 acc; correction A.Bl in f16 acc folded per chunk (x 1/1024).
#define TCG_STAGE_BYTES 49152
#define TCG_NSTAGE 3
#define TCG_SMEM (TCG_NSTAGE * TCG_STAGE_BYTES)

__global__ __launch_bounds__(256, 1) void tc_gemm_kernel(
    const __half* __restrict__ A,
    const __half* __restrict__ Bhi, const __half* __restrict__ Blo,
    float* __restrict__ C, const float* __restrict__ addend,
    __half* __restrict__ outH, __half* __restrict__ outL, float outLoScale,
    const float* __restrict__ gateMul,
    int M, int N, int K)
{
    extern __shared__ char sm[];
    uint32_t sbase = smem_u32(sm);
    int tid = threadIdx.x, lane = tid & 31, wid = tid >> 5;
    int warp_m = wid & 1, warp_n = wid >> 1;
    int by = blockIdx.x, bx = blockIdx.y;   // M-block fastest

    const __half* srcs[3] = {
        A   + (size_t)(by * 128) * K,
        Bhi + (size_t)(bx * 128) * K,
        Blo + (size_t)(bx * 128) * K };

    int nchunk = K >> 6;

    auto load_stage = [&](int stg, int c) {
        uint32_t dst0 = sbase + stg * TCG_STAGE_BYTES;
        int kc = c << 6;
#pragma unroll
        for (int i = 0; i < 12; i++) {
            int u = i * 256 + tid;
            int tile = u >> 10, w = u & 1023;
            int row = w >> 3, c16 = w & 7;
            uint32_t dst = dst0 + tile * 16384 + row * 128 + ((c16 ^ (row & 7)) << 4);
            cp_async16(dst, srcs[tile] + (size_t)row * K + kc + c16 * 8);
        }
    };

    load_stage(0, 0); CP_COMMIT();
    load_stage(1, 1); CP_COMMIT();

    float acc[4][4][4];
    uint32_t cacc[4][4][2];
#pragma unroll
    for (int a = 0; a < 4; a++)
#pragma unroll
        for (int b = 0; b < 4; b++) {
#pragma unroll
            for (int f = 0; f < 4; f++) acc[a][b][f] = 0.f;
            cacc[a][b][0] = 0u; cacc[a][b][1] = 0u;
        }

    int a_r   = warp_m * 64 + (lane & 15);
    int a_kh  = lane >> 4;
    int b_r   = warp_n * 32 + (lane & 7) + ((lane >> 4) << 3);
    int b_kh  = (lane >> 3) & 1;

    for (int c = 0; c < nchunk; c++) {
        CP_WAIT1();
        __syncthreads();
        if (c + 2 < nchunk) load_stage((c + 2) % TCG_NSTAGE, c + 2);
        CP_COMMIT();

        uint32_t st = sbase + (c % TCG_NSTAGE) * TCG_STAGE_BYTES;
#pragma unroll
        for (int kk = 0; kk < 4; kk++) {
            int c16 = kk * 2;
            uint32_t ah[4][4], bh[2][4], bl[2][4];
#pragma unroll
            for (int mb = 0; mb < 4; mb++) {
                int r = a_r + mb * 16;
                uint32_t off = r * 128 + (((c16 + a_kh) ^ (r & 7)) << 4);
                ldsm4(ah[mb], st + off);
            }
#pragma unroll
            for (int nb = 0; nb < 2; nb++) {
                int r = b_r + nb * 16;
                uint32_t off = r * 128 + (((c16 + b_kh) ^ (r & 7)) << 4);
                ldsm4(bh[nb], st + 16384 + off);
                ldsm4(bl[nb], st + 32768 + off);
            }
#pragma unroll
            for (int mb = 0; mb < 4; mb++)
#pragma unroll
                for (int nb = 0; nb < 4; nb++) {
                    uint32_t b0h = bh[nb >> 1][(nb & 1) * 2], b1h = bh[nb >> 1][(nb & 1) * 2 + 1];
                    uint32_t b0l = bl[nb >> 1][(nb & 1) * 2], b1l = bl[nb >> 1][(nb & 1) * 2 + 1];
                    mmaF32(acc[mb][nb], ah[mb], b0h, b1h);
                    mmaF16(cacc[mb][nb], ah[mb], b0l, b1l);
                }
        }
        // fold f16 corrections (x 1/1024)
#pragma unroll
        for (int mb = 0; mb < 4; mb++)
#pragma unroll
            for (int nb = 0; nb < 4; nb++) {
                float2 f01 = __half22float2(*(__half2*)&cacc[mb][nb][0]);
                float2 f23 = __half22float2(*(__half2*)&cacc[mb][nb][1]);
                acc[mb][nb][0] = fmaf(f01.x, INV_LO, acc[mb][nb][0]);
                acc[mb][nb][1] = fmaf(f01.y, INV_LO, acc[mb][nb][1]);
                acc[mb][nb][2] = fmaf(f23.x, INV_LO, acc[mb][nb][2]);
                acc[mb][nb][3] = fmaf(f23.y, INV_LO, acc[mb][nb][3]);
                cacc[mb][nb][0] = 0u; cacc[mb][nb][1] = 0u;
            }
        __syncthreads();
    }

#pragma unroll
    for (int mb = 0; mb < 4; mb++) {
        int mrow = by * 128 + warp_m * 64 + mb * 16 + (lane >> 2);
#pragma unroll
        for (int nb = 0; nb < 4; nb++) {
            int ncol = bx * 128 + warp_n * 32 + nb * 8 + (lane & 3) * 2;
            size_t i0 = (size_t)mrow * N + ncol;
            size_t i1 = (size_t)(mrow + 8) * N + ncol;
            float2 r0 = make_float2(acc[mb][nb][0], acc[mb][nb][1]);
            float2 r1 = make_float2(acc[mb][nb][2], acc[mb][nb][3]);
            if (addend) {
                float2 a0 = *(const float2*)(addend + i0);
                float2 a1 = *(const float2*)(addend + i1);
                r0.x += a0.x; r0.y += a0.y;
                r1.x += a1.x; r1.y += a1.y;
            }
            if (gateMul) {
                float2 g0 = *(const float2*)(gateMul + i0);
                float2 g1 = *(const float2*)(gateMul + i1);
                r0.x *= g0.x / (1.f + __expf(-g0.x));
                r0.y *= g0.y / (1.f + __expf(-g0.y));
                r1.x *= g1.x / (1.f + __expf(-g1.x));
                r1.y *= g1.y / (1.f + __expf(-g1.y));
            }
            if (C) {
                *(float2*)(C + i0) = r0;
                *(float2*)(C + i1) = r1;
            }
            if (outH) {
                if (outL) {
                    uint32_t h0, l0, h1, l1;
                    split2h(r0.x, r0.y, h0, l0, outLoScale);
                    split2h(r1.x, r1.y, h1, l1, outLoScale);
                    *(uint32_t*)(outH + i0) = h0;
                    *(uint32_t*)(outL + i0) = l0;
                    *(uint32_t*)(outH + i1) = h1;
                    *(uint32_t*)(outL + i1) = l1;
                } else {
                    *(uint32_t*)(outH + i0) = packh(__float2half_rn(r0.x), __float2half_rn(r0.y));
                    *(uint32_t*)(outH + i1) = packh(__float2half_rn(r1.x), __float2half_rn(r1.y));
                }
            }
        }
    }
}

// ================= HMMA causal flash attention, GQA, split-fp16, single-fp16 out =================
#define FA_STAGE_OFF 32768
#define FA_STAGE_BYTES 65536
#define FA_SMEM (FA_STAGE_OFF + 2 * FA_STAGE_BYTES)   // 160KB

__global__ __launch_bounds__(128, 1) void flash_attn_kernel(
    const __half* __restrict__ qh, const __half* __restrict__ ql,
    const __half* __restrict__ kh, const __half* __restrict__ kl,
    const __half* __restrict__ vh, const __half* __restrict__ vl,
    __half* __restrict__ o)
{
    extern __shared__ char sm[];
    uint32_t sbase = smem_u32(sm);
    int qb = blockIdx.x, h = blockIdx.y, kvh = h >> 2;
    int tid = threadIdx.x, lane = tid & 31, w = tid >> 5;

#pragma unroll
    for (int i = 0; i < 8; i++) {
        int u = tid + i * 128;
        int row = u >> 4, c16 = u & 15;
        uint32_t dst = sbase + row * 256 + ((c16 ^ (row & 7)) << 4);
        size_t srco = (size_t)(qb * 64 + row) * DMODEL + h * HDIM + c16 * 8;
        cp_async16(dst,         qh + srco);
        cp_async16(dst + 16384, ql + srco);
    }

    auto load_kv = [&](int stg, int kb) {
        uint32_t dst0 = sbase + FA_STAGE_OFF + stg * FA_STAGE_BYTES;
        const __half* srcs[4] = { kh, kl, vh, vl };
#pragma unroll
        for (int b = 0; b < 4; b++) {
            const __half* s = srcs[b];
#pragma unroll
            for (int i = 0; i < 8; i++) {
                int u = tid + i * 128;
                int row = u >> 4, c16 = u & 15;
                uint32_t dst = dst0 + b * 16384 + row * 256 + ((c16 ^ (row & 7)) << 4);
                cp_async16(dst, s + (size_t)(kb * 64 + row) * (NKVH * HDIM) + kvh * HDIM + c16 * 8);
            }
        }
    };

    load_kv(0, 0); CP_COMMIT();
    if (qb >= 1) load_kv(1, 1);
    CP_COMMIT();

    float O[16][4];
#pragma unroll
    for (int i = 0; i < 16; i++)
#pragma unroll
        for (int f = 0; f < 4; f++) O[i][f] = 0.f;
    float m_lo = -1e30f, m_hi = -1e30f, l_lo = 0.f, l_hi = 0.f;

    int r_loc = w * 16 + (lane >> 2);

    for (int kb = 0; kb <= qb; kb++) {
        CP_WAIT1();
        __syncthreads();
        uint32_t kbase = sbase + FA_STAGE_OFF + (kb & 1) * FA_STAGE_BYTES;

        float S[8][4];
#pragma unroll
        for (int i = 0; i < 8; i++)
#pragma unroll
            for (int f = 0; f < 4; f++) S[i][f] = 0.f;

#pragma unroll
        for (int kk = 0; kk < 8; kk++) {
            uint32_t aqh[4], aql[4];
            int ar = w * 16 + (lane & 15);
            int ac = kk * 2 + (lane >> 4);
            uint32_t aoff = ar * 256 + ((ac ^ (ar & 7)) << 4);
            ldsm4(aqh, sbase + aoff);
            ldsm4(aql, sbase + 16384 + aoff);
#pragma unroll
            for (int nblk = 0; nblk < 4; nblk++) {
                int br = nblk * 16 + (lane & 7) + ((lane >> 4) << 3);
                int bc = kk * 2 + ((lane >> 3) & 1);
                uint32_t boff = br * 256 + ((bc ^ (br & 7)) << 4);
                uint32_t bh4[4], bl4[4];
                ldsm4(bh4, kbase + boff);
                ldsm4(bl4, kbase + 16384 + boff);
                mmaF32(S[2*nblk],   aqh, bh4[0], bh4[1]);
                mmaF32(S[2*nblk],   aqh, bl4[0], bl4[1]);
                mmaF32(S[2*nblk],   aql, bh4[0], bh4[1]);
                mmaF32(S[2*nblk+1], aqh, bh4[2], bh4[3]);
                mmaF32(S[2*nblk+1], aqh, bl4[2], bl4[3]);
                mmaF32(S[2*nblk+1], aql, bh4[2], bh4[3]);
            }
        }

        if (kb == qb) {
#pragma unroll
            for (int nt = 0; nt < 8; nt++) {
                int c = nt * 8 + (lane & 3) * 2;
                if (c     > r_loc)     S[nt][0] = -1e30f;
                if (c + 1 > r_loc)     S[nt][1] = -1e30f;
                if (c     > r_loc + 8) S[nt][2] = -1e30f;
                if (c + 1 > r_loc + 8) S[nt][3] = -1e30f;
            }
        }

        float rm_lo = -1e30f, rm_hi = -1e30f;
#pragma unroll
        for (int nt = 0; nt < 8; nt++) {
            rm_lo = fmaxf(rm_lo, fmaxf(S[nt][0], S[nt][1]));
            rm_hi = fmaxf(rm_hi, fmaxf(S[nt][2], S[nt][3]));
        }
        rm_lo = fmaxf(rm_lo, __shfl_xor_sync(0xffffffffu, rm_lo, 1));
        rm_lo = fmaxf(rm_lo, __shfl_xor_sync(0xffffffffu, rm_lo, 2));
        rm_hi = fmaxf(rm_hi, __shfl_xor_sync(0xffffffffu, rm_hi, 1));
        rm_hi = fmaxf(rm_hi, __shfl_xor_sync(0xffffffffu, rm_hi, 2));
        float mn_lo = fmaxf(m_lo, rm_lo), mn_hi = fmaxf(m_hi, rm_hi);
        float corr_lo = __expf(m_lo - mn_lo), corr_hi = __expf(m_hi - mn_hi);

        uint32_t ph[8][2], pl[8][2];
        float sum_lo = 0.f, sum_hi = 0.f;
#pragma unroll
        for (int nt = 0; nt < 8; nt++) {
            float p0 = __expf(S[nt][0] - mn_lo);
            float p1 = __expf(S[nt][1] - mn_lo);
            float p2 = __expf(S[nt][2] - mn_hi);
            float p3 = __expf(S[nt][3] - mn_hi);
            sum_lo += p0 + p1; sum_hi += p2 + p3;
            split2h(p0, p1, ph[nt][0], pl[nt][0], 1.f);
            split2h(p2, p3, ph[nt][1], pl[nt][1], 1.f);
        }
        sum_lo += __shfl_xor_sync(0xffffffffu, sum_lo, 1);
        sum_lo += __shfl_xor_sync(0xffffffffu, sum_lo, 2);
        sum_hi += __shfl_xor_sync(0xffffffffu, sum_hi, 1);
        sum_hi += __shfl_xor_sync(0xffffffffu, sum_hi, 2);
        l_lo = l_lo * corr_lo + sum_lo;
        l_hi = l_hi * corr_hi + sum_hi;
        m_lo = mn_lo; m_hi = mn_hi;
#pragma unroll
        for (int ot = 0; ot < 16; ot++) {
            O[ot][0] *= corr_lo; O[ot][1] *= corr_lo;
            O[ot][2] *= corr_hi; O[ot][3] *= corr_hi;
        }

        uint32_t vbase = kbase + 32768;
#pragma unroll
        for (int kt = 0; kt < 4; kt++) {
            uint32_t aH[4] = { ph[2*kt][0], ph[2*kt][1], ph[2*kt+1][0], ph[2*kt+1][1] };
            uint32_t aL[4] = { pl[2*kt][0], pl[2*kt][1], pl[2*kt+1][0], pl[2*kt+1][1] };
            int krow = kt * 16 + (lane & 7) + ((lane >> 3) & 1) * 8;
#pragma unroll
            for (int ob = 0; ob < 8; ob++) {
                int cu = ob * 2 + (lane >> 4);
                uint32_t off = krow * 256 + ((cu ^ (krow & 7)) << 4);
                uint32_t bvh[4], bvl[4];
                ldsm4t(bvh, vbase + off);
                ldsm4t(bvl, vbase + 16384 + off);
                mmaF32(O[2*ob],   aH, bvh[0], bvh[1]);
                mmaF32(O[2*ob],   aH, bvl[0], bvl[1]);
                mmaF32(O[2*ob],   aL, bvh[0], bvh[1]);
                mmaF32(O[2*ob+1], aH, bvh[2], bvh[3]);
                mmaF32(O[2*ob+1], aH, bvl[2], bvl[3]);
                mmaF32(O[2*ob+1], aL, bvh[2], bvh[3]);
            }
        }

        __syncthreads();
        if (kb + 2 <= qb) load_kv(kb & 1, kb + 2);
        CP_COMMIT();
    }

    float il_lo = 1.f / l_lo, il_hi = 1.f / l_hi;
    int row0 = qb * 64 + r_loc;
#pragma unroll
    for (int ot = 0; ot < 16; ot++) {
        int col = h * HDIM + ot * 8 + (lane & 3) * 2;
        size_t i0 = (size_t)row0 * DMODEL + col;
        size_t i1 = (size_t)(row0 + 8) * DMODEL + col;
        *(uint32_t*)(o + i0) = packh(__float2half_rn(O[ot][0] * il_lo), __float2half_rn(O[ot][1] * il_lo));
        *(uint32_t*)(o + i1) = packh(__float2half_rn(O[ot][2] * il_hi), __float2half_rn(O[ot][3] * il_hi));
    }
}

// ================= host launcher =================
extern "C" void kernel_launch(void* const* d_in, const int* in_sizes, int n_in,
                              void* d_out, int out_size)
{
    const float* hidden = (const float*)d_in[0];
    const float* cosb  = (const float*)d_in[2];
    const float* sinb  = (const float*)d_in[3];
    const float* ln1   = (const float*)d_in[4];
    const float* wq    = (const float*)d_in[5];
    const float* wk    = (const float*)d_in[6];
    const float* wv    = (const float*)d_in[7];
    const float* wo    = (const float*)d_in[8];
    const float* ln2   = (const float*)d_in[9];
    const float* gatew = (const float*)d_in[10];
    const float* upw   = (const float*)d_in[11];
    const float* downw = (const float*)d_in[12];
    float* out = (float*)d_out;

    float *q, *k, *h, *gate;
    cudaGetSymbolAddress((void**)&q,    g_q);
    cudaGetSymbolAddress((void**)&k,    g_k);
    cudaGetSymbolAddress((void**)&h,    g_h);
    cudaGetSymbolAddress((void**)&gate, g_gate);

    __half *wqTh,*wqTl,*wkTh,*wkTl,*wvTh,*wvTl,*woTh,*woTl,*gwTh,*gwTl,*uwTh,*uwTl,*dwTh,*dwTl;
    cudaGetSymbolAddress((void**)&wqTh, g_wqT_h); cudaGetSymbolAddress((void**)&wqTl, g_wqT_l);
    cudaGetSymbolAddress((void**)&wkTh, g_wkT_h); cudaGetSymbolAddress((void**)&wkTl, g_wkT_l);
    cudaGetSymbolAddress((void**)&wvTh, g_wvT_h); cudaGetSymbolAddress((void**)&wvTl, g_wvT_l);
    cudaGetSymbolAddress((void**)&woTh, g_woT_h); cudaGetSymbolAddress((void**)&woTl, g_woT_l);
    cudaGetSymbolAddress((void**)&gwTh, g_gwT_h); cudaGetSymbolAddress((void**)&gwTl, g_gwT_l);
    cudaGetSymbolAddress((void**)&uwTh, g_uwT_h); cudaGetSymbolAddress((void**)&uwTl, g_uwT_l);
    cudaGetSymbolAddress((void**)&dwTh, g_dwT_h); cudaGetSymbolAddress((void**)&dwTl, g_dwT_l);

    __half *xn,*at,*x2,*ga,*qhp,*qlp,*khp,*klp,*vhp,*vlp;
    cudaGetSymbolAddress((void**)&xn, g_xn);
    cudaGetSymbolAddress((void**)&at, g_at);
    cudaGetSymbolAddress((void**)&x2, g_x2);
    cudaGetSymbolAddress((void**)&ga, g_ga);
    cudaGetSymbolAddress((void**)&qhp, g_qh); cudaGetSymbolAddress((void**)&qlp, g_ql);
    cudaGetSymbolAddress((void**)&khp, g_kh); cudaGetSymbolAddress((void**)&klp, g_kl);
    cudaGetSymbolAddress((void**)&vhp, g_vh); cudaGetSymbolAddress((void**)&vlp, g_vl);

    cudaFuncSetAttribute(tc_gemm_kernel, cudaFuncAttributeMaxDynamicSharedMemorySize, TCG_SMEM);
    cudaFuncSetAttribute(flash_attn_kernel, cudaFuncAttributeMaxDynamicSharedMemorySize, FA_SMEM);

    // Launch order chosen so ncu (-s 5 -c 1) profiles the 6th launch = tc_gemm (Q proj).
    transpose_split_kernel<<<dim3(DMODEL/64, DMODEL/64), 256>>>(wq, wqTh, wqTl, DMODEL, DMODEL);          // 1
    rmsnorm_h_kernel<<<S_LEN, 256>>>(hidden, ln1, xn);                                                    // 2
    transpose_split_kernel<<<dim3(NKVH*HDIM/64, DMODEL/64), 256>>>(wk, wkTh, wkTl, DMODEL, NKVH*HDIM);    // 3
    transpose_split_kernel<<<dim3(NKVH*HDIM/64, DMODEL/64), 256>>>(wv, wvTh, wvTl, DMODEL, NKVH*HDIM);    // 4
    transpose_split_kernel<<<dim3(DMODEL/64, DMODEL/64), 256>>>(wo, woTh, woTl, DMODEL, DMODEL);          // 5
    tc_gemm_kernel<<<dim3(S_LEN/128, DMODEL/128), 256, TCG_SMEM>>>(                                        // 6 (profiled)
        xn, wqTh, wqTl, q, nullptr, nullptr, nullptr, 1.f, nullptr, S_LEN, DMODEL, DMODEL);
    transpose_split_kernel<<<dim3(DFFN/64, DMODEL/64), 256>>>(gatew, gwTh, gwTl, DMODEL, DFFN);           // 7
    transpose_split_kernel<<<dim3(DFFN/64, DMODEL/64), 256>>>(upw,   uwTh, uwTl, DMODEL, DFFN);           // 8
    transpose_split_kernel<<<dim3(DMODEL/64, DFFN/64), 256>>>(downw, dwTh, dwTl, DFFN, DMODEL);           // 9

    tc_gemm_kernel<<<dim3(S_LEN/128, NKVH*HDIM/128), 256, TCG_SMEM>>>(
        xn, wkTh, wkTl, k, nullptr, nullptr, nullptr, 1.f, nullptr, S_LEN, NKVH*HDIM, DMODEL);
    tc_gemm_kernel<<<dim3(S_LEN/128, NKVH*HDIM/128), 256, TCG_SMEM>>>(
        xn, wvTh, wvTl, nullptr, nullptr, vhp, vlp, 1.f, nullptr, S_LEN, NKVH*HDIM, DMODEL);

    const float qscale = 0.08838834764831845f;
    rope_l2_split_kernel<<<S_LEN * NHEADS / 8, 256>>>(q, qhp, qlp, NHEADS, cosb, sinb, qscale);
    rope_l2_split_kernel<<<S_LEN * NKVH  / 8, 256>>>(k, khp, klp, NKVH,  cosb, sinb, 1.f);

    flash_attn_kernel<<<dim3(S_LEN / 64, NHEADS), 128, FA_SMEM>>>(qhp, qlp, khp, klp, vhp, vlp, at);

    tc_gemm_kernel<<<dim3(S_LEN/128, DMODEL/128), 256, TCG_SMEM>>>(
        at, woTh, woTl, h, hidden, nullptr, nullptr, 1.f, nullptr, S_LEN, DMODEL, DMODEL);

    rmsnorm_h_kernel<<<S_LEN, 256>>>(h, ln2, x2);

    tc_gemm_kernel<<<dim3(S_LEN/128, DFFN/128), 256, TCG_SMEM>>>(
        x2, gwTh, gwTl, gate, nullptr, nullptr, nullptr, 1.f, nullptr, S_LEN, DFFN, DMODEL);
    tc_gemm_kernel<<<dim3(S_LEN/128, DFFN/128), 256, TCG_SMEM>>>(
        x2, uwTh, uwTl, nullptr, nullptr, ga, nullptr, 1.f, gate, S_LEN, DFFN, DMODEL);

    tc_gemm_kernel<<<dim3(S_LEN/128, DMODEL/128), 256, TCG_SMEM>>>(
        ga, dwTh, dwTl, out, h, nullptr, nullptr, 1.f, nullptr, S_LEN, DMODEL, DFFN);
}

// round 10
// speedup vs baseline: 1.4399x; 1.1014x over previous
#include <cuda_runtime.h>
#include <cuda_fp16.h>
#include <math.h>
#include <stdint.h>

#define S_LEN  2048
#define DMODEL 4096
#define NHEADS 32
#define NKVH   8
#define HDIM   128
#define DFFN   16384

#define LO_SCALE 1024.0f
#define INV_LO   0.0009765625f

// ================= low-level helpers (base sm_103 ISA: ldmatrix/mma/cp.async) =================
__device__ __forceinline__ uint32_t smem_u32(const void* p) {
    uint32_t a;
    asm("{ .reg .u64 t; cvta.to.shared.u64 t, %1; cvt.u32.u64 %0, t; }" : "=r"(a) : "l"(p));
    return a;
}
__device__ __forceinline__ void cp_async16(uint32_t dst, const void* src) {
    asm volatile("cp.async.cg.shared.global [%0], [%1], 16;" :: "r"(dst), "l"(src));
}
#define CP_COMMIT() asm volatile("cp.async.commit_group;" ::: "memory")
#define CP_WAIT0()  asm volatile("cp.async.wait_group 0;" ::: "memory")
#define CP_WAIT1()  asm volatile("cp.async.wait_group 1;" ::: "memory")

__device__ __forceinline__ void ldsm4(uint32_t* r, uint32_t addr) {
    asm volatile("ldmatrix.sync.aligned.m8n8.x4.shared.b16 {%0,%1,%2,%3}, [%4];"
        : "=r"(r[0]), "=r"(r[1]), "=r"(r[2]), "=r"(r[3]) : "r"(addr));
}
__device__ __forceinline__ void ldsm4t(uint32_t* r, uint32_t addr) {
    asm volatile("ldmatrix.sync.aligned.m8n8.x4.trans.shared.b16 {%0,%1,%2,%3}, [%4];"
        : "=r"(r[0]), "=r"(r[1]), "=r"(r[2]), "=r"(r[3]) : "r"(addr));
}
__device__ __forceinline__ void mmaF32(float* d, const uint32_t* a, uint32_t b0, uint32_t b1) {
    asm volatile("mma.sync.aligned.m16n8k16.row.col.f32.f16.f16.f32 "
        "{%0,%1,%2,%3}, {%4,%5,%6,%7}, {%8,%9}, {%0,%1,%2,%3};"
        : "+f"(d[0]), "+f"(d[1]), "+f"(d[2]), "+f"(d[3])
        : "r"(a[0]), "r"(a[1]), "r"(a[2]), "r"(a[3]), "r"(b0), "r"(b1));
}
__device__ __forceinline__ void mmaF16(uint32_t* d, const uint32_t* a, uint32_t b0, uint32_t b1) {
    asm volatile("mma.sync.aligned.m16n8k16.row.col.f16.f16.f16.f16 "
        "{%0,%1}, {%2,%3,%4,%5}, {%6,%7}, {%0,%1};"
        : "+r"(d[0]), "+r"(d[1])
        : "r"(a[0]), "r"(a[1]), "r"(a[2]), "r"(a[3]), "r"(b0), "r"(b1));
}

__device__ __forceinline__ uint32_t packh(__half a, __half b) {
    __half2 t = __halves2half2(a, b);
    return *(uint32_t*)&t;
}
__device__ __forceinline__ void split2h(float a, float b, uint32_t& hi, uint32_t& lo, float ls) {
    __half ha = __float2half_rn(a), hb = __float2half_rn(b);
    __half la = __float2half_rn((a - __half2float(ha)) * ls);
    __half lb = __float2half_rn((b - __half2float(hb)) * ls);
    hi = packh(ha, hb);
    lo = packh(la, lb);
}

// ================= scratch (device globals; no allocation allowed) =================
__device__ float g_q   [S_LEN * DMODEL];
__device__ float g_k   [S_LEN * NKVH * HDIM];
__device__ float g_h   [S_LEN * DMODEL];
__device__ float g_gate[S_LEN * DFFN];

// fp16 hi/lo transposed weights (lo x1024). QKV combined: [6144, 4096]
#define NQKV (DMODEL + 2 * NKVH * HDIM)
__device__ __half g_wqkvT_h[NQKV * DMODEL], g_wqkvT_l[NQKV * DMODEL];
__device__ __half g_woT_h[DMODEL * DMODEL], g_woT_l[DMODEL * DMODEL];
__device__ __half g_gwT_h[DFFN * DMODEL],   g_gwT_l[DFFN * DMODEL];
__device__ __half g_uwT_h[DFFN * DMODEL],   g_uwT_l[DFFN * DMODEL];
__device__ __half g_dwT_h[DMODEL * DFFN],   g_dwT_l[DMODEL * DFFN];

// activations: single fp16 (GEMM A operands)
__device__ __half g_xn[S_LEN * DMODEL];
__device__ __half g_at[S_LEN * DMODEL];
__device__ __half g_x2[S_LEN * DMODEL];
__device__ __half g_ga[S_LEN * DFFN];

// attention operands: fp16 hi/lo (unscaled lo)
__device__ __half g_qh[S_LEN * DMODEL],      g_ql[S_LEN * DMODEL];
__device__ __half g_kh[S_LEN * NKVH * HDIM], g_kl[S_LEN * NKVH * HDIM];
__device__ __half g_vh[S_LEN * NKVH * HDIM], g_vl[S_LEN * NKVH * HDIM];

// ================= RMSNorm -> single fp16 =================
__global__ __launch_bounds__(256) void rmsnorm_h_kernel(
    const float* __restrict__ x, const float* __restrict__ w, __half* __restrict__ y)
{
    int row = blockIdx.x;
    const float* xr = x + (size_t)row * DMODEL;

    float4 vals[4];
    float ss = 0.f;
#pragma unroll
    for (int it = 0; it < 4; it++) {
        int idx = (threadIdx.x + it * 256) * 4;
        float4 v = *(const float4*)(xr + idx);
        vals[it] = v;
        ss += v.x*v.x + v.y*v.y + v.z*v.z + v.w*v.w;
    }
#pragma unroll
    for (int o = 16; o; o >>= 1) ss += __shfl_xor_sync(0xffffffffu, ss, o);

    __shared__ float red[8];
    if ((threadIdx.x & 31) == 0) red[threadIdx.x >> 5] = ss;
    __syncthreads();
    float tot = 0.f;
#pragma unroll
    for (int i = 0; i < 8; i++) tot += red[i];
    float inv = rsqrtf(tot * (1.f / DMODEL) + 1e-5f);

#pragma unroll
    for (int it = 0; it < 4; it++) {
        int idx = (threadIdx.x + it * 256) * 4;
        float4 v  = vals[it];
        float4 wv = *(const float4*)(w + idx);
        uint2 hv;
        hv.x = packh(__float2half_rn(v.x * inv * wv.x), __float2half_rn(v.y * inv * wv.y));
        hv.y = packh(__float2half_rn(v.z * inv * wv.z), __float2half_rn(v.w * inv * wv.w));
        *(uint2*)(y + (size_t)row * DMODEL + idx) = hv;
    }
}

// ================= RoPE + L2-norm -> fp16 hi/lo (unscaled) =================
__global__ __launch_bounds__(256) void rope_l2_split_kernel(
    const float* __restrict__ in, __half* __restrict__ outh, __half* __restrict__ outl,
    int nheads, const float* __restrict__ cosb, const float* __restrict__ sinb, float scale)
{
    int wid  = (blockIdx.x * 256 + threadIdx.x) >> 5;
    int lane = threadIdx.x & 31;
    int s  = wid / nheads;
    int hh = wid % nheads;
    size_t base = (size_t)s * nheads * HDIM + hh * HDIM + lane * 4;
    float4 vv = *(const float4*)(in + base);

    float c0 = cosb[s * 64 + lane * 2],     s0 = sinb[s * 64 + lane * 2];
    float c1 = cosb[s * 64 + lane * 2 + 1], s1 = sinb[s * 64 + lane * 2 + 1];
    float o0 = vv.x * c0 - vv.y * s0;
    float o1 = vv.x * s0 + vv.y * c0;
    float o2 = vv.z * c1 - vv.w * s1;
    float o3 = vv.z * s1 + vv.w * c1;

    float ss = o0*o0 + o1*o1 + o2*o2 + o3*o3;
#pragma unroll
    for (int o = 16; o; o >>= 1) ss += __shfl_xor_sync(0xffffffffu, ss, o);
    float rr = rsqrtf(ss * (1.f / HDIM) + 1e-5f) * scale;
    o0 *= rr; o1 *= rr; o2 *= rr; o3 *= rr;

    uint2 hv, lv;
    split2h(o0, o1, hv.x, lv.x, 1.f);
    split2h(o2, o3, hv.y, lv.y, 1.f);
    *(uint2*)(outh + base) = hv;
    *(uint2*)(outl + base) = lv;
}

// ================= transpose + fp16 hi/lo split (lo x1024): in[K,N] fp32 -> [N,K] =================
__global__ __launch_bounds__(256) void transpose_split_kernel(
    const float* __restrict__ in, __half* __restrict__ hi, __half* __restrict__ lo,
    int K, int N)
{
    __shared__ float s[64][65];
    int r0 = blockIdx.y * 64, c0 = blockIdx.x * 64;
#pragma unroll
    for (int i = 0; i < 8; i++) {
        int idx = threadIdx.x + i * 256;
        int lr = idx >> 5, p = idx & 31;
        float2 v = *(const float2*)(in + (size_t)(r0 + lr) * N + c0 + 2 * p);
        s[lr][2 * p]     = v.x;
        s[lr][2 * p + 1] = v.y;
    }
    __syncthreads();
#pragma unroll
    for (int i = 0; i < 8; i++) {
        int idx = threadIdx.x + i * 256;
        int lr = idx >> 5, p = idx & 31;
        float a = s[2 * p][lr];
        float b = s[2 * p + 1][lr];
        uint32_t hv, lv;
        split2h(a, b, hv, lv, LO_SCALE);
        size_t o = (size_t)(c0 + lr) * K + (r0 + 2 * p);
        *(uint32_t*)(hi + o) = hv;
        *(uint32_t*)(lo + o) = lv;
    }
}

// ================= HMMA 2-term GEMM: A fp16 x W(hi + lo/1024) =================
// CTA 128x128, K-chunk 128 (256B rows), 2-stage (2x96KB). 8 warps @ 64x32.
// Main A.Bh -> f32 acc; correction A.Bl -> f16 acc (x1024), folded ONCE in epilogue.
// qkvMode: N=6144 routed epilogue (q fp32 / k fp32 / v hi-lo split).
#define TCG_STAGE_BYTES 98304
#define TCG_SMEM (2 * TCG_STAGE_BYTES)

__global__ __launch_bounds__(256, 1) void tc_gemm_kernel(
    const __half* __restrict__ A,
    const __half* __restrict__ Bhi, const __half* __restrict__ Blo,
    float* __restrict__ C, const float* __restrict__ addend,
    __half* __restrict__ outH, __half* __restrict__ outL,
    const float* __restrict__ gateMul,
    float* __restrict__ kDest, __half* __restrict__ vH, __half* __restrict__ vL, int qkvMode,
    int M, int N, int K)
{
    extern __shared__ char sm[];
    uint32_t sbase = smem_u32(sm);
    int tid = threadIdx.x, lane = tid & 31, wid = tid >> 5;
    int warp_m = wid & 1, warp_n = wid >> 1;
    int by = blockIdx.x, bx = blockIdx.y;   // M-block fastest

    const __half* srcs[3] = {
        A   + (size_t)(by * 128) * K,
        Bhi + (size_t)(bx * 128) * K,
        Blo + (size_t)(bx * 128) * K };

    int nchunk = K >> 7;

    auto load_stage = [&](int stg, int c) {
        uint32_t dst0 = sbase + stg * TCG_STAGE_BYTES;
        int kc = c << 7;
#pragma unroll
        for (int i = 0; i < 24; i++) {
            int u = i * 256 + tid;
            int tile = u >> 11, w = u & 2047;     // 2048 16B-units per 32KB tile
            int row = w >> 4, c16 = w & 15;       // 128 rows x 256B
            uint32_t dst = dst0 + tile * 32768 + row * 256 + ((c16 ^ (row & 7)) << 4);
            cp_async16(dst, srcs[tile] + (size_t)row * K + kc + c16 * 8);
        }
    };

    load_stage(0, 0); CP_COMMIT();

    float acc[4][4][4];
    uint32_t cacc[4][4][2];
#pragma unroll
    for (int a = 0; a < 4; a++)
#pragma unroll
        for (int b = 0; b < 4; b++) {
#pragma unroll
            for (int f = 0; f < 4; f++) acc[a][b][f] = 0.f;
            cacc[a][b][0] = 0u; cacc[a][b][1] = 0u;
        }

    int a_r   = warp_m * 64 + (lane & 15);
    int a_kh  = lane >> 4;
    int b_r   = warp_n * 32 + (lane & 7) + ((lane >> 4) << 3);
    int b_kh  = (lane >> 3) & 1;

    for (int c = 0; c < nchunk; c++) {
        if (c + 1 < nchunk) { load_stage((c + 1) & 1, c + 1); CP_COMMIT(); CP_WAIT1(); }
        else                { CP_WAIT0(); }
        __syncthreads();

        uint32_t st = sbase + (c & 1) * TCG_STAGE_BYTES;
#pragma unroll
        for (int kk = 0; kk < 8; kk++) {
            int c16 = kk * 2;
            uint32_t ah[4][4], bh[2][4], bl[2][4];
#pragma unroll
            for (int mb = 0; mb < 4; mb++) {
                int r = a_r + mb * 16;
                uint32_t off = r * 256 + (((c16 + a_kh) ^ (r & 7)) << 4);
                ldsm4(ah[mb], st + off);
            }
#pragma unroll
            for (int nb = 0; nb < 2; nb++) {
                int r = b_r + nb * 16;
                uint32_t off = r * 256 + (((c16 + b_kh) ^ (r & 7)) << 4);
                ldsm4(bh[nb], st + 32768 + off);
                ldsm4(bl[nb], st + 65536 + off);
            }
#pragma unroll
            for (int mb = 0; mb < 4; mb++)
#pragma unroll
                for (int nb = 0; nb < 4; nb++) {
                    uint32_t b0h = bh[nb >> 1][(nb & 1) * 2], b1h = bh[nb >> 1][(nb & 1) * 2 + 1];
                    uint32_t b0l = bl[nb >> 1][(nb & 1) * 2], b1l = bl[nb >> 1][(nb & 1) * 2 + 1];
                    mmaF32(acc[mb][nb], ah[mb], b0h, b1h);
                    mmaF16(cacc[mb][nb], ah[mb], b0l, b1l);
                }
        }
        __syncthreads();
    }

    // fold f16 corrections once (x 1/1024)
#pragma unroll
    for (int mb = 0; mb < 4; mb++)
#pragma unroll
        for (int nb = 0; nb < 4; nb++) {
            float2 f01 = __half22float2(*(__half2*)&cacc[mb][nb][0]);
            float2 f23 = __half22float2(*(__half2*)&cacc[mb][nb][1]);
            acc[mb][nb][0] = fmaf(f01.x, INV_LO, acc[mb][nb][0]);
            acc[mb][nb][1] = fmaf(f01.y, INV_LO, acc[mb][nb][1]);
            acc[mb][nb][2] = fmaf(f23.x, INV_LO, acc[mb][nb][2]);
            acc[mb][nb][3] = fmaf(f23.y, INV_LO, acc[mb][nb][3]);
        }

#pragma unroll
    for (int mb = 0; mb < 4; mb++) {
        int mrow = by * 128 + warp_m * 64 + mb * 16 + (lane >> 2);
#pragma unroll
        for (int nb = 0; nb < 4; nb++) {
            int ncol = bx * 128 + warp_n * 32 + nb * 8 + (lane & 3) * 2;
            float2 r0 = make_float2(acc[mb][nb][0], acc[mb][nb][1]);
            float2 r1 = make_float2(acc[mb][nb][2], acc[mb][nb][3]);

            if (qkvMode) {
                if (ncol < DMODEL) {
                    size_t i0 = (size_t)mrow * DMODEL + ncol;
                    size_t i1 = (size_t)(mrow + 8) * DMODEL + ncol;
                    *(float2*)(C + i0) = r0;
                    *(float2*)(C + i1) = r1;
                } else if (ncol < DMODEL + NKVH * HDIM) {
                    int cc = ncol - DMODEL;
                    size_t i0 = (size_t)mrow * (NKVH * HDIM) + cc;
                    size_t i1 = (size_t)(mrow + 8) * (NKVH * HDIM) + cc;
                    *(float2*)(kDest + i0) = r0;
                    *(float2*)(kDest + i1) = r1;
                } else {
                    int cc = ncol - DMODEL - NKVH * HDIM;
                    size_t i0 = (size_t)mrow * (NKVH * HDIM) + cc;
                    size_t i1 = (size_t)(mrow + 8) * (NKVH * HDIM) + cc;
                    uint32_t h0, l0, h1, l1;
                    split2h(r0.x, r0.y, h0, l0, 1.f);
                    split2h(r1.x, r1.y, h1, l1, 1.f);
                    *(uint32_t*)(vH + i0) = h0;
                    *(uint32_t*)(vL + i0) = l0;
                    *(uint32_t*)(vH + i1) = h1;
                    *(uint32_t*)(vL + i1) = l1;
                }
                continue;
            }

            size_t i0 = (size_t)mrow * N + ncol;
            size_t i1 = (size_t)(mrow + 8) * N + ncol;
            if (addend) {
                float2 a0 = *(const float2*)(addend + i0);
                float2 a1 = *(const float2*)(addend + i1);
                r0.x += a0.x; r0.y += a0.y;
                r1.x += a1.x; r1.y += a1.y;
            }
            if (gateMul) {
                float2 g0 = *(const float2*)(gateMul + i0);
                float2 g1 = *(const float2*)(gateMul + i1);
                r0.x *= g0.x / (1.f + __expf(-g0.x));
                r0.y *= g0.y / (1.f + __expf(-g0.y));
                r1.x *= g1.x / (1.f + __expf(-g1.x));
                r1.y *= g1.y / (1.f + __expf(-g1.y));
            }
            if (C) {
                *(float2*)(C + i0) = r0;
                *(float2*)(C + i1) = r1;
            }
            if (outH) {
                *(uint32_t*)(outH + i0) = packh(__float2half_rn(r0.x), __float2half_rn(r0.y));
                *(uint32_t*)(outH + i1) = packh(__float2half_rn(r1.x), __float2half_rn(r1.y));
            }
        }
    }
}

// ================= HMMA causal flash attention, GQA, split-fp16, single-fp16 out =================
#define FA_STAGE_OFF 32768
#define FA_STAGE_BYTES 65536
#define FA_SMEM (FA_STAGE_OFF + 2 * FA_STAGE_BYTES)   // 160KB

__global__ __launch_bounds__(128, 1) void flash_attn_kernel(
    const __half* __restrict__ qh, const __half* __restrict__ ql,
    const __half* __restrict__ kh, const __half* __restrict__ kl,
    const __half* __restrict__ vh, const __half* __restrict__ vl,
    __half* __restrict__ o)
{
    extern __shared__ char sm[];
    uint32_t sbase = smem_u32(sm);
    int qb = blockIdx.x, h = blockIdx.y, kvh = h >> 2;
    int tid = threadIdx.x, lane = tid & 31, w = tid >> 5;

#pragma unroll
    for (int i = 0; i < 8; i++) {
        int u = tid + i * 128;
        int row = u >> 4, c16 = u & 15;
        uint32_t dst = sbase + row * 256 + ((c16 ^ (row & 7)) << 4);
        size_t srco = (size_t)(qb * 64 + row) * DMODEL + h * HDIM + c16 * 8;
        cp_async16(dst,         qh + srco);
        cp_async16(dst + 16384, ql + srco);
    }

    auto load_kv = [&](int stg, int kb) {
        uint32_t dst0 = sbase + FA_STAGE_OFF + stg * FA_STAGE_BYTES;
        const __half* srcs[4] = { kh, kl, vh, vl };
#pragma unroll
        for (int b = 0; b < 4; b++) {
            const __half* s = srcs[b];
#pragma unroll
            for (int i = 0; i < 8; i++) {
                int u = tid + i * 128;
                int row = u >> 4, c16 = u & 15;
                uint32_t dst = dst0 + b * 16384 + row * 256 + ((c16 ^ (row & 7)) << 4);
                cp_async16(dst, s + (size_t)(kb * 64 + row) * (NKVH * HDIM) + kvh * HDIM + c16 * 8);
            }
        }
    };

    load_kv(0, 0); CP_COMMIT();
    if (qb >= 1) load_kv(1, 1);
    CP_COMMIT();

    float O[16][4];
#pragma unroll
    for (int i = 0; i < 16; i++)
#pragma unroll
        for (int f = 0; f < 4; f++) O[i][f] = 0.f;
    float m_lo = -1e30f, m_hi = -1e30f, l_lo = 0.f, l_hi = 0.f;

    int r_loc = w * 16 + (lane >> 2);

    for (int kb = 0; kb <= qb; kb++) {
        CP_WAIT1();
        __syncthreads();
        uint32_t kbase = sbase + FA_STAGE_OFF + (kb & 1) * FA_STAGE_BYTES;

        float S[8][4];
#pragma unroll
        for (int i = 0; i < 8; i++)
#pragma unroll
            for (int f = 0; f < 4; f++) S[i][f] = 0.f;

#pragma unroll
        for (int kk = 0; kk < 8; kk++) {
            uint32_t aqh[4], aql[4];
            int ar = w * 16 + (lane & 15);
            int ac = kk * 2 + (lane >> 4);
            uint32_t aoff = ar * 256 + ((ac ^ (ar & 7)) << 4);
            ldsm4(aqh, sbase + aoff);
            ldsm4(aql, sbase + 16384 + aoff);
#pragma unroll
            for (int nblk = 0; nblk < 4; nblk++) {
                int br = nblk * 16 + (lane & 7) + ((lane >> 4) << 3);
                int bc = kk * 2 + ((lane >> 3) & 1);
                uint32_t boff = br * 256 + ((bc ^ (br & 7)) << 4);
                uint32_t bh4[4], bl4[4];
                ldsm4(bh4, kbase + boff);
                ldsm4(bl4, kbase + 16384 + boff);
                mmaF32(S[2*nblk],   aqh, bh4[0], bh4[1]);
                mmaF32(S[2*nblk],   aqh, bl4[0], bl4[1]);
                mmaF32(S[2*nblk],   aql, bh4[0], bh4[1]);
                mmaF32(S[2*nblk+1], aqh, bh4[2], bh4[3]);
                mmaF32(S[2*nblk+1], aqh, bl4[2], bl4[3]);
                mmaF32(S[2*nblk+1], aql, bh4[2], bh4[3]);
            }
        }

        if (kb == qb) {
#pragma unroll
            for (int nt = 0; nt < 8; nt++) {
                int c = nt * 8 + (lane & 3) * 2;
                if (c     > r_loc)     S[nt][0] = -1e30f;
                if (c + 1 > r_loc)     S[nt][1] = -1e30f;
                if (c     > r_loc + 8) S[nt][2] = -1e30f;
                if (c + 1 > r_loc + 8) S[nt][3] = -1e30f;
            }
        }

        float rm_lo = -1e30f, rm_hi = -1e30f;
#pragma unroll
        for (int nt = 0; nt < 8; nt++) {
            rm_lo = fmaxf(rm_lo, fmaxf(S[nt][0], S[nt][1]));
            rm_hi = fmaxf(rm_hi, fmaxf(S[nt][2], S[nt][3]));
        }
        rm_lo = fmaxf(rm_lo, __shfl_xor_sync(0xffffffffu, rm_lo, 1));
        rm_lo = fmaxf(rm_lo, __shfl_xor_sync(0xffffffffu, rm_lo, 2));
        rm_hi = fmaxf(rm_hi, __shfl_xor_sync(0xffffffffu, rm_hi, 1));
        rm_hi = fmaxf(rm_hi, __shfl_xor_sync(0xffffffffu, rm_hi, 2));
        float mn_lo = fmaxf(m_lo, rm_lo), mn_hi = fmaxf(m_hi, rm_hi);
        float corr_lo = __expf(m_lo - mn_lo), corr_hi = __expf(m_hi - mn_hi);

        uint32_t ph[8][2], pl[8][2];
        float sum_lo = 0.f, sum_hi = 0.f;
#pragma unroll
        for (int nt = 0; nt < 8; nt++) {
            float p0 = __expf(S[nt][0] - mn_lo);
            float p1 = __expf(S[nt][1] - mn_lo);
            float p2 = __expf(S[nt][2] - mn_hi);
            float p3 = __expf(S[nt][3] - mn_hi);
            sum_lo += p0 + p1; sum_hi += p2 + p3;
            split2h(p0, p1, ph[nt][0], pl[nt][0], 1.f);
            split2h(p2, p3, ph[nt][1], pl[nt][1], 1.f);
        }
        sum_lo += __shfl_xor_sync(0xffffffffu, sum_lo, 1);
        sum_lo += __shfl_xor_sync(0xffffffffu, sum_lo, 2);
        sum_hi += __shfl_xor_sync(0xffffffffu, sum_hi, 1);
        sum_hi += __shfl_xor_sync(0xffffffffu, sum_hi, 2);
        l_lo = l_lo * corr_lo + sum_lo;
        l_hi = l_hi * corr_hi + sum_hi;
        m_lo = mn_lo; m_hi = mn_hi;
#pragma unroll
        for (int ot = 0; ot < 16; ot++) {
            O[ot][0] *= corr_lo; O[ot][1] *= corr_lo;
            O[ot][2] *= corr_hi; O[ot][3] *= corr_hi;
        }

        uint32_t vbase = kbase + 32768;
#pragma unroll
        for (int kt = 0; kt < 4; kt++) {
            uint32_t aH[4] = { ph[2*kt][0], ph[2*kt][1], ph[2*kt+1][0], ph[2*kt+1][1] };
            uint32_t aL[4] = { pl[2*kt][0], pl[2*kt][1], pl[2*kt+1][0], pl[2*kt+1][1] };
            int krow = kt * 16 + (lane & 7) + ((lane >> 3) & 1) * 8;
#pragma unroll
            for (int ob = 0; ob < 8; ob++) {
                int cu = ob * 2 + (lane >> 4);
                uint32_t off = krow * 256 + ((cu ^ (krow & 7)) << 4);
                uint32_t bvh[4], bvl[4];
                ldsm4t(bvh, vbase + off);
                ldsm4t(bvl, vbase + 16384 + off);
                mmaF32(O[2*ob],   aH, bvh[0], bvh[1]);
                mmaF32(O[2*ob],   aH, bvl[0], bvl[1]);
                mmaF32(O[2*ob],   aL, bvh[0], bvh[1]);
                mmaF32(O[2*ob+1], aH, bvh[2], bvh[3]);
                mmaF32(O[2*ob+1], aH, bvl[2], bvl[3]);
                mmaF32(O[2*ob+1], aL, bvh[2], bvh[3]);
            }
        }

        __syncthreads();
        if (kb + 2 <= qb) load_kv(kb & 1, kb + 2);
        CP_COMMIT();
    }

    float il_lo = 1.f / l_lo, il_hi = 1.f / l_hi;
    int row0 = qb * 64 + r_loc;
#pragma unroll
    for (int ot = 0; ot < 16; ot++) {
        int col = h * HDIM + ot * 8 + (lane & 3) * 2;
        size_t i0 = (size_t)row0 * DMODEL + col;
        size_t i1 = (size_t)(row0 + 8) * DMODEL + col;
        *(uint32_t*)(o + i0) = packh(__float2half_rn(O[ot][0] * il_lo), __float2half_rn(O[ot][1] * il_lo));
        *(uint32_t*)(o + i1) = packh(__float2half_rn(O[ot][2] * il_hi), __float2half_rn(O[ot][3] * il_hi));
    }
}

// ================= host launcher =================
extern "C" void kernel_launch(void* const* d_in, const int* in_sizes, int n_in,
                              void* d_out, int out_size)
{
    const float* hidden = (const float*)d_in[0];
    const float* cosb  = (const float*)d_in[2];
    const float* sinb  = (const float*)d_in[3];
    const float* ln1   = (const float*)d_in[4];
    const float* wq    = (const float*)d_in[5];
    const float* wk    = (const float*)d_in[6];
    const float* wv    = (const float*)d_in[7];
    const float* wo    = (const float*)d_in[8];
    const float* ln2   = (const float*)d_in[9];
    const float* gatew = (const float*)d_in[10];
    const float* upw   = (const float*)d_in[11];
    const float* downw = (const float*)d_in[12];
    float* out = (float*)d_out;

    float *q, *k, *h, *gate;
    cudaGetSymbolAddress((void**)&q,    g_q);
    cudaGetSymbolAddress((void**)&k,    g_k);
    cudaGetSymbolAddress((void**)&h,    g_h);
    cudaGetSymbolAddress((void**)&gate, g_gate);

    __half *qkvTh,*qkvTl,*woTh,*woTl,*gwTh,*gwTl,*uwTh,*uwTl,*dwTh,*dwTl;
    cudaGetSymbolAddress((void**)&qkvTh, g_wqkvT_h); cudaGetSymbolAddress((void**)&qkvTl, g_wqkvT_l);
    cudaGetSymbolAddress((void**)&woTh, g_woT_h); cudaGetSymbolAddress((void**)&woTl, g_woT_l);
    cudaGetSymbolAddress((void**)&gwTh, g_gwT_h); cudaGetSymbolAddress((void**)&gwTl, g_gwT_l);
    cudaGetSymbolAddress((void**)&uwTh, g_uwT_h); cudaGetSymbolAddress((void**)&uwTl, g_uwT_l);
    cudaGetSymbolAddress((void**)&dwTh, g_dwT_h); cudaGetSymbolAddress((void**)&dwTl, g_dwT_l);

    __half *xn,*at,*x2,*ga,*qhp,*qlp,*khp,*klp,*vhp,*vlp;
    cudaGetSymbolAddress((void**)&xn, g_xn);
    cudaGetSymbolAddress((void**)&at, g_at);
    cudaGetSymbolAddress((void**)&x2, g_x2);
    cudaGetSymbolAddress((void**)&ga, g_ga);
    cudaGetSymbolAddress((void**)&qhp, g_qh); cudaGetSymbolAddress((void**)&qlp, g_ql);
    cudaGetSymbolAddress((void**)&khp, g_kh); cudaGetSymbolAddress((void**)&klp, g_kl);
    cudaGetSymbolAddress((void**)&vhp, g_vh); cudaGetSymbolAddress((void**)&vlp, g_vl);

    cudaFuncSetAttribute(tc_gemm_kernel, cudaFuncAttributeMaxDynamicSharedMemorySize, TCG_SMEM);
    cudaFuncSetAttribute(flash_attn_kernel, cudaFuncAttributeMaxDynamicSharedMemorySize, FA_SMEM);

    // weight preps (QKV into one combined [6144,4096] buffer); tc_gemm is 6th launch (profiled)
    transpose_split_kernel<<<dim3(DMODEL/64, DMODEL/64), 256>>>(wq, qkvTh, qkvTl, DMODEL, DMODEL);                         // 1
    rmsnorm_h_kernel<<<S_LEN, 256>>>(hidden, ln1, xn);                                                                     // 2
    transpose_split_kernel<<<dim3(NKVH*HDIM/64, DMODEL/64), 256>>>(wk, qkvTh + (size_t)DMODEL*DMODEL, qkvTl + (size_t)DMODEL*DMODEL, DMODEL, NKVH*HDIM);   // 3
    transpose_split_kernel<<<dim3(NKVH*HDIM/64, DMODEL/64), 256>>>(wv, qkvTh + (size_t)(DMODEL+NKVH*HDIM)*DMODEL, qkvTl + (size_t)(DMODEL+NKVH*HDIM)*DMODEL, DMODEL, NKVH*HDIM); // 4
    transpose_split_kernel<<<dim3(DMODEL/64, DMODEL/64), 256>>>(wo, woTh, woTl, DMODEL, DMODEL);                           // 5
    tc_gemm_kernel<<<dim3(S_LEN/128, NQKV/128), 256, TCG_SMEM>>>(                                                          // 6 (profiled)
        xn, qkvTh, qkvTl, q, nullptr, nullptr, nullptr, nullptr, k, vhp, vlp, 1, S_LEN, NQKV, DMODEL);
    transpose_split_kernel<<<dim3(DFFN/64, DMODEL/64), 256>>>(gatew, gwTh, gwTl, DMODEL, DFFN);                            // 7
    transpose_split_kernel<<<dim3(DFFN/64, DMODEL/64), 256>>>(upw,   uwTh, uwTl, DMODEL, DFFN);                            // 8
    transpose_split_kernel<<<dim3(DMODEL/64, DFFN/64), 256>>>(downw, dwTh, dwTl, DFFN, DMODEL);                            // 9

    const float qscale = 0.08838834764831845f;
    rope_l2_split_kernel<<<S_LEN * NHEADS / 8, 256>>>(q, qhp, qlp, NHEADS, cosb, sinb, qscale);
    rope_l2_split_kernel<<<S_LEN * NKVH  / 8, 256>>>(k, khp, klp, NKVH,  cosb, sinb, 1.f);

    flash_attn_kernel<<<dim3(S_LEN / 64, NHEADS), 128, FA_SMEM>>>(qhp, qlp, khp, klp, vhp, vlp, at);

    tc_gemm_kernel<<<dim3(S_LEN/128, DMODEL/128), 256, TCG_SMEM>>>(
        at, woTh, woTl, h, hidden, nullptr, nullptr, nullptr, nullptr, nullptr, nullptr, 0, S_LEN, DMODEL, DMODEL);

    rmsnorm_h_kernel<<<S_LEN, 256>>>(h, ln2, x2);

    tc_gemm_kernel<<<dim3(S_LEN/128, DFFN/128), 256, TCG_SMEM>>>(
        x2, gwTh, gwTl, gate, nullptr, nullptr, nullptr, nullptr, nullptr, nullptr, nullptr, 0, S_LEN, DFFN, DMODEL);
    tc_gemm_kernel<<<dim3(S_LEN/128, DFFN/128), 256, TCG_SMEM>>>(
        x2, uwTh, uwTl, nullptr, nullptr, ga, nullptr, gate, nullptr, nullptr, nullptr, 0, S_LEN, DFFN, DMODEL);

    tc_gemm_kernel<<<dim3(S_LEN/128, DMODEL/128), 256, TCG_SMEM>>>(
        ga, dwTh, dwTl, out, h, nullptr, nullptr, nullptr, nullptr, nullptr, nullptr, 0, S_LEN, DMODEL, DFFN);
}

// round 11
// speedup vs baseline: 1.5102x; 1.0488x over previous
#include <cuda_runtime.h>
#include <cuda_fp16.h>
#include <math.h>
#include <stdint.h>

#define S_LEN  2048
#define DMODEL 4096
#define NHEADS 32
#define NKVH   8
#define HDIM   128
#define DFFN   16384

#define LO_SCALE 1024.0f
#define INV_LO   0.0009765625f

// ================= low-level helpers (base sm_103 ISA: ldmatrix/mma/cp.async) =================
__device__ __forceinline__ uint32_t smem_u32(const void* p) {
    uint32_t a;
    asm("{ .reg .u64 t; cvta.to.shared.u64 t, %1; cvt.u32.u64 %0, t; }" : "=r"(a) : "l"(p));
    return a;
}
__device__ __forceinline__ void cp_async16(uint32_t dst, const void* src) {
    asm volatile("cp.async.cg.shared.global [%0], [%1], 16;" :: "r"(dst), "l"(src));
}
#define CP_COMMIT() asm volatile("cp.async.commit_group;" ::: "memory")
#define CP_WAIT0()  asm volatile("cp.async.wait_group 0;" ::: "memory")
#define CP_WAIT1()  asm volatile("cp.async.wait_group 1;" ::: "memory")

__device__ __forceinline__ void ldsm4(uint32_t* r, uint32_t addr) {
    asm volatile("ldmatrix.sync.aligned.m8n8.x4.shared.b16 {%0,%1,%2,%3}, [%4];"
        : "=r"(r[0]), "=r"(r[1]), "=r"(r[2]), "=r"(r[3]) : "r"(addr));
}
__device__ __forceinline__ void ldsm4t(uint32_t* r, uint32_t addr) {
    asm volatile("ldmatrix.sync.aligned.m8n8.x4.trans.shared.b16 {%0,%1,%2,%3}, [%4];"
        : "=r"(r[0]), "=r"(r[1]), "=r"(r[2]), "=r"(r[3]) : "r"(addr));
}
__device__ __forceinline__ void mmaF32(float* d, const uint32_t* a, uint32_t b0, uint32_t b1) {
    asm volatile("mma.sync.aligned.m16n8k16.row.col.f32.f16.f16.f32 "
        "{%0,%1,%2,%3}, {%4,%5,%6,%7}, {%8,%9}, {%0,%1,%2,%3};"
        : "+f"(d[0]), "+f"(d[1]), "+f"(d[2]), "+f"(d[3])
        : "r"(a[0]), "r"(a[1]), "r"(a[2]), "r"(a[3]), "r"(b0), "r"(b1));
}
__device__ __forceinline__ void mmaF16(uint32_t* d, const uint32_t* a, uint32_t b0, uint32_t b1) {
    asm volatile("mma.sync.aligned.m16n8k16.row.col.f16.f16.f16.f16 "
        "{%0,%1}, {%2,%3,%4,%5}, {%6,%7}, {%0,%1};"
        : "+r"(d[0]), "+r"(d[1])
        : "r"(a[0]), "r"(a[1]), "r"(a[2]), "r"(a[3]), "r"(b0), "r"(b1));
}

__device__ __forceinline__ uint32_t packh(__half a, __half b) {
    __half2 t = __halves2half2(a, b);
    return *(uint32_t*)&t;
}
__device__ __forceinline__ void split2h(float a, float b, uint32_t& hi, uint32_t& lo, float ls) {
    __half ha = __float2half_rn(a), hb = __float2half_rn(b);
    __half la = __float2half_rn((a - __half2float(ha)) * ls);
    __half lb = __float2half_rn((b - __half2float(hb)) * ls);
    hi = packh(ha, hb);
    lo = packh(la, lb);
}

// ================= scratch (device globals; no allocation allowed) =================
__device__ float g_q   [S_LEN * DMODEL];
__device__ float g_k   [S_LEN * NKVH * HDIM];
__device__ float g_h   [S_LEN * DMODEL];
__device__ float g_gate[S_LEN * DFFN];

#define NQKV (DMODEL + 2 * NKVH * HDIM)
__device__ __half g_wqkvT_h[NQKV * DMODEL], g_wqkvT_l[NQKV * DMODEL];
__device__ __half g_woT_h[DMODEL * DMODEL], g_woT_l[DMODEL * DMODEL];
__device__ __half g_gwT_h[DFFN * DMODEL],   g_gwT_l[DFFN * DMODEL];
__device__ __half g_uwT_h[DFFN * DMODEL],   g_uwT_l[DFFN * DMODEL];
__device__ __half g_dwT_h[DMODEL * DFFN],   g_dwT_l[DMODEL * DFFN];

// activations: single fp16 (GEMM A operands)
__device__ __half g_xn[S_LEN * DMODEL];
__device__ __half g_at[S_LEN * DMODEL];
__device__ __half g_x2[S_LEN * DMODEL];
__device__ __half g_ga[S_LEN * DFFN];

// attention operands: Q single fp16; K/V fp16 hi/lo
__device__ __half g_qh[S_LEN * DMODEL];
__device__ __half g_kh[S_LEN * NKVH * HDIM], g_kl[S_LEN * NKVH * HDIM];
__device__ __half g_vh[S_LEN * NKVH * HDIM], g_vl[S_LEN * NKVH * HDIM];

// ================= RMSNorm -> single fp16 =================
__global__ __launch_bounds__(256) void rmsnorm_h_kernel(
    const float* __restrict__ x, const float* __restrict__ w, __half* __restrict__ y)
{
    int row = blockIdx.x;
    const float* xr = x + (size_t)row * DMODEL;

    float4 vals[4];
    float ss = 0.f;
#pragma unroll
    for (int it = 0; it < 4; it++) {
        int idx = (threadIdx.x + it * 256) * 4;
        float4 v = *(const float4*)(xr + idx);
        vals[it] = v;
        ss += v.x*v.x + v.y*v.y + v.z*v.z + v.w*v.w;
    }
#pragma unroll
    for (int o = 16; o; o >>= 1) ss += __shfl_xor_sync(0xffffffffu, ss, o);

    __shared__ float red[8];
    if ((threadIdx.x & 31) == 0) red[threadIdx.x >> 5] = ss;
    __syncthreads();
    float tot = 0.f;
#pragma unroll
    for (int i = 0; i < 8; i++) tot += red[i];
    float inv = rsqrtf(tot * (1.f / DMODEL) + 1e-5f);

#pragma unroll
    for (int it = 0; it < 4; it++) {
        int idx = (threadIdx.x + it * 256) * 4;
        float4 v  = vals[it];
        float4 wv = *(const float4*)(w + idx);
        uint2 hv;
        hv.x = packh(__float2half_rn(v.x * inv * wv.x), __float2half_rn(v.y * inv * wv.y));
        hv.y = packh(__float2half_rn(v.z * inv * wv.z), __float2half_rn(v.w * inv * wv.w));
        *(uint2*)(y + (size_t)row * DMODEL + idx) = hv;
    }
}

// ================= RoPE + L2-norm -> fp16 (hi only if outl==nullptr) =================
__global__ __launch_bounds__(256) void rope_l2_split_kernel(
    const float* __restrict__ in, __half* __restrict__ outh, __half* __restrict__ outl,
    int nheads, const float* __restrict__ cosb, const float* __restrict__ sinb, float scale)
{
    int wid  = (blockIdx.x * 256 + threadIdx.x) >> 5;
    int lane = threadIdx.x & 31;
    int s  = wid / nheads;
    int hh = wid % nheads;
    size_t base = (size_t)s * nheads * HDIM + hh * HDIM + lane * 4;
    float4 vv = *(const float4*)(in + base);

    float c0 = cosb[s * 64 + lane * 2],     s0 = sinb[s * 64 + lane * 2];
    float c1 = cosb[s * 64 + lane * 2 + 1], s1 = sinb[s * 64 + lane * 2 + 1];
    float o0 = vv.x * c0 - vv.y * s0;
    float o1 = vv.x * s0 + vv.y * c0;
    float o2 = vv.z * c1 - vv.w * s1;
    float o3 = vv.z * s1 + vv.w * c1;

    float ss = o0*o0 + o1*o1 + o2*o2 + o3*o3;
#pragma unroll
    for (int o = 16; o; o >>= 1) ss += __shfl_xor_sync(0xffffffffu, ss, o);
    float rr = rsqrtf(ss * (1.f / HDIM) + 1e-5f) * scale;
    o0 *= rr; o1 *= rr; o2 *= rr; o3 *= rr;

    uint2 hv, lv;
    split2h(o0, o1, hv.x, lv.x, 1.f);
    split2h(o2, o3, hv.y, lv.y, 1.f);
    *(uint2*)(outh + base) = hv;
    if (outl) *(uint2*)(outl + base) = lv;
}

// ================= transpose + fp16 hi/lo split (lo x1024): in[K,N] fp32 -> [N,K] =================
__global__ __launch_bounds__(256) void transpose_split_kernel(
    const float* __restrict__ in, __half* __restrict__ hi, __half* __restrict__ lo,
    int K, int N)
{
    __shared__ float s[64][65];
    int r0 = blockIdx.y * 64, c0 = blockIdx.x * 64;
#pragma unroll
    for (int i = 0; i < 8; i++) {
        int idx = threadIdx.x + i * 256;
        int lr = idx >> 5, p = idx & 31;
        float2 v = *(const float2*)(in + (size_t)(r0 + lr) * N + c0 + 2 * p);
        s[lr][2 * p]     = v.x;
        s[lr][2 * p + 1] = v.y;
    }
    __syncthreads();
#pragma unroll
    for (int i = 0; i < 8; i++) {
        int idx = threadIdx.x + i * 256;
        int lr = idx >> 5, p = idx & 31;
        float a = s[2 * p][lr];
        float b = s[2 * p + 1][lr];
        uint32_t hv, lv;
        split2h(a, b, hv, lv, LO_SCALE);
        size_t o = (size_t)(c0 + lr) * K + (r0 + 2 * p);
        *(uint32_t*)(hi + o) = hv;
        *(uint32_t*)(lo + o) = lv;
    }
}

// ================= HMMA GEMM: A fp16 x W(hi [+ lo/1024 if Blo]) =================
// CTA 128x128, K-chunk 128, 2-stage. Main -> f32 acc; correction -> f16 acc folded once.
#define TCG_STAGE_BYTES 98304
#define TCG_SMEM (2 * TCG_STAGE_BYTES)

__global__ __launch_bounds__(256, 1) void tc_gemm_kernel(
    const __half* __restrict__ A,
    const __half* __restrict__ Bhi, const __half* __restrict__ Blo,
    float* __restrict__ C, const float* __restrict__ addend,
    __half* __restrict__ outH,
    const float* __restrict__ gateMul,
    float* __restrict__ kDest, __half* __restrict__ vH, __half* __restrict__ vL, int qkvMode,
    int M, int N, int K)
{
    extern __shared__ char sm[];
    uint32_t sbase = smem_u32(sm);
    int tid = threadIdx.x, lane = tid & 31, wid = tid >> 5;
    int warp_m = wid & 1, warp_n = wid >> 1;
    int by = blockIdx.x, bx = blockIdx.y;   // M-block fastest

    const bool hasLo = (Blo != nullptr);

    const __half* srcs[3] = {
        A   + (size_t)(by * 128) * K,
        Bhi + (size_t)(bx * 128) * K,
        hasLo ? Blo + (size_t)(bx * 128) * K : Bhi };

    int nchunk = K >> 7;

    auto load_stage = [&](int stg, int c) {
        uint32_t dst0 = sbase + stg * TCG_STAGE_BYTES;
        int kc = c << 7;
#pragma unroll
        for (int i = 0; i < 24; i++) {
            int u = i * 256 + tid;
            int tile = u >> 11, w = u & 2047;
            if (tile == 2 && !hasLo) continue;
            int row = w >> 4, c16 = w & 15;
            uint32_t dst = dst0 + tile * 32768 + row * 256 + ((c16 ^ (row & 7)) << 4);
            cp_async16(dst, srcs[tile] + (size_t)row * K + kc + c16 * 8);
        }
    };

    load_stage(0, 0); CP_COMMIT();

    float acc[4][4][4];
    uint32_t cacc[4][4][2];
#pragma unroll
    for (int a = 0; a < 4; a++)
#pragma unroll
        for (int b = 0; b < 4; b++) {
#pragma unroll
            for (int f = 0; f < 4; f++) acc[a][b][f] = 0.f;
            cacc[a][b][0] = 0u; cacc[a][b][1] = 0u;
        }

    int a_r   = warp_m * 64 + (lane & 15);
    int a_kh  = lane >> 4;
    int b_r   = warp_n * 32 + (lane & 7) + ((lane >> 4) << 3);
    int b_kh  = (lane >> 3) & 1;

    for (int c = 0; c < nchunk; c++) {
        if (c + 1 < nchunk) { load_stage((c + 1) & 1, c + 1); CP_COMMIT(); CP_WAIT1(); }
        else                { CP_WAIT0(); }
        __syncthreads();

        uint32_t st = sbase + (c & 1) * TCG_STAGE_BYTES;
#pragma unroll
        for (int kk = 0; kk < 8; kk++) {
            int c16 = kk * 2;
            uint32_t ah[4][4], bh[2][4], bl[2][4];
#pragma unroll
            for (int mb = 0; mb < 4; mb++) {
                int r = a_r + mb * 16;
                uint32_t off = r * 256 + (((c16 + a_kh) ^ (r & 7)) << 4);
                ldsm4(ah[mb], st + off);
            }
#pragma unroll
            for (int nb = 0; nb < 2; nb++) {
                int r = b_r + nb * 16;
                uint32_t off = r * 256 + (((c16 + b_kh) ^ (r & 7)) << 4);
                ldsm4(bh[nb], st + 32768 + off);
                if (hasLo) ldsm4(bl[nb], st + 65536 + off);
            }
#pragma unroll
            for (int mb = 0; mb < 4; mb++)
#pragma unroll
                for (int nb = 0; nb < 4; nb++) {
                    uint32_t b0h = bh[nb >> 1][(nb & 1) * 2], b1h = bh[nb >> 1][(nb & 1) * 2 + 1];
                    mmaF32(acc[mb][nb], ah[mb], b0h, b1h);
                    if (hasLo) {
                        uint32_t b0l = bl[nb >> 1][(nb & 1) * 2], b1l = bl[nb >> 1][(nb & 1) * 2 + 1];
                        mmaF16(cacc[mb][nb], ah[mb], b0l, b1l);
                    }
                }
        }
        __syncthreads();
    }

    if (hasLo) {
#pragma unroll
        for (int mb = 0; mb < 4; mb++)
#pragma unroll
            for (int nb = 0; nb < 4; nb++) {
                float2 f01 = __half22float2(*(__half2*)&cacc[mb][nb][0]);
                float2 f23 = __half22float2(*(__half2*)&cacc[mb][nb][1]);
                acc[mb][nb][0] = fmaf(f01.x, INV_LO, acc[mb][nb][0]);
                acc[mb][nb][1] = fmaf(f01.y, INV_LO, acc[mb][nb][1]);
                acc[mb][nb][2] = fmaf(f23.x, INV_LO, acc[mb][nb][2]);
                acc[mb][nb][3] = fmaf(f23.y, INV_LO, acc[mb][nb][3]);
            }
    }

#pragma unroll
    for (int mb = 0; mb < 4; mb++) {
        int mrow = by * 128 + warp_m * 64 + mb * 16 + (lane >> 2);
#pragma unroll
        for (int nb = 0; nb < 4; nb++) {
            int ncol = bx * 128 + warp_n * 32 + nb * 8 + (lane & 3) * 2;
            float2 r0 = make_float2(acc[mb][nb][0], acc[mb][nb][1]);
            float2 r1 = make_float2(acc[mb][nb][2], acc[mb][nb][3]);

            if (qkvMode) {
                if (ncol < DMODEL) {
                    size_t i0 = (size_t)mrow * DMODEL + ncol;
                    size_t i1 = (size_t)(mrow + 8) * DMODEL + ncol;
                    *(float2*)(C + i0) = r0;
                    *(float2*)(C + i1) = r1;
                } else if (ncol < DMODEL + NKVH * HDIM) {
                    int cc = ncol - DMODEL;
                    size_t i0 = (size_t)mrow * (NKVH * HDIM) + cc;
                    size_t i1 = (size_t)(mrow + 8) * (NKVH * HDIM) + cc;
                    *(float2*)(kDest + i0) = r0;
                    *(float2*)(kDest + i1) = r1;
                } else {
                    int cc = ncol - DMODEL - NKVH * HDIM;
                    size_t i0 = (size_t)mrow * (NKVH * HDIM) + cc;
                    size_t i1 = (size_t)(mrow + 8) * (NKVH * HDIM) + cc;
                    uint32_t h0, l0, h1, l1;
                    split2h(r0.x, r0.y, h0, l0, 1.f);
                    split2h(r1.x, r1.y, h1, l1, 1.f);
                    *(uint32_t*)(vH + i0) = h0;
                    *(uint32_t*)(vL + i0) = l0;
                    *(uint32_t*)(vH + i1) = h1;
                    *(uint32_t*)(vL + i1) = l1;
                }
                continue;
            }

            size_t i0 = (size_t)mrow * N + ncol;
            size_t i1 = (size_t)(mrow + 8) * N + ncol;
            if (addend) {
                float2 a0 = *(const float2*)(addend + i0);
                float2 a1 = *(const float2*)(addend + i1);
                r0.x += a0.x; r0.y += a0.y;
                r1.x += a1.x; r1.y += a1.y;
            }
            if (gateMul) {
                float2 g0 = *(const float2*)(gateMul + i0);
                float2 g1 = *(const float2*)(gateMul + i1);
                r0.x *= g0.x / (1.f + __expf(-g0.x));
                r0.y *= g0.y / (1.f + __expf(-g0.y));
                r1.x *= g1.x / (1.f + __expf(-g1.x));
                r1.y *= g1.y / (1.f + __expf(-g1.y));
            }
            if (C) {
                *(float2*)(C + i0) = r0;
                *(float2*)(C + i1) = r1;
            }
            if (outH) {
                *(uint32_t*)(outH + i0) = packh(__float2half_rn(r0.x), __float2half_rn(r0.y));
                *(uint32_t*)(outH + i1) = packh(__float2half_rn(r1.x), __float2half_rn(r1.y));
            }
        }
    }
}

// ================= HMMA causal flash attention: Q fp16, K/V hi+lo, P hi =================
#define FA_STAGE_OFF 32768
#define FA_STAGE_BYTES 65536
#define FA_SMEM (FA_STAGE_OFF + 2 * FA_STAGE_BYTES)   // 160KB

__global__ __launch_bounds__(128, 1) void flash_attn_kernel(
    const __half* __restrict__ qh,
    const __half* __restrict__ kh, const __half* __restrict__ kl,
    const __half* __restrict__ vh, const __half* __restrict__ vl,
    __half* __restrict__ o)
{
    extern __shared__ char sm[];
    uint32_t sbase = smem_u32(sm);
    int qb = blockIdx.x, h = blockIdx.y, kvh = h >> 2;
    int tid = threadIdx.x, lane = tid & 31, w = tid >> 5;

#pragma unroll
    for (int i = 0; i < 8; i++) {
        int u = tid + i * 128;
        int row = u >> 4, c16 = u & 15;
        uint32_t dst = sbase + row * 256 + ((c16 ^ (row & 7)) << 4);
        cp_async16(dst, qh + (size_t)(qb * 64 + row) * DMODEL + h * HDIM + c16 * 8);
    }

    auto load_kv = [&](int stg, int kb) {
        uint32_t dst0 = sbase + FA_STAGE_OFF + stg * FA_STAGE_BYTES;
        const __half* srcs[4] = { kh, kl, vh, vl };
#pragma unroll
        for (int b = 0; b < 4; b++) {
            const __half* s = srcs[b];
#pragma unroll
            for (int i = 0; i < 8; i++) {
                int u = tid + i * 128;
                int row = u >> 4, c16 = u & 15;
                uint32_t dst = dst0 + b * 16384 + row * 256 + ((c16 ^ (row & 7)) << 4);
                cp_async16(dst, s + (size_t)(kb * 64 + row) * (NKVH * HDIM) + kvh * HDIM + c16 * 8);
            }
        }
    };

    load_kv(0, 0); CP_COMMIT();
    if (qb >= 1) load_kv(1, 1);
    CP_COMMIT();

    float O[16][4];
#pragma unroll
    for (int i = 0; i < 16; i++)
#pragma unroll
        for (int f = 0; f < 4; f++) O[i][f] = 0.f;
    float m_lo = -1e30f, m_hi = -1e30f, l_lo = 0.f, l_hi = 0.f;

    int r_loc = w * 16 + (lane >> 2);

    for (int kb = 0; kb <= qb; kb++) {
        CP_WAIT1();
        __syncthreads();
        uint32_t kbase = sbase + FA_STAGE_OFF + (kb & 1) * FA_STAGE_BYTES;

        float S[8][4];
#pragma unroll
        for (int i = 0; i < 8; i++)
#pragma unroll
            for (int f = 0; f < 4; f++) S[i][f] = 0.f;

#pragma unroll
        for (int kk = 0; kk < 8; kk++) {
            uint32_t aq[4];
            int ar = w * 16 + (lane & 15);
            int ac = kk * 2 + (lane >> 4);
            ldsm4(aq, sbase + ar * 256 + ((ac ^ (ar & 7)) << 4));
#pragma unroll
            for (int nblk = 0; nblk < 4; nblk++) {
                int br = nblk * 16 + (lane & 7) + ((lane >> 4) << 3);
                int bc = kk * 2 + ((lane >> 3) & 1);
                uint32_t boff = br * 256 + ((bc ^ (br & 7)) << 4);
                uint32_t bh4[4], bl4[4];
                ldsm4(bh4, kbase + boff);
                ldsm4(bl4, kbase + 16384 + boff);
                mmaF32(S[2*nblk],   aq, bh4[0], bh4[1]);
                mmaF32(S[2*nblk],   aq, bl4[0], bl4[1]);
                mmaF32(S[2*nblk+1], aq, bh4[2], bh4[3]);
                mmaF32(S[2*nblk+1], aq, bl4[2], bl4[3]);
            }
        }

        if (kb == qb) {
#pragma unroll
            for (int nt = 0; nt < 8; nt++) {
                int c = nt * 8 + (lane & 3) * 2;
                if (c     > r_loc)     S[nt][0] = -1e30f;
                if (c + 1 > r_loc)     S[nt][1] = -1e30f;
                if (c     > r_loc + 8) S[nt][2] = -1e30f;
                if (c + 1 > r_loc + 8) S[nt][3] = -1e30f;
            }
        }

        float rm_lo = -1e30f, rm_hi = -1e30f;
#pragma unroll
        for (int nt = 0; nt < 8; nt++) {
            rm_lo = fmaxf(rm_lo, fmaxf(S[nt][0], S[nt][1]));
            rm_hi = fmaxf(rm_hi, fmaxf(S[nt][2], S[nt][3]));
        }
        rm_lo = fmaxf(rm_lo, __shfl_xor_sync(0xffffffffu, rm_lo, 1));
        rm_lo = fmaxf(rm_lo, __shfl_xor_sync(0xffffffffu, rm_lo, 2));
        rm_hi = fmaxf(rm_hi, __shfl_xor_sync(0xffffffffu, rm_hi, 1));
        rm_hi = fmaxf(rm_hi, __shfl_xor_sync(0xffffffffu, rm_hi, 2));
        float mn_lo = fmaxf(m_lo, rm_lo), mn_hi = fmaxf(m_hi, rm_hi);
        float corr_lo = __expf(m_lo - mn_lo), corr_hi = __expf(m_hi - mn_hi);

        uint32_t ph[8][2];
        float sum_lo = 0.f, sum_hi = 0.f;
#pragma unroll
        for (int nt = 0; nt < 8; nt++) {
            float p0 = __expf(S[nt][0] - mn_lo);
            float p1 = __expf(S[nt][1] - mn_lo);
            float p2 = __expf(S[nt][2] - mn_hi);
            float p3 = __expf(S[nt][3] - mn_hi);
            sum_lo += p0 + p1; sum_hi += p2 + p3;
            ph[nt][0] = packh(__float2half_rn(p0), __float2half_rn(p1));
            ph[nt][1] = packh(__float2half_rn(p2), __float2half_rn(p3));
        }
        sum_lo += __shfl_xor_sync(0xffffffffu, sum_lo, 1);
        sum_lo += __shfl_xor_sync(0xffffffffu, sum_lo, 2);
        sum_hi += __shfl_xor_sync(0xffffffffu, sum_hi, 1);
        sum_hi += __shfl_xor_sync(0xffffffffu, sum_hi, 2);
        l_lo = l_lo * corr_lo + sum_lo;
        l_hi = l_hi * corr_hi + sum_hi;
        m_lo = mn_lo; m_hi = mn_hi;
#pragma unroll
        for (int ot = 0; ot < 16; ot++) {
            O[ot][0] *= corr_lo; O[ot][1] *= corr_lo;
            O[ot][2] *= corr_hi; O[ot][3] *= corr_hi;
        }

        uint32_t vbase = kbase + 32768;
#pragma unroll
        for (int kt = 0; kt < 4; kt++) {
            uint32_t aH[4] = { ph[2*kt][0], ph[2*kt][1], ph[2*kt+1][0], ph[2*kt+1][1] };
            int krow = kt * 16 + (lane & 7) + ((lane >> 3) & 1) * 8;
#pragma unroll
            for (int ob = 0; ob < 8; ob++) {
                int cu = ob * 2 + (lane >> 4);
                uint32_t off = krow * 256 + ((cu ^ (krow & 7)) << 4);
                uint32_t bvh[4], bvl[4];
                ldsm4t(bvh, vbase + off);
                ldsm4t(bvl, vbase + 16384 + off);
                mmaF32(O[2*ob],   aH, bvh[0], bvh[1]);
                mmaF32(O[2*ob],   aH, bvl[0], bvl[1]);
                mmaF32(O[2*ob+1], aH, bvh[2], bvh[3]);
                mmaF32(O[2*ob+1], aH, bvl[2], bvl[3]);
            }
        }

        __syncthreads();
        if (kb + 2 <= qb) load_kv(kb & 1, kb + 2);
        CP_COMMIT();
    }

    float il_lo = 1.f / l_lo, il_hi = 1.f / l_hi;
    int row0 = qb * 64 + r_loc;
#pragma unroll
    for (int ot = 0; ot < 16; ot++) {
        int col = h * HDIM + ot * 8 + (lane & 3) * 2;
        size_t i0 = (size_t)row0 * DMODEL + col;
        size_t i1 = (size_t)(row0 + 8) * DMODEL + col;
        *(uint32_t*)(o + i0) = packh(__float2half_rn(O[ot][0] * il_lo), __float2half_rn(O[ot][1] * il_lo));
        *(uint32_t*)(o + i1) = packh(__float2half_rn(O[ot][2] * il_hi), __float2half_rn(O[ot][3] * il_hi));
    }
}

// ================= host launcher =================
extern "C" void kernel_launch(void* const* d_in, const int* in_sizes, int n_in,
                              void* d_out, int out_size)
{
    const float* hidden = (const float*)d_in[0];
    const float* cosb  = (const float*)d_in[2];
    const float* sinb  = (const float*)d_in[3];
    const float* ln1   = (const float*)d_in[4];
    const float* wq    = (const float*)d_in[5];
    const float* wk    = (const float*)d_in[6];
    const float* wv    = (const float*)d_in[7];
    const float* wo    = (const float*)d_in[8];
    const float* ln2   = (const float*)d_in[9];
    const float* gatew = (const float*)d_in[10];
    const float* upw   = (const float*)d_in[11];
    const float* downw = (const float*)d_in[12];
    float* out = (float*)d_out;

    float *q, *k, *h, *gate;
    cudaGetSymbolAddress((void**)&q,    g_q);
    cudaGetSymbolAddress((void**)&k,    g_k);
    cudaGetSymbolAddress((void**)&h,    g_h);
    cudaGetSymbolAddress((void**)&gate, g_gate);

    __half *qkvTh,*qkvTl,*woTh,*woTl,*gwTh,*gwTl,*uwTh,*uwTl,*dwTh,*dwTl;
    cudaGetSymbolAddress((void**)&qkvTh, g_wqkvT_h); cudaGetSymbolAddress((void**)&qkvTl, g_wqkvT_l);
    cudaGetSymbolAddress((void**)&woTh, g_woT_h); cudaGetSymbolAddress((void**)&woTl, g_woT_l);
    cudaGetSymbolAddress((void**)&gwTh, g_gwT_h); cudaGetSymbolAddress((void**)&gwTl, g_gwT_l);
    cudaGetSymbolAddress((void**)&uwTh, g_uwT_h); cudaGetSymbolAddress((void**)&uwTl, g_uwT_l);
    cudaGetSymbolAddress((void**)&dwTh, g_dwT_h); cudaGetSymbolAddress((void**)&dwTl, g_dwT_l);

    __half *xn,*at,*x2,*ga,*qhp,*khp,*klp,*vhp,*vlp;
    cudaGetSymbolAddress((void**)&xn, g_xn);
    cudaGetSymbolAddress((void**)&at, g_at);
    cudaGetSymbolAddress((void**)&x2, g_x2);
    cudaGetSymbolAddress((void**)&ga, g_ga);
    cudaGetSymbolAddress((void**)&qhp, g_qh);
    cudaGetSymbolAddress((void**)&khp, g_kh); cudaGetSymbolAddress((void**)&klp, g_kl);
    cudaGetSymbolAddress((void**)&vhp, g_vh); cudaGetSymbolAddress((void**)&vlp, g_vl);

    cudaFuncSetAttribute(tc_gemm_kernel, cudaFuncAttributeMaxDynamicSharedMemorySize, TCG_SMEM);
    cudaFuncSetAttribute(flash_attn_kernel, cudaFuncAttributeMaxDynamicSharedMemorySize, FA_SMEM);

    // side stream + events: created once, OUTSIDE capture (first call is the correctness run)
    static cudaStream_t s2 = nullptr;
    static cudaEvent_t evFork = nullptr, evJoin = nullptr;
    if (!s2) {
        cudaStreamCreateWithFlags(&s2, cudaStreamNonBlocking);
        cudaEventCreateWithFlags(&evFork, cudaEventDisableTiming);
        cudaEventCreateWithFlags(&evJoin, cudaEventDisableTiming);
    }

    // ---- main stream: QKV weight prep + rmsnorm ----
    rmsnorm_h_kernel<<<S_LEN, 256>>>(hidden, ln1, xn);
    transpose_split_kernel<<<dim3(DMODEL/64, DMODEL/64), 256>>>(wq, qkvTh, qkvTl, DMODEL, DMODEL);
    transpose_split_kernel<<<dim3(NKVH*HDIM/64, DMODEL/64), 256>>>(wk, qkvTh + (size_t)DMODEL*DMODEL, qkvTl + (size_t)DMODEL*DMODEL, DMODEL, NKVH*HDIM);
    transpose_split_kernel<<<dim3(NKVH*HDIM/64, DMODEL/64), 256>>>(wv, qkvTh + (size_t)(DMODEL+NKVH*HDIM)*DMODEL, qkvTl + (size_t)(DMODEL+NKVH*HDIM)*DMODEL, DMODEL, NKVH*HDIM);

    // ---- fork: wo/gate/up/down transposes run on side stream, overlapped with attention chain ----
    cudaEventRecord(evFork, 0);
    cudaStreamWaitEvent(s2, evFork, 0);
    transpose_split_kernel<<<dim3(DMODEL/64, DMODEL/64), 256, 0, s2>>>(wo, woTh, woTl, DMODEL, DMODEL);
    transpose_split_kernel<<<dim3(DFFN/64, DMODEL/64), 256, 0, s2>>>(gatew, gwTh, gwTl, DMODEL, DFFN);
    transpose_split_kernel<<<dim3(DFFN/64, DMODEL/64), 256, 0, s2>>>(upw, uwTh, uwTl, DMODEL, DFFN);
    transpose_split_kernel<<<dim3(DMODEL/64, DFFN/64), 256, 0, s2>>>(downw, dwTh, dwTl, DFFN, DMODEL);
    cudaEventRecord(evJoin, s2);

    // ---- main chain: QKV (1-term) -> rope -> attention ----
    tc_gemm_kernel<<<dim3(S_LEN/128, NQKV/128), 256, TCG_SMEM>>>(
        xn, qkvTh, nullptr, q, nullptr, nullptr, nullptr, k, vhp, vlp, 1, S_LEN, NQKV, DMODEL);

    const float qscale = 0.08838834764831845f;
    rope_l2_split_kernel<<<S_LEN * NHEADS / 8, 256>>>(q, qhp, nullptr, NHEADS, cosb, sinb, qscale);
    rope_l2_split_kernel<<<S_LEN * NKVH  / 8, 256>>>(k, khp, klp, NKVH,  cosb, sinb, 1.f);

    flash_attn_kernel<<<dim3(S_LEN / 64, NHEADS), 128, FA_SMEM>>>(qhp, khp, klp, vhp, vlp, at);

    // ---- join: weight prep must be done before wo GEMM ----
    cudaStreamWaitEvent(0, evJoin, 0);

    tc_gemm_kernel<<<dim3(S_LEN/128, DMODEL/128), 256, TCG_SMEM>>>(
        at, woTh, woTl, h, hidden, nullptr, nullptr, nullptr, nullptr, nullptr, 0, S_LEN, DMODEL, DMODEL);

    rmsnorm_h_kernel<<<S_LEN, 256>>>(h, ln2, x2);

    tc_gemm_kernel<<<dim3(S_LEN/128, DFFN/128), 256, TCG_SMEM>>>(
        x2, gwTh, gwTl, gate, nullptr, nullptr, nullptr, nullptr, nullptr, nullptr, 0, S_LEN, DFFN, DMODEL);
    tc_gemm_kernel<<<dim3(S_LEN/128, DFFN/128), 256, TCG_SMEM>>>(
        x2, uwTh, uwTl, nullptr, nullptr, ga, gate, nullptr, nullptr, nullptr, 0, S_LEN, DFFN, DMODEL);

    tc_gemm_kernel<<<dim3(S_LEN/128, DMODEL/128), 256, TCG_SMEM>>>(
        ga, dwTh, dwTl, out, h, nullptr, nullptr, nullptr, nullptr, nullptr, 0, S_LEN, DMODEL, DFFN);
}

// round 12
// speedup vs baseline: 1.5588x; 1.0322x over previous
#include <cuda_runtime.h>
#include <cuda_fp16.h>
#include <math.h>
#include <stdint.h>

#define S_LEN  2048
#define DMODEL 4096
#define NHEADS 32
#define NKVH   8
#define HDIM   128
#define DFFN   16384

#define LO_SCALE 1024.0f
#define INV_LO   0.0009765625f

// ================= low-level helpers (base sm_103 ISA: ldmatrix/mma/cp.async) =================
__device__ __forceinline__ uint32_t smem_u32(const void* p) {
    uint32_t a;
    asm("{ .reg .u64 t; cvta.to.shared.u64 t, %1; cvt.u32.u64 %0, t; }" : "=r"(a) : "l"(p));
    return a;
}
__device__ __forceinline__ void cp_async16(uint32_t dst, const void* src) {
    asm volatile("cp.async.cg.shared.global [%0], [%1], 16;" :: "r"(dst), "l"(src));
}
#define CP_COMMIT() asm volatile("cp.async.commit_group;" ::: "memory")
#define CP_WAIT0()  asm volatile("cp.async.wait_group 0;" ::: "memory")
#define CP_WAIT1()  asm volatile("cp.async.wait_group 1;" ::: "memory")

__device__ __forceinline__ void ldsm4(uint32_t* r, uint32_t addr) {
    asm volatile("ldmatrix.sync.aligned.m8n8.x4.shared.b16 {%0,%1,%2,%3}, [%4];"
        : "=r"(r[0]), "=r"(r[1]), "=r"(r[2]), "=r"(r[3]) : "r"(addr));
}
__device__ __forceinline__ void ldsm4t(uint32_t* r, uint32_t addr) {
    asm volatile("ldmatrix.sync.aligned.m8n8.x4.trans.shared.b16 {%0,%1,%2,%3}, [%4];"
        : "=r"(r[0]), "=r"(r[1]), "=r"(r[2]), "=r"(r[3]) : "r"(addr));
}
__device__ __forceinline__ void mmaF32(float* d, const uint32_t* a, uint32_t b0, uint32_t b1) {
    asm volatile("mma.sync.aligned.m16n8k16.row.col.f32.f16.f16.f32 "
        "{%0,%1,%2,%3}, {%4,%5,%6,%7}, {%8,%9}, {%0,%1,%2,%3};"
        : "+f"(d[0]), "+f"(d[1]), "+f"(d[2]), "+f"(d[3])
        : "r"(a[0]), "r"(a[1]), "r"(a[2]), "r"(a[3]), "r"(b0), "r"(b1));
}
__device__ __forceinline__ void mmaF16(uint32_t* d, const uint32_t* a, uint32_t b0, uint32_t b1) {
    asm volatile("mma.sync.aligned.m16n8k16.row.col.f16.f16.f16.f16 "
        "{%0,%1}, {%2,%3,%4,%5}, {%6,%7}, {%0,%1};"
        : "+r"(d[0]), "+r"(d[1])
        : "r"(a[0]), "r"(a[1]), "r"(a[2]), "r"(a[3]), "r"(b0), "r"(b1));
}

__device__ __forceinline__ uint32_t packh(__half a, __half b) {
    __half2 t = __halves2half2(a, b);
    return *(uint32_t*)&t;
}
__device__ __forceinline__ void split2h(float a, float b, uint32_t& hi, uint32_t& lo, float ls) {
    __half ha = __float2half_rn(a), hb = __float2half_rn(b);
    __half la = __float2half_rn((a - __half2float(ha)) * ls);
    __half lb = __float2half_rn((b - __half2float(hb)) * ls);
    hi = packh(ha, hb);
    lo = packh(la, lb);
}

// ================= scratch (device globals; no allocation allowed) =================
__device__ float g_q   [S_LEN * DMODEL];
__device__ float g_k   [S_LEN * NKVH * HDIM];
__device__ float g_h   [S_LEN * DMODEL];
__device__ float g_gate[S_LEN * DFFN];

#define NQKV (DMODEL + 2 * NKVH * HDIM)
__device__ __half g_wqkvT_h[NQKV * DMODEL], g_wqkvT_l[NQKV * DMODEL];
__device__ __half g_woT_h[DMODEL * DMODEL], g_woT_l[DMODEL * DMODEL];
__device__ __half g_gwT_h[DFFN * DMODEL];
__device__ __half g_uwT_h[DFFN * DMODEL];
__device__ __half g_dwT_h[DMODEL * DFFN],   g_dwT_l[DMODEL * DFFN];

// activations: single fp16 (GEMM A operands)
__device__ __half g_xn[S_LEN * DMODEL];
__device__ __half g_at[S_LEN * DMODEL];
__device__ __half g_x2[S_LEN * DMODEL];
__device__ __half g_ga[S_LEN * DFFN];

// attention operands: Q single fp16; K/V fp16 hi/lo
__device__ __half g_qh[S_LEN * DMODEL];
__device__ __half g_kh[S_LEN * NKVH * HDIM], g_kl[S_LEN * NKVH * HDIM];
__device__ __half g_vh[S_LEN * NKVH * HDIM], g_vl[S_LEN * NKVH * HDIM];

// ================= RMSNorm -> single fp16 =================
__global__ __launch_bounds__(256) void rmsnorm_h_kernel(
    const float* __restrict__ x, const float* __restrict__ w, __half* __restrict__ y)
{
    int row = blockIdx.x;
    const float* xr = x + (size_t)row * DMODEL;

    float4 vals[4];
    float ss = 0.f;
#pragma unroll
    for (int it = 0; it < 4; it++) {
        int idx = (threadIdx.x + it * 256) * 4;
        float4 v = *(const float4*)(xr + idx);
        vals[it] = v;
        ss += v.x*v.x + v.y*v.y + v.z*v.z + v.w*v.w;
    }
#pragma unroll
    for (int o = 16; o; o >>= 1) ss += __shfl_xor_sync(0xffffffffu, ss, o);

    __shared__ float red[8];
    if ((threadIdx.x & 31) == 0) red[threadIdx.x >> 5] = ss;
    __syncthreads();
    float tot = 0.f;
#pragma unroll
    for (int i = 0; i < 8; i++) tot += red[i];
    float inv = rsqrtf(tot * (1.f / DMODEL) + 1e-5f);

#pragma unroll
    for (int it = 0; it < 4; it++) {
        int idx = (threadIdx.x + it * 256) * 4;
        float4 v  = vals[it];
        float4 wv = *(const float4*)(w + idx);
        uint2 hv;
        hv.x = packh(__float2half_rn(v.x * inv * wv.x), __float2half_rn(v.y * inv * wv.y));
        hv.y = packh(__float2half_rn(v.z * inv * wv.z), __float2half_rn(v.w * inv * wv.w));
        *(uint2*)(y + (size_t)row * DMODEL + idx) = hv;
    }
}

// ================= RoPE + L2-norm -> fp16 (hi only if outl==nullptr) =================
__global__ __launch_bounds__(256) void rope_l2_split_kernel(
    const float* __restrict__ in, __half* __restrict__ outh, __half* __restrict__ outl,
    int nheads, const float* __restrict__ cosb, const float* __restrict__ sinb, float scale)
{
    int wid  = (blockIdx.x * 256 + threadIdx.x) >> 5;
    int lane = threadIdx.x & 31;
    int s  = wid / nheads;
    int hh = wid % nheads;
    size_t base = (size_t)s * nheads * HDIM + hh * HDIM + lane * 4;
    float4 vv = *(const float4*)(in + base);

    float c0 = cosb[s * 64 + lane * 2],     s0 = sinb[s * 64 + lane * 2];
    float c1 = cosb[s * 64 + lane * 2 + 1], s1 = sinb[s * 64 + lane * 2 + 1];
    float o0 = vv.x * c0 - vv.y * s0;
    float o1 = vv.x * s0 + vv.y * c0;
    float o2 = vv.z * c1 - vv.w * s1;
    float o3 = vv.z * s1 + vv.w * c1;

    float ss = o0*o0 + o1*o1 + o2*o2 + o3*o3;
#pragma unroll
    for (int o = 16; o; o >>= 1) ss += __shfl_xor_sync(0xffffffffu, ss, o);
    float rr = rsqrtf(ss * (1.f / HDIM) + 1e-5f) * scale;
    o0 *= rr; o1 *= rr; o2 *= rr; o3 *= rr;

    uint2 hv, lv;
    split2h(o0, o1, hv.x, lv.x, 1.f);
    split2h(o2, o3, hv.y, lv.y, 1.f);
    *(uint2*)(outh + base) = hv;
    if (outl) *(uint2*)(outl + base) = lv;
}

// ================= transpose + fp16 split (lo optional, x1024): in[K,N] fp32 -> [N,K] =================
__global__ __launch_bounds__(256) void transpose_split_kernel(
    const float* __restrict__ in, __half* __restrict__ hi, __half* __restrict__ lo,
    int K, int N)
{
    __shared__ float s[64][65];
    int r0 = blockIdx.y * 64, c0 = blockIdx.x * 64;
#pragma unroll
    for (int i = 0; i < 8; i++) {
        int idx = threadIdx.x + i * 256;
        int lr = idx >> 5, p = idx & 31;
        float2 v = *(const float2*)(in + (size_t)(r0 + lr) * N + c0 + 2 * p);
        s[lr][2 * p]     = v.x;
        s[lr][2 * p + 1] = v.y;
    }
    __syncthreads();
#pragma unroll
    for (int i = 0; i < 8; i++) {
        int idx = threadIdx.x + i * 256;
        int lr = idx >> 5, p = idx & 31;
        float a = s[2 * p][lr];
        float b = s[2 * p + 1][lr];
        uint32_t hv, lv;
        split2h(a, b, hv, lv, LO_SCALE);
        size_t o = (size_t)(c0 + lr) * K + (r0 + 2 * p);
        *(uint32_t*)(hi + o) = hv;
        if (lo) *(uint32_t*)(lo + o) = lv;
    }
}

// ================= HMMA GEMM: A fp16 x W(hi [+ lo/1024 if Blo]) =================
// CTA 128x128, K-chunk 128, 2-stage. Main -> f32 acc; correction -> f16 acc folded once.
#define TCG_STAGE_BYTES 98304
#define TCG_SMEM (2 * TCG_STAGE_BYTES)

__global__ __launch_bounds__(256, 1) void tc_gemm_kernel(
    const __half* __restrict__ A,
    const __half* __restrict__ Bhi, const __half* __restrict__ Blo,
    float* __restrict__ C, const float* __restrict__ addend,
    __half* __restrict__ outH,
    const float* __restrict__ gateMul,
    float* __restrict__ kDest, __half* __restrict__ vH, __half* __restrict__ vL, int qkvMode,
    int M, int N, int K)
{
    extern __shared__ char sm[];
    uint32_t sbase = smem_u32(sm);
    int tid = threadIdx.x, lane = tid & 31, wid = tid >> 5;
    int warp_m = wid & 1, warp_n = wid >> 1;
    int by = blockIdx.x, bx = blockIdx.y;   // M-block fastest

    const bool hasLo = (Blo != nullptr);

    const __half* srcs[3] = {
        A   + (size_t)(by * 128) * K,
        Bhi + (size_t)(bx * 128) * K,
        hasLo ? Blo + (size_t)(bx * 128) * K : Bhi };

    int nchunk = K >> 7;

    auto load_stage = [&](int stg, int c) {
        uint32_t dst0 = sbase + stg * TCG_STAGE_BYTES;
        int kc = c << 7;
#pragma unroll
        for (int i = 0; i < 24; i++) {
            int u = i * 256 + tid;
            int tile = u >> 11, w = u & 2047;
            if (tile == 2 && !hasLo) continue;
            int row = w >> 4, c16 = w & 15;
            uint32_t dst = dst0 + tile * 32768 + row * 256 + ((c16 ^ (row & 7)) << 4);
            cp_async16(dst, srcs[tile] + (size_t)row * K + kc + c16 * 8);
        }
    };

    load_stage(0, 0); CP_COMMIT();

    float acc[4][4][4];
    uint32_t cacc[4][4][2];
#pragma unroll
    for (int a = 0; a < 4; a++)
#pragma unroll
        for (int b = 0; b < 4; b++) {
#pragma unroll
            for (int f = 0; f < 4; f++) acc[a][b][f] = 0.f;
            cacc[a][b][0] = 0u; cacc[a][b][1] = 0u;
        }

    int a_r   = warp_m * 64 + (lane & 15);
    int a_kh  = lane >> 4;
    int b_r   = warp_n * 32 + (lane & 7) + ((lane >> 4) << 3);
    int b_kh  = (lane >> 3) & 1;

    for (int c = 0; c < nchunk; c++) {
        if (c + 1 < nchunk) { load_stage((c + 1) & 1, c + 1); CP_COMMIT(); CP_WAIT1(); }
        else                { CP_WAIT0(); }
        __syncthreads();

        uint32_t st = sbase + (c & 1) * TCG_STAGE_BYTES;
#pragma unroll
        for (int kk = 0; kk < 8; kk++) {
            int c16 = kk * 2;
            uint32_t ah[4][4], bh[2][4], bl[2][4];
#pragma unroll
            for (int mb = 0; mb < 4; mb++) {
                int r = a_r + mb * 16;
                uint32_t off = r * 256 + (((c16 + a_kh) ^ (r & 7)) << 4);
                ldsm4(ah[mb], st + off);
            }
#pragma unroll
            for (int nb = 0; nb < 2; nb++) {
                int r = b_r + nb * 16;
                uint32_t off = r * 256 + (((c16 + b_kh) ^ (r & 7)) << 4);
                ldsm4(bh[nb], st + 32768 + off);
                if (hasLo) ldsm4(bl[nb], st + 65536 + off);
            }
#pragma unroll
            for (int mb = 0; mb < 4; mb++)
#pragma unroll
                for (int nb = 0; nb < 4; nb++) {
                    uint32_t b0h = bh[nb >> 1][(nb & 1) * 2], b1h = bh[nb >> 1][(nb & 1) * 2 + 1];
                    mmaF32(acc[mb][nb], ah[mb], b0h, b1h);
                    if (hasLo) {
                        uint32_t b0l = bl[nb >> 1][(nb & 1) * 2], b1l = bl[nb >> 1][(nb & 1) * 2 + 1];
                        mmaF16(cacc[mb][nb], ah[mb], b0l, b1l);
                    }
                }
        }
        __syncthreads();
    }

    if (hasLo) {
#pragma unroll
        for (int mb = 0; mb < 4; mb++)
#pragma unroll
            for (int nb = 0; nb < 4; nb++) {
                float2 f01 = __half22float2(*(__half2*)&cacc[mb][nb][0]);
                float2 f23 = __half22float2(*(__half2*)&cacc[mb][nb][1]);
                acc[mb][nb][0] = fmaf(f01.x, INV_LO, acc[mb][nb][0]);
                acc[mb][nb][1] = fmaf(f01.y, INV_LO, acc[mb][nb][1]);
                acc[mb][nb][2] = fmaf(f23.x, INV_LO, acc[mb][nb][2]);
                acc[mb][nb][3] = fmaf(f23.y, INV_LO, acc[mb][nb][3]);
            }
    }

#pragma unroll
    for (int mb = 0; mb < 4; mb++) {
        int mrow = by * 128 + warp_m * 64 + mb * 16 + (lane >> 2);
#pragma unroll
        for (int nb = 0; nb < 4; nb++) {
            int ncol = bx * 128 + warp_n * 32 + nb * 8 + (lane & 3) * 2;
            float2 r0 = make_float2(acc[mb][nb][0], acc[mb][nb][1]);
            float2 r1 = make_float2(acc[mb][nb][2], acc[mb][nb][3]);

            if (qkvMode) {
                if (ncol < DMODEL) {
                    size_t i0 = (size_t)mrow * DMODEL + ncol;
                    size_t i1 = (size_t)(mrow + 8) * DMODEL + ncol;
                    *(float2*)(C + i0) = r0;
                    *(float2*)(C + i1) = r1;
                } else if (ncol < DMODEL + NKVH * HDIM) {
                    int cc = ncol - DMODEL;
                    size_t i0 = (size_t)mrow * (NKVH * HDIM) + cc;
                    size_t i1 = (size_t)(mrow + 8) * (NKVH * HDIM) + cc;
                    *(float2*)(kDest + i0) = r0;
                    *(float2*)(kDest + i1) = r1;
                } else {
                    int cc = ncol - DMODEL - NKVH * HDIM;
                    size_t i0 = (size_t)mrow * (NKVH * HDIM) + cc;
                    size_t i1 = (size_t)(mrow + 8) * (NKVH * HDIM) + cc;
                    uint32_t h0, l0, h1, l1;
                    split2h(r0.x, r0.y, h0, l0, 1.f);
                    split2h(r1.x, r1.y, h1, l1, 1.f);
                    *(uint32_t*)(vH + i0) = h0;
                    *(uint32_t*)(vL + i0) = l0;
                    *(uint32_t*)(vH + i1) = h1;
                    *(uint32_t*)(vL + i1) = l1;
                }
                continue;
            }

            size_t i0 = (size_t)mrow * N + ncol;
            size_t i1 = (size_t)(mrow + 8) * N + ncol;
            if (addend) {
                float2 a0 = *(const float2*)(addend + i0);
                float2 a1 = *(const float2*)(addend + i1);
                r0.x += a0.x; r0.y += a0.y;
                r1.x += a1.x; r1.y += a1.y;
            }
            if (gateMul) {
                float2 g0 = *(const float2*)(gateMul + i0);
                float2 g1 = *(const float2*)(gateMul + i1);
                r0.x *= g0.x / (1.f + __expf(-g0.x));
                r0.y *= g0.y / (1.f + __expf(-g0.y));
                r1.x *= g1.x / (1.f + __expf(-g1.x));
                r1.y *= g1.y / (1.f + __expf(-g1.y));
            }
            if (C) {
                *(float2*)(C + i0) = r0;
                *(float2*)(C + i1) = r1;
            }
            if (outH) {
                *(uint32_t*)(outH + i0) = packh(__float2half_rn(r0.x), __float2half_rn(r0.y));
                *(uint32_t*)(outH + i1) = packh(__float2half_rn(r1.x), __float2half_rn(r1.y));
            }
        }
    }
}

// ================= HMMA causal flash attention: Q fp16, K/V hi+lo, P hi =================
#define FA_STAGE_OFF 32768
#define FA_STAGE_BYTES 65536
#define FA_SMEM (FA_STAGE_OFF + 2 * FA_STAGE_BYTES)   // 160KB

__global__ __launch_bounds__(128, 1) void flash_attn_kernel(
    const __half* __restrict__ qh,
    const __half* __restrict__ kh, const __half* __restrict__ kl,
    const __half* __restrict__ vh, const __half* __restrict__ vl,
    __half* __restrict__ o)
{
    extern __shared__ char sm[];
    uint32_t sbase = smem_u32(sm);
    int qb = blockIdx.x, h = blockIdx.y, kvh = h >> 2;
    int tid = threadIdx.x, lane = tid & 31, w = tid >> 5;

#pragma unroll
    for (int i = 0; i < 8; i++) {
        int u = tid + i * 128;
        int row = u >> 4, c16 = u & 15;
        uint32_t dst = sbase + row * 256 + ((c16 ^ (row & 7)) << 4);
        cp_async16(dst, qh + (size_t)(qb * 64 + row) * DMODEL + h * HDIM + c16 * 8);
    }

    auto load_kv = [&](int stg, int kb) {
        uint32_t dst0 = sbase + FA_STAGE_OFF + stg * FA_STAGE_BYTES;
        const __half* srcs[4] = { kh, kl, vh, vl };
#pragma unroll
        for (int b = 0; b < 4; b++) {
            const __half* s = srcs[b];
#pragma unroll
            for (int i = 0; i < 8; i++) {
                int u = tid + i * 128;
                int row = u >> 4, c16 = u & 15;
                uint32_t dst = dst0 + b * 16384 + row * 256 + ((c16 ^ (row & 7)) << 4);
                cp_async16(dst, s + (size_t)(kb * 64 + row) * (NKVH * HDIM) + kvh * HDIM + c16 * 8);
            }
        }
    };

    load_kv(0, 0); CP_COMMIT();
    if (qb >= 1) load_kv(1, 1);
    CP_COMMIT();

    float O[16][4];
#pragma unroll
    for (int i = 0; i < 16; i++)
#pragma unroll
        for (int f = 0; f < 4; f++) O[i][f] = 0.f;
    float m_lo = -1e30f, m_hi = -1e30f, l_lo = 0.f, l_hi = 0.f;

    int r_loc = w * 16 + (lane >> 2);

    for (int kb = 0; kb <= qb; kb++) {
        CP_WAIT1();
        __syncthreads();
        uint32_t kbase = sbase + FA_STAGE_OFF + (kb & 1) * FA_STAGE_BYTES;

        float S[8][4];
#pragma unroll
        for (int i = 0; i < 8; i++)
#pragma unroll
            for (int f = 0; f < 4; f++) S[i][f] = 0.f;

#pragma unroll
        for (int kk = 0; kk < 8; kk++) {
            uint32_t aq[4];
            int ar = w * 16 + (lane & 15);
            int ac = kk * 2 + (lane >> 4);
            ldsm4(aq, sbase + ar * 256 + ((ac ^ (ar & 7)) << 4));
#pragma unroll
            for (int nblk = 0; nblk < 4; nblk++) {
                int br = nblk * 16 + (lane & 7) + ((lane >> 4) << 3);
                int bc = kk * 2 + ((lane >> 3) & 1);
                uint32_t boff = br * 256 + ((bc ^ (br & 7)) << 4);
                uint32_t bh4[4], bl4[4];
                ldsm4(bh4, kbase + boff);
                ldsm4(bl4, kbase + 16384 + boff);
                mmaF32(S[2*nblk],   aq, bh4[0], bh4[1]);
                mmaF32(S[2*nblk],   aq, bl4[0], bl4[1]);
                mmaF32(S[2*nblk+1], aq, bh4[2], bh4[3]);
                mmaF32(S[2*nblk+1], aq, bl4[2], bl4[3]);
            }
        }

        if (kb == qb) {
#pragma unroll
            for (int nt = 0; nt < 8; nt++) {
                int c = nt * 8 + (lane & 3) * 2;
                if (c     > r_loc)     S[nt][0] = -1e30f;
                if (c + 1 > r_loc)     S[nt][1] = -1e30f;
                if (c     > r_loc + 8) S[nt][2] = -1e30f;
                if (c + 1 > r_loc + 8) S[nt][3] = -1e30f;
            }
        }

        float rm_lo = -1e30f, rm_hi = -1e30f;
#pragma unroll
        for (int nt = 0; nt < 8; nt++) {
            rm_lo = fmaxf(rm_lo, fmaxf(S[nt][0], S[nt][1]));
            rm_hi = fmaxf(rm_hi, fmaxf(S[nt][2], S[nt][3]));
        }
        rm_lo = fmaxf(rm_lo, __shfl_xor_sync(0xffffffffu, rm_lo, 1));
        rm_lo = fmaxf(rm_lo, __shfl_xor_sync(0xffffffffu, rm_lo, 2));
        rm_hi = fmaxf(rm_hi, __shfl_xor_sync(0xffffffffu, rm_hi, 1));
        rm_hi = fmaxf(rm_hi, __shfl_xor_sync(0xffffffffu, rm_hi, 2));
        float mn_lo = fmaxf(m_lo, rm_lo), mn_hi = fmaxf(m_hi, rm_hi);
        float corr_lo = __expf(m_lo - mn_lo), corr_hi = __expf(m_hi - mn_hi);

        uint32_t ph[8][2];
        float sum_lo = 0.f, sum_hi = 0.f;
#pragma unroll
        for (int nt = 0; nt < 8; nt++) {
            float p0 = __expf(S[nt][0] - mn_lo);
            float p1 = __expf(S[nt][1] - mn_lo);
            float p2 = __expf(S[nt][2] - mn_hi);
            float p3 = __expf(S[nt][3] - mn_hi);
            sum_lo += p0 + p1; sum_hi += p2 + p3;
            ph[nt][0] = packh(__float2half_rn(p0), __float2half_rn(p1));
            ph[nt][1] = packh(__float2half_rn(p2), __float2half_rn(p3));
        }
        sum_lo += __shfl_xor_sync(0xffffffffu, sum_lo, 1);
        sum_lo += __shfl_xor_sync(0xffffffffu, sum_lo, 2);
        sum_hi += __shfl_xor_sync(0xffffffffu, sum_hi, 1);
        sum_hi += __shfl_xor_sync(0xffffffffu, sum_hi, 2);
        l_lo = l_lo * corr_lo + sum_lo;
        l_hi = l_hi * corr_hi + sum_hi;
        m_lo = mn_lo; m_hi = mn_hi;
#pragma unroll
        for (int ot = 0; ot < 16; ot++) {
            O[ot][0] *= corr_lo; O[ot][1] *= corr_lo;
            O[ot][2] *= corr_hi; O[ot][3] *= corr_hi;
        }

        uint32_t vbase = kbase + 32768;
#pragma unroll
        for (int kt = 0; kt < 4; kt++) {
            uint32_t aH[4] = { ph[2*kt][0], ph[2*kt][1], ph[2*kt+1][0], ph[2*kt+1][1] };
            int krow = kt * 16 + (lane & 7) + ((lane >> 3) & 1) * 8;
#pragma unroll
            for (int ob = 0; ob < 8; ob++) {
                int cu = ob * 2 + (lane >> 4);
                uint32_t off = krow * 256 + ((cu ^ (krow & 7)) << 4);
                uint32_t bvh[4], bvl[4];
                ldsm4t(bvh, vbase + off);
                ldsm4t(bvl, vbase + 16384 + off);
                mmaF32(O[2*ob],   aH, bvh[0], bvh[1]);
                mmaF32(O[2*ob],   aH, bvl[0], bvl[1]);
                mmaF32(O[2*ob+1], aH, bvh[2], bvh[3]);
                mmaF32(O[2*ob+1], aH, bvl[2], bvl[3]);
            }
        }

        __syncthreads();
        if (kb + 2 <= qb) load_kv(kb & 1, kb + 2);
        CP_COMMIT();
    }

    float il_lo = 1.f / l_lo, il_hi = 1.f / l_hi;
    int row0 = qb * 64 + r_loc;
#pragma unroll
    for (int ot = 0; ot < 16; ot++) {
        int col = h * HDIM + ot * 8 + (lane & 3) * 2;
        size_t i0 = (size_t)row0 * DMODEL + col;
        size_t i1 = (size_t)(row0 + 8) * DMODEL + col;
        *(uint32_t*)(o + i0) = packh(__float2half_rn(O[ot][0] * il_lo), __float2half_rn(O[ot][1] * il_lo));
        *(uint32_t*)(o + i1) = packh(__float2half_rn(O[ot][2] * il_hi), __float2half_rn(O[ot][3] * il_hi));
    }
}

// ================= host launcher =================
extern "C" void kernel_launch(void* const* d_in, const int* in_sizes, int n_in,
                              void* d_out, int out_size)
{
    const float* hidden = (const float*)d_in[0];
    const float* cosb  = (const float*)d_in[2];
    const float* sinb  = (const float*)d_in[3];
    const float* ln1   = (const float*)d_in[4];
    const float* wq    = (const float*)d_in[5];
    const float* wk    = (const float*)d_in[6];
    const float* wv    = (const float*)d_in[7];
    const float* wo    = (const float*)d_in[8];
    const float* ln2   = (const float*)d_in[9];
    const float* gatew = (const float*)d_in[10];
    const float* upw   = (const float*)d_in[11];
    const float* downw = (const float*)d_in[12];
    float* out = (float*)d_out;

    float *q, *k, *h, *gate;
    cudaGetSymbolAddress((void**)&q,    g_q);
    cudaGetSymbolAddress((void**)&k,    g_k);
    cudaGetSymbolAddress((void**)&h,    g_h);
    cudaGetSymbolAddress((void**)&gate, g_gate);

    __half *qkvTh,*qkvTl,*woTh,*woTl,*gwTh,*uwTh,*dwTh,*dwTl;
    cudaGetSymbolAddress((void**)&qkvTh, g_wqkvT_h); cudaGetSymbolAddress((void**)&qkvTl, g_wqkvT_l);
    cudaGetSymbolAddress((void**)&woTh, g_woT_h); cudaGetSymbolAddress((void**)&woTl, g_woT_l);
    cudaGetSymbolAddress((void**)&gwTh, g_gwT_h);
    cudaGetSymbolAddress((void**)&uwTh, g_uwT_h);
    cudaGetSymbolAddress((void**)&dwTh, g_dwT_h); cudaGetSymbolAddress((void**)&dwTl, g_dwT_l);

    __half *xn,*at,*x2,*ga,*qhp,*khp,*klp,*vhp,*vlp;
    cudaGetSymbolAddress((void**)&xn, g_xn);
    cudaGetSymbolAddress((void**)&at, g_at);
    cudaGetSymbolAddress((void**)&x2, g_x2);
    cudaGetSymbolAddress((void**)&ga, g_ga);
    cudaGetSymbolAddress((void**)&qhp, g_qh);
    cudaGetSymbolAddress((void**)&khp, g_kh); cudaGetSymbolAddress((void**)&klp, g_kl);
    cudaGetSymbolAddress((void**)&vhp, g_vh); cudaGetSymbolAddress((void**)&vlp, g_vl);

    cudaFuncSetAttribute(tc_gemm_kernel, cudaFuncAttributeMaxDynamicSharedMemorySize, TCG_SMEM);
    cudaFuncSetAttribute(flash_attn_kernel, cudaFuncAttributeMaxDynamicSharedMemorySize, FA_SMEM);

    // side stream + events: created once, OUTSIDE capture (first call is the correctness run)
    static cudaStream_t s2 = nullptr;
    static cudaEvent_t evFork = nullptr, evJoin = nullptr;
    if (!s2) {
        cudaStreamCreateWithFlags(&s2, cudaStreamNonBlocking);
        cudaEventCreateWithFlags(&evFork, cudaEventDisableTiming);
        cudaEventCreateWithFlags(&evJoin, cudaEventDisableTiming);
    }

    // ---- main stream: QKV weight prep (hi only) + rmsnorm ----
    rmsnorm_h_kernel<<<S_LEN, 256>>>(hidden, ln1, xn);
    transpose_split_kernel<<<dim3(DMODEL/64, DMODEL/64), 256>>>(wq, qkvTh, nullptr, DMODEL, DMODEL);
    transpose_split_kernel<<<dim3(NKVH*HDIM/64, DMODEL/64), 256>>>(wk, qkvTh + (size_t)DMODEL*DMODEL, nullptr, DMODEL, NKVH*HDIM);
    transpose_split_kernel<<<dim3(NKVH*HDIM/64, DMODEL/64), 256>>>(wv, qkvTh + (size_t)(DMODEL+NKVH*HDIM)*DMODEL, nullptr, DMODEL, NKVH*HDIM);

    // ---- fork: wo/gate/up/down transposes on side stream (gate/up hi-only) ----
    cudaEventRecord(evFork, 0);
    cudaStreamWaitEvent(s2, evFork, 0);
    transpose_split_kernel<<<dim3(DMODEL/64, DMODEL/64), 256, 0, s2>>>(wo, woTh, woTl, DMODEL, DMODEL);
    transpose_split_kernel<<<dim3(DFFN/64, DMODEL/64), 256, 0, s2>>>(gatew, gwTh, nullptr, DMODEL, DFFN);
    transpose_split_kernel<<<dim3(DFFN/64, DMODEL/64), 256, 0, s2>>>(upw, uwTh, nullptr, DMODEL, DFFN);
    transpose_split_kernel<<<dim3(DMODEL/64, DFFN/64), 256, 0, s2>>>(downw, dwTh, dwTl, DFFN, DMODEL);
    cudaEventRecord(evJoin, s2);

    // ---- main chain: QKV (1-term) -> rope -> attention ----
    tc_gemm_kernel<<<dim3(S_LEN/128, NQKV/128), 256, TCG_SMEM>>>(
        xn, qkvTh, nullptr, q, nullptr, nullptr, nullptr, k, vhp, vlp, 1, S_LEN, NQKV, DMODEL);

    const float qscale = 0.08838834764831845f;
    rope_l2_split_kernel<<<S_LEN * NHEADS / 8, 256>>>(q, qhp, nullptr, NHEADS, cosb, sinb, qscale);
    rope_l2_split_kernel<<<S_LEN * NKVH  / 8, 256>>>(k, khp, klp, NKVH,  cosb, sinb, 1.f);

    flash_attn_kernel<<<dim3(S_LEN / 64, NHEADS), 128, FA_SMEM>>>(qhp, khp, klp, vhp, vlp, at);

    // ---- join: weight prep must be done before wo GEMM ----
    cudaStreamWaitEvent(0, evJoin, 0);

    // wo: 2-term
    tc_gemm_kernel<<<dim3(S_LEN/128, DMODEL/128), 256, TCG_SMEM>>>(
        at, woTh, woTl, h, hidden, nullptr, nullptr, nullptr, nullptr, nullptr, 0, S_LEN, DMODEL, DMODEL);

    rmsnorm_h_kernel<<<S_LEN, 256>>>(h, ln2, x2);

    // gate/up: 1-term (weight hi only)
    tc_gemm_kernel<<<dim3(S_LEN/128, DFFN/128), 256, TCG_SMEM>>>(
        x2, gwTh, nullptr, gate, nullptr, nullptr, nullptr, nullptr, nullptr, nullptr, 0, S_LEN, DFFN, DMODEL);
    tc_gemm_kernel<<<dim3(S_LEN/128, DFFN/128), 256, TCG_SMEM>>>(
        x2, uwTh, nullptr, nullptr, nullptr, ga, gate, nullptr, nullptr, nullptr, 0, S_LEN, DFFN, DMODEL);

    // down: 2-term (accuracy anchor)
    tc_gemm_kernel<<<dim3(S_LEN/128, DMODEL/128), 256, TCG_SMEM>>>(
        ga, dwTh, dwTl, out, h, nullptr, nullptr, nullptr, nullptr, nullptr, 0, S_LEN, DMODEL, DFFN);
}

// round 13
// speedup vs baseline: 2.4192x; 1.5520x over previous
#include <cuda_runtime.h>
#include <cuda_fp16.h>
#include <math.h>
#include <stdint.h>

#define S_LEN  2048
#define DMODEL 4096
#define NHEADS 32
#define NKVH   8
#define HDIM   128
#define DFFN   16384

// ================= low-level helpers (base sm_103 ISA: ldmatrix/mma/cp.async) =================
__device__ __forceinline__ uint32_t smem_u32(const void* p) {
    uint32_t a;
    asm("{ .reg .u64 t; cvta.to.shared.u64 t, %1; cvt.u32.u64 %0, t; }" : "=r"(a) : "l"(p));
    return a;
}
__device__ __forceinline__ void cp_async16(uint32_t dst, const void* src) {
    asm volatile("cp.async.cg.shared.global [%0], [%1], 16;" :: "r"(dst), "l"(src));
}
#define CP_COMMIT() asm volatile("cp.async.commit_group;" ::: "memory")
#define CP_WAIT0()  asm volatile("cp.async.wait_group 0;" ::: "memory")
#define CP_WAIT1()  asm volatile("cp.async.wait_group 1;" ::: "memory")

__device__ __forceinline__ void ldsm4(uint32_t* r, uint32_t addr) {
    asm volatile("ldmatrix.sync.aligned.m8n8.x4.shared.b16 {%0,%1,%2,%3}, [%4];"
        : "=r"(r[0]), "=r"(r[1]), "=r"(r[2]), "=r"(r[3]) : "r"(addr));
}
__device__ __forceinline__ void ldsm4t(uint32_t* r, uint32_t addr) {
    asm volatile("ldmatrix.sync.aligned.m8n8.x4.trans.shared.b16 {%0,%1,%2,%3}, [%4];"
        : "=r"(r[0]), "=r"(r[1]), "=r"(r[2]), "=r"(r[3]) : "r"(addr));
}
__device__ __forceinline__ void mmaF32(float* d, const uint32_t* a, uint32_t b0, uint32_t b1) {
    asm volatile("mma.sync.aligned.m16n8k16.row.col.f32.f16.f16.f32 "
        "{%0,%1,%2,%3}, {%4,%5,%6,%7}, {%8,%9}, {%0,%1,%2,%3};"
        : "+f"(d[0]), "+f"(d[1]), "+f"(d[2]), "+f"(d[3])
        : "r"(a[0]), "r"(a[1]), "r"(a[2]), "r"(a[3]), "r"(b0), "r"(b1));
}

__device__ __forceinline__ uint32_t packh(__half a, __half b) {
    __half2 t = __halves2half2(a, b);
    return *(uint32_t*)&t;
}
__device__ __forceinline__ void split2h(float a, float b, uint32_t& hi, uint32_t& lo) {
    __half ha = __float2half_rn(a), hb = __float2half_rn(b);
    __half la = __float2half_rn(a - __half2float(ha));
    __half lb = __float2half_rn(b - __half2float(hb));
    hi = packh(ha, hb);
    lo = packh(la, lb);
}

// ================= scratch (device globals; no allocation allowed) =================
__device__ float g_q   [S_LEN * DMODEL];
__device__ float g_k   [S_LEN * NKVH * HDIM];
__device__ float g_h   [S_LEN * DMODEL];
__device__ float g_gate[S_LEN * DFFN];

#define NQKV (DMODEL + 2 * NKVH * HDIM)
__device__ __half g_wqkvT[NQKV * DMODEL];
__device__ __half g_woT[DMODEL * DMODEL];
__device__ __half g_gwT[DFFN * DMODEL];
__device__ __half g_uwT[DFFN * DMODEL];
__device__ __half g_dwT[DMODEL * DFFN];

// activations: single fp16 (GEMM A operands)
__device__ __half g_xn[S_LEN * DMODEL];
__device__ __half g_at[S_LEN * DMODEL];
__device__ __half g_x2[S_LEN * DMODEL];
__device__ __half g_ga[S_LEN * DFFN];

// attention operands: Q single fp16; K/V fp16 hi/lo
__device__ __half g_qh[S_LEN * DMODEL];
__device__ __half g_kh[S_LEN * NKVH * HDIM], g_kl[S_LEN * NKVH * HDIM];
__device__ __half g_vh[S_LEN * NKVH * HDIM], g_vl[S_LEN * NKVH * HDIM];

// ================= RMSNorm -> single fp16 =================
__global__ __launch_bounds__(256) void rmsnorm_h_kernel(
    const float* __restrict__ x, const float* __restrict__ w, __half* __restrict__ y)
{
    int row = blockIdx.x;
    const float* xr = x + (size_t)row * DMODEL;

    float4 vals[4];
    float ss = 0.f;
#pragma unroll
    for (int it = 0; it < 4; it++) {
        int idx = (threadIdx.x + it * 256) * 4;
        float4 v = *(const float4*)(xr + idx);
        vals[it] = v;
        ss += v.x*v.x + v.y*v.y + v.z*v.z + v.w*v.w;
    }
#pragma unroll
    for (int o = 16; o; o >>= 1) ss += __shfl_xor_sync(0xffffffffu, ss, o);

    __shared__ float red[8];
    if ((threadIdx.x & 31) == 0) red[threadIdx.x >> 5] = ss;
    __syncthreads();
    float tot = 0.f;
#pragma unroll
    for (int i = 0; i < 8; i++) tot += red[i];
    float inv = rsqrtf(tot * (1.f / DMODEL) + 1e-5f);

#pragma unroll
    for (int it = 0; it < 4; it++) {
        int idx = (threadIdx.x + it * 256) * 4;
        float4 v  = vals[it];
        float4 wv = *(const float4*)(w + idx);
        uint2 hv;
        hv.x = packh(__float2half_rn(v.x * inv * wv.x), __float2half_rn(v.y * inv * wv.y));
        hv.y = packh(__float2half_rn(v.z * inv * wv.z), __float2half_rn(v.w * inv * wv.w));
        *(uint2*)(y + (size_t)row * DMODEL + idx) = hv;
    }
}

// ================= RoPE + L2-norm -> fp16 (hi only if outl==nullptr) =================
__global__ __launch_bounds__(256) void rope_l2_split_kernel(
    const float* __restrict__ in, __half* __restrict__ outh, __half* __restrict__ outl,
    int nheads, const float* __restrict__ cosb, const float* __restrict__ sinb, float scale)
{
    int wid  = (blockIdx.x * 256 + threadIdx.x) >> 5;
    int lane = threadIdx.x & 31;
    int s  = wid / nheads;
    int hh = wid % nheads;
    size_t base = (size_t)s * nheads * HDIM + hh * HDIM + lane * 4;
    float4 vv = *(const float4*)(in + base);

    float c0 = cosb[s * 64 + lane * 2],     s0 = sinb[s * 64 + lane * 2];
    float c1 = cosb[s * 64 + lane * 2 + 1], s1 = sinb[s * 64 + lane * 2 + 1];
    float o0 = vv.x * c0 - vv.y * s0;
    float o1 = vv.x * s0 + vv.y * c0;
    float o2 = vv.z * c1 - vv.w * s1;
    float o3 = vv.z * s1 + vv.w * c1;

    float ss = o0*o0 + o1*o1 + o2*o2 + o3*o3;
#pragma unroll
    for (int o = 16; o; o >>= 1) ss += __shfl_xor_sync(0xffffffffu, ss, o);
    float rr = rsqrtf(ss * (1.f / HDIM) + 1e-5f) * scale;
    o0 *= rr; o1 *= rr; o2 *= rr; o3 *= rr;

    uint2 hv, lv;
    split2h(o0, o1, hv.x, lv.x);
    split2h(o2, o3, hv.y, lv.y);
    *(uint2*)(outh + base) = hv;
    if (outl) *(uint2*)(outl + base) = lv;
}

// ================= transpose to fp16: in[K,N] fp32 -> [N,K] fp16 =================
__global__ __launch_bounds__(256) void transpose_h_kernel(
    const float* __restrict__ in, __half* __restrict__ hi, int K, int N)
{
    __shared__ float s[64][65];
    int r0 = blockIdx.y * 64, c0 = blockIdx.x * 64;
#pragma unroll
    for (int i = 0; i < 8; i++) {
        int idx = threadIdx.x + i * 256;
        int lr = idx >> 5, p = idx & 31;
        float2 v = *(const float2*)(in + (size_t)(r0 + lr) * N + c0 + 2 * p);
        s[lr][2 * p]     = v.x;
        s[lr][2 * p + 1] = v.y;
    }
    __syncthreads();
#pragma unroll
    for (int i = 0; i < 8; i++) {
        int idx = threadIdx.x + i * 256;
        int lr = idx >> 5, p = idx & 31;
        uint32_t hv = packh(__float2half_rn(s[2 * p][lr]), __float2half_rn(s[2 * p + 1][lr]));
        *(uint32_t*)(hi + (size_t)(c0 + lr) * K + (r0 + 2 * p)) = hv;
    }
}

// ================= HMMA GEMM: C = A(fp16) x B(fp16)^T, fp32 acc =================
// CTA 128x128, K-chunk 128, 3-stage ring (3 x 64KB). 8 warps @ 64x32.
#define TCG_STAGE_BYTES 65536
#define TCG_NSTAGE 3
#define TCG_SMEM (TCG_NSTAGE * TCG_STAGE_BYTES)

__global__ __launch_bounds__(256, 1) void tc_gemm_kernel(
    const __half* __restrict__ A, const __half* __restrict__ B,
    float* __restrict__ C, const float* __restrict__ addend,
    __half* __restrict__ outH,
    const float* __restrict__ gateMul,
    float* __restrict__ kDest, __half* __restrict__ vH, __half* __restrict__ vL, int qkvMode,
    int M, int N, int K)
{
    extern __shared__ char sm[];
    uint32_t sbase = smem_u32(sm);
    int tid = threadIdx.x, lane = tid & 31, wid = tid >> 5;
    int warp_m = wid & 1, warp_n = wid >> 1;
    int by = blockIdx.x, bx = blockIdx.y;   // M-block fastest

    const __half* srcs[2] = {
        A + (size_t)(by * 128) * K,
        B + (size_t)(bx * 128) * K };

    int nchunk = K >> 7;

    auto load_stage = [&](int stg, int c) {
        uint32_t dst0 = sbase + stg * TCG_STAGE_BYTES;
        int kc = c << 7;
#pragma unroll
        for (int i = 0; i < 16; i++) {
            int u = i * 256 + tid;
            int tile = u >> 11, w = u & 2047;      // 2048 16B-units per 32KB tile
            int row = w >> 4, c16 = w & 15;        // 128 rows x 256B
            uint32_t dst = dst0 + tile * 32768 + row * 256 + ((c16 ^ (row & 7)) << 4);
            cp_async16(dst, srcs[tile] + (size_t)row * K + kc + c16 * 8);
        }
    };

    load_stage(0, 0); CP_COMMIT();
    if (nchunk > 1) load_stage(1, 1);
    CP_COMMIT();

    float acc[4][4][4];
#pragma unroll
    for (int a = 0; a < 4; a++)
#pragma unroll
        for (int b = 0; b < 4; b++)
#pragma unroll
            for (int f = 0; f < 4; f++) acc[a][b][f] = 0.f;

    int a_r   = warp_m * 64 + (lane & 15);
    int a_kh  = lane >> 4;
    int b_r   = warp_n * 32 + (lane & 7) + ((lane >> 4) << 3);
    int b_kh  = (lane >> 3) & 1;

    for (int c = 0; c < nchunk; c++) {
        CP_WAIT1();
        __syncthreads();
        if (c + 2 < nchunk) load_stage((c + 2) % TCG_NSTAGE, c + 2);
        CP_COMMIT();

        uint32_t st = sbase + (c % TCG_NSTAGE) * TCG_STAGE_BYTES;
#pragma unroll
        for (int kk = 0; kk < 8; kk++) {
            int c16 = kk * 2;
            uint32_t ah[4][4], bh[2][4];
#pragma unroll
            for (int mb = 0; mb < 4; mb++) {
                int r = a_r + mb * 16;
                uint32_t off = r * 256 + (((c16 + a_kh) ^ (r & 7)) << 4);
                ldsm4(ah[mb], st + off);
            }
#pragma unroll
            for (int nb = 0; nb < 2; nb++) {
                int r = b_r + nb * 16;
                uint32_t off = r * 256 + (((c16 + b_kh) ^ (r & 7)) << 4);
                ldsm4(bh[nb], st + 32768 + off);
            }
#pragma unroll
            for (int mb = 0; mb < 4; mb++)
#pragma unroll
                for (int nb = 0; nb < 4; nb++) {
                    uint32_t b0 = bh[nb >> 1][(nb & 1) * 2], b1 = bh[nb >> 1][(nb & 1) * 2 + 1];
                    mmaF32(acc[mb][nb], ah[mb], b0, b1);
                }
        }
        __syncthreads();
    }

#pragma unroll
    for (int mb = 0; mb < 4; mb++) {
        int mrow = by * 128 + warp_m * 64 + mb * 16 + (lane >> 2);
#pragma unroll
        for (int nb = 0; nb < 4; nb++) {
            int ncol = bx * 128 + warp_n * 32 + nb * 8 + (lane & 3) * 2;
            float2 r0 = make_float2(acc[mb][nb][0], acc[mb][nb][1]);
            float2 r1 = make_float2(acc[mb][nb][2], acc[mb][nb][3]);

            if (qkvMode) {
                if (ncol < DMODEL) {
                    size_t i0 = (size_t)mrow * DMODEL + ncol;
                    size_t i1 = (size_t)(mrow + 8) * DMODEL + ncol;
                    *(float2*)(C + i0) = r0;
                    *(float2*)(C + i1) = r1;
                } else if (ncol < DMODEL + NKVH * HDIM) {
                    int cc = ncol - DMODEL;
                    size_t i0 = (size_t)mrow * (NKVH * HDIM) + cc;
                    size_t i1 = (size_t)(mrow + 8) * (NKVH * HDIM) + cc;
                    *(float2*)(kDest + i0) = r0;
                    *(float2*)(kDest + i1) = r1;
                } else {
                    int cc = ncol - DMODEL - NKVH * HDIM;
                    size_t i0 = (size_t)mrow * (NKVH * HDIM) + cc;
                    size_t i1 = (size_t)(mrow + 8) * (NKVH * HDIM) + cc;
                    uint32_t h0, l0, h1, l1;
                    split2h(r0.x, r0.y, h0, l0);
                    split2h(r1.x, r1.y, h1, l1);
                    *(uint32_t*)(vH + i0) = h0;
                    *(uint32_t*)(vL + i0) = l0;
                    *(uint32_t*)(vH + i1) = h1;
                    *(uint32_t*)(vL + i1) = l1;
                }
                continue;
            }

            size_t i0 = (size_t)mrow * N + ncol;
            size_t i1 = (size_t)(mrow + 8) * N + ncol;
            if (addend) {
                float2 a0 = *(const float2*)(addend + i0);
                float2 a1 = *(const float2*)(addend + i1);
                r0.x += a0.x; r0.y += a0.y;
                r1.x += a1.x; r1.y += a1.y;
            }
            if (gateMul) {
                float2 g0 = *(const float2*)(gateMul + i0);
                float2 g1 = *(const float2*)(gateMul + i1);
                r0.x *= g0.x / (1.f + __expf(-g0.x));
                r0.y *= g0.y / (1.f + __expf(-g0.y));
                r1.x *= g1.x / (1.f + __expf(-g1.x));
                r1.y *= g1.y / (1.f + __expf(-g1.y));
            }
            if (C) {
                *(float2*)(C + i0) = r0;
                *(float2*)(C + i1) = r1;
            }
            if (outH) {
                *(uint32_t*)(outH + i0) = packh(__float2half_rn(r0.x), __float2half_rn(r0.y));
                *(uint32_t*)(outH + i1) = packh(__float2half_rn(r1.x), __float2half_rn(r1.y));
            }
        }
    }
}

// ================= HMMA causal flash attention: Q fp16, K/V hi+lo, P hi =================
#define FA_STAGE_OFF 32768
#define FA_STAGE_BYTES 65536
#define FA_SMEM (FA_STAGE_OFF + 2 * FA_STAGE_BYTES)   // 160KB

__global__ __launch_bounds__(128, 1) void flash_attn_kernel(
    const __half* __restrict__ qh,
    const __half* __restrict__ kh, const __half* __restrict__ kl,
    const __half* __restrict__ vh, const __half* __restrict__ vl,
    __half* __restrict__ o)
{
    extern __shared__ char sm[];
    uint32_t sbase = smem_u32(sm);
    int qb = blockIdx.x, h = blockIdx.y, kvh = h >> 2;
    int tid = threadIdx.x, lane = tid & 31, w = tid >> 5;

#pragma unroll
    for (int i = 0; i < 8; i++) {
        int u = tid + i * 128;
        int row = u >> 4, c16 = u & 15;
        uint32_t dst = sbase + row * 256 + ((c16 ^ (row & 7)) << 4);
        cp_async16(dst, qh + (size_t)(qb * 64 + row) * DMODEL + h * HDIM + c16 * 8);
    }

    auto load_kv = [&](int stg, int kb) {
        uint32_t dst0 = sbase + FA_STAGE_OFF + stg * FA_STAGE_BYTES;
        const __half* srcs[4] = { kh, kl, vh, vl };
#pragma unroll
        for (int b = 0; b < 4; b++) {
            const __half* s = srcs[b];
#pragma unroll
            for (int i = 0; i < 8; i++) {
                int u = tid + i * 128;
                int row = u >> 4, c16 = u & 15;
                uint32_t dst = dst0 + b * 16384 + row * 256 + ((c16 ^ (row & 7)) << 4);
                cp_async16(dst, s + (size_t)(kb * 64 + row) * (NKVH * HDIM) + kvh * HDIM + c16 * 8);
            }
        }
    };

    load_kv(0, 0); CP_COMMIT();
    if (qb >= 1) load_kv(1, 1);
    CP_COMMIT();

    float O[16][4];
#pragma unroll
    for (int i = 0; i < 16; i++)
#pragma unroll
        for (int f = 0; f < 4; f++) O[i][f] = 0.f;
    float m_lo = -1e30f, m_hi = -1e30f, l_lo = 0.f, l_hi = 0.f;

    int r_loc = w * 16 + (lane >> 2);

    for (int kb = 0; kb <= qb; kb++) {
        CP_WAIT1();
        __syncthreads();
        uint32_t kbase = sbase + FA_STAGE_OFF + (kb & 1) * FA_STAGE_BYTES;

        float S[8][4];
#pragma unroll
        for (int i = 0; i < 8; i++)
#pragma unroll
            for (int f = 0; f < 4; f++) S[i][f] = 0.f;

#pragma unroll
        for (int kk = 0; kk < 8; kk++) {
            uint32_t aq[4];
            int ar = w * 16 + (lane & 15);
            int ac = kk * 2 + (lane >> 4);
            ldsm4(aq, sbase + ar * 256 + ((ac ^ (ar & 7)) << 4));
#pragma unroll
            for (int nblk = 0; nblk < 4; nblk++) {
                int br = nblk * 16 + (lane & 7) + ((lane >> 4) << 3);
                int bc = kk * 2 + ((lane >> 3) & 1);
                uint32_t boff = br * 256 + ((bc ^ (br & 7)) << 4);
                uint32_t bh4[4], bl4[4];
                ldsm4(bh4, kbase + boff);
                ldsm4(bl4, kbase + 16384 + boff);
                mmaF32(S[2*nblk],   aq, bh4[0], bh4[1]);
                mmaF32(S[2*nblk],   aq, bl4[0], bl4[1]);
                mmaF32(S[2*nblk+1], aq, bh4[2], bh4[3]);
                mmaF32(S[2*nblk+1], aq, bl4[2], bl4[3]);
            }
        }

        if (kb == qb) {
#pragma unroll
            for (int nt = 0; nt < 8; nt++) {
                int c = nt * 8 + (lane & 3) * 2;
                if (c     > r_loc)     S[nt][0] = -1e30f;
                if (c + 1 > r_loc)     S[nt][1] = -1e30f;
                if (c     > r_loc + 8) S[nt][2] = -1e30f;
                if (c + 1 > r_loc + 8) S[nt][3] = -1e30f;
            }
        }

        float rm_lo = -1e30f, rm_hi = -1e30f;
#pragma unroll
        for (int nt = 0; nt < 8; nt++) {
            rm_lo = fmaxf(rm_lo, fmaxf(S[nt][0], S[nt][1]));
            rm_hi = fmaxf(rm_hi, fmaxf(S[nt][2], S[nt][3]));
        }
        rm_lo = fmaxf(rm_lo, __shfl_xor_sync(0xffffffffu, rm_lo, 1));
        rm_lo = fmaxf(rm_lo, __shfl_xor_sync(0xffffffffu, rm_lo, 2));
        rm_hi = fmaxf(rm_hi, __shfl_xor_sync(0xffffffffu, rm_hi, 1));
        rm_hi = fmaxf(rm_hi, __shfl_xor_sync(0xffffffffu, rm_hi, 2));
        float mn_lo = fmaxf(m_lo, rm_lo), mn_hi = fmaxf(m_hi, rm_hi);
        float corr_lo = __expf(m_lo - mn_lo), corr_hi = __expf(m_hi - mn_hi);

        uint32_t ph[8][2];
        float sum_lo = 0.f, sum_hi = 0.f;
#pragma unroll
        for (int nt = 0; nt < 8; nt++) {
            float p0 = __expf(S[nt][0] - mn_lo);
            float p1 = __expf(S[nt][1] - mn_lo);
            float p2 = __expf(S[nt][2] - mn_hi);
            float p3 = __expf(S[nt][3] - mn_hi);
            sum_lo += p0 + p1; sum_hi += p2 + p3;
            ph[nt][0] = packh(__float2half_rn(p0), __float2half_rn(p1));
            ph[nt][1] = packh(__float2half_rn(p2), __float2half_rn(p3));
        }
        sum_lo += __shfl_xor_sync(0xffffffffu, sum_lo, 1);
        sum_lo += __shfl_xor_sync(0xffffffffu, sum_lo, 2);
        sum_hi += __shfl_xor_sync(0xffffffffu, sum_hi, 1);
        sum_hi += __shfl_xor_sync(0xffffffffu, sum_hi, 2);
        l_lo = l_lo * corr_lo + sum_lo;
        l_hi = l_hi * corr_hi + sum_hi;
        m_lo = mn_lo; m_hi = mn_hi;
#pragma unroll
        for (int ot = 0; ot < 16; ot++) {
            O[ot][0] *= corr_lo; O[ot][1] *= corr_lo;
            O[ot][2] *= corr_hi; O[ot][3] *= corr_hi;
        }

        uint32_t vbase = kbase + 32768;
#pragma unroll
        for (int kt = 0; kt < 4; kt++) {
            uint32_t aH[4] = { ph[2*kt][0], ph[2*kt][1], ph[2*kt+1][0], ph[2*kt+1][1] };
            int krow = kt * 16 + (lane & 7) + ((lane >> 3) & 1) * 8;
#pragma unroll
            for (int ob = 0; ob < 8; ob++) {
                int cu = ob * 2 + (lane >> 4);
                uint32_t off = krow * 256 + ((cu ^ (krow & 7)) << 4);
                uint32_t bvh[4], bvl[4];
                ldsm4t(bvh, vbase + off);
                ldsm4t(bvl, vbase + 16384 + off);
                mmaF32(O[2*ob],   aH, bvh[0], bvh[1]);
                mmaF32(O[2*ob],   aH, bvl[0], bvl[1]);
                mmaF32(O[2*ob+1], aH, bvh[2], bvh[3]);
                mmaF32(O[2*ob+1], aH, bvl[2], bvl[3]);
            }
        }

        __syncthreads();
        if (kb + 2 <= qb) load_kv(kb & 1, kb + 2);
        CP_COMMIT();
    }

    float il_lo = 1.f / l_lo, il_hi = 1.f / l_hi;
    int row0 = qb * 64 + r_loc;
#pragma unroll
    for (int ot = 0; ot < 16; ot++) {
        int col = h * HDIM + ot * 8 + (lane & 3) * 2;
        size_t i0 = (size_t)row0 * DMODEL + col;
        size_t i1 = (size_t)(row0 + 8) * DMODEL + col;
        *(uint32_t*)(o + i0) = packh(__float2half_rn(O[ot][0] * il_lo), __float2half_rn(O[ot][1] * il_lo));
        *(uint32_t*)(o + i1) = packh(__float2half_rn(O[ot][2] * il_hi), __float2half_rn(O[ot][3] * il_hi));
    }
}

// ================= host launcher =================
extern "C" void kernel_launch(void* const* d_in, const int* in_sizes, int n_in,
                              void* d_out, int out_size)
{
    const float* hidden = (const float*)d_in[0];
    const float* cosb  = (const float*)d_in[2];
    const float* sinb  = (const float*)d_in[3];
    const float* ln1   = (const float*)d_in[4];
    const float* wq    = (const float*)d_in[5];
    const float* wk    = (const float*)d_in[6];
    const float* wv    = (const float*)d_in[7];
    const float* wo    = (const float*)d_in[8];
    const float* ln2   = (const float*)d_in[9];
    const float* gatew = (const float*)d_in[10];
    const float* upw   = (const float*)d_in[11];
    const float* downw = (const float*)d_in[12];
    float* out = (float*)d_out;

    float *q, *k, *h, *gate;
    cudaGetSymbolAddress((void**)&q,    g_q);
    cudaGetSymbolAddress((void**)&k,    g_k);
    cudaGetSymbolAddress((void**)&h,    g_h);
    cudaGetSymbolAddress((void**)&gate, g_gate);

    __half *qkvT,*woT,*gwT,*uwT,*dwT;
    cudaGetSymbolAddress((void**)&qkvT, g_wqkvT);
    cudaGetSymbolAddress((void**)&woT, g_woT);
    cudaGetSymbolAddress((void**)&gwT, g_gwT);
    cudaGetSymbolAddress((void**)&uwT, g_uwT);
    cudaGetSymbolAddress((void**)&dwT, g_dwT);

    __half *xn,*at,*x2,*ga,*qhp,*khp,*klp,*vhp,*vlp;
    cudaGetSymbolAddress((void**)&xn, g_xn);
    cudaGetSymbolAddress((void**)&at, g_at);
    cudaGetSymbolAddress((void**)&x2, g_x2);
    cudaGetSymbolAddress((void**)&ga, g_ga);
    cudaGetSymbolAddress((void**)&qhp, g_qh);
    cudaGetSymbolAddress((void**)&khp, g_kh); cudaGetSymbolAddress((void**)&klp, g_kl);
    cudaGetSymbolAddress((void**)&vhp, g_vh); cudaGetSymbolAddress((void**)&vlp, g_vl);

    cudaFuncSetAttribute(tc_gemm_kernel, cudaFuncAttributeMaxDynamicSharedMemorySize, TCG_SMEM);
    cudaFuncSetAttribute(flash_attn_kernel, cudaFuncAttributeMaxDynamicSharedMemorySize, FA_SMEM);

    // side stream + events: created once, OUTSIDE capture
    static cudaStream_t s2 = nullptr;
    static cudaEvent_t evFork = nullptr, evJoin = nullptr;
    if (!s2) {
        cudaStreamCreateWithFlags(&s2, cudaStreamNonBlocking);
        cudaEventCreateWithFlags(&evFork, cudaEventDisableTiming);
        cudaEventCreateWithFlags(&evJoin, cudaEventDisableTiming);
    }

    // ---- main stream: QKV weight prep + rmsnorm ----
    rmsnorm_h_kernel<<<S_LEN, 256>>>(hidden, ln1, xn);
    transpose_h_kernel<<<dim3(DMODEL/64, DMODEL/64), 256>>>(wq, qkvT, DMODEL, DMODEL);
    transpose_h_kernel<<<dim3(NKVH*HDIM/64, DMODEL/64), 256>>>(wk, qkvT + (size_t)DMODEL*DMODEL, DMODEL, NKVH*HDIM);
    transpose_h_kernel<<<dim3(NKVH*HDIM/64, DMODEL/64), 256>>>(wv, qkvT + (size_t)(DMODEL+NKVH*HDIM)*DMODEL, DMODEL, NKVH*HDIM);

    // ---- fork: wo/gate/up/down transposes on side stream ----
    cudaEventRecord(evFork, 0);
    cudaStreamWaitEvent(s2, evFork, 0);
    transpose_h_kernel<<<dim3(DMODEL/64, DMODEL/64), 256, 0, s2>>>(wo, woT, DMODEL, DMODEL);
    transpose_h_kernel<<<dim3(DFFN/64, DMODEL/64), 256, 0, s2>>>(gatew, gwT, DMODEL, DFFN);
    transpose_h_kernel<<<dim3(DFFN/64, DMODEL/64), 256, 0, s2>>>(upw, uwT, DMODEL, DFFN);
    transpose_h_kernel<<<dim3(DMODEL/64, DFFN/64), 256, 0, s2>>>(downw, dwT, DFFN, DMODEL);
    cudaEventRecord(evJoin, s2);

    // ---- main chain: QKV -> rope -> attention ----
    tc_gemm_kernel<<<dim3(S_LEN/128, NQKV/128), 256, TCG_SMEM>>>(
        xn, qkvT, q, nullptr, nullptr, nullptr, k, vhp, vlp, 1, S_LEN, NQKV, DMODEL);

    const float qscale = 0.08838834764831845f;
    rope_l2_split_kernel<<<S_LEN * NHEADS / 8, 256>>>(q, qhp, nullptr, NHEADS, cosb, sinb, qscale);
    rope_l2_split_kernel<<<S_LEN * NKVH  / 8, 256>>>(k, khp, klp, NKVH,  cosb, sinb, 1.f);

    flash_attn_kernel<<<dim3(S_LEN / 64, NHEADS), 128, FA_SMEM>>>(qhp, khp, klp, vhp, vlp, at);

    // ---- join: weight prep must be done before wo GEMM ----
    cudaStreamWaitEvent(0, evJoin, 0);

    tc_gemm_kernel<<<dim3(S_LEN/128, DMODEL/128), 256, TCG_SMEM>>>(
        at, woT, h, hidden, nullptr, nullptr, nullptr, nullptr, nullptr, 0, S_LEN, DMODEL, DMODEL);

    rmsnorm_h_kernel<<<S_LEN, 256>>>(h, ln2, x2);

    tc_gemm_kernel<<<dim3(S_LEN/128, DFFN/128), 256, TCG_SMEM>>>(
        x2, gwT, gate, nullptr, nullptr, nullptr, nullptr, nullptr, nullptr, 0, S_LEN, DFFN, DMODEL);
    tc_gemm_kernel<<<dim3(S_LEN/128, DFFN/128), 256, TCG_SMEM>>>(
        x2, uwT, nullptr, nullptr, ga, gate, nullptr, nullptr, nullptr, 0, S_LEN, DFFN, DMODEL);

    tc_gemm_kernel<<<dim3(S_LEN/128, DMODEL/128), 256, TCG_SMEM>>>(
        ga, dwT, out, h, nullptr, nullptr, nullptr, nullptr, nullptr, 0, S_LEN, DMODEL, DFFN);
}

// round 14
// speedup vs baseline: 2.5114x; 1.0381x over previous
#include <cuda_runtime.h>
#include <cuda_fp16.h>
#include <math.h>
#include <stdint.h>

#define S_LEN  2048
#define DMODEL 4096
#define NHEADS 32
#define NKVH   8
#define HDIM   128
#define DFFN   16384

// ================= low-level helpers =================
__device__ __forceinline__ uint32_t smem_u32(const void* p) {
    uint32_t a;
    asm("{ .reg .u64 t; cvta.to.shared.u64 t, %1; cvt.u32.u64 %0, t; }" : "=r"(a) : "l"(p));
    return a;
}
__device__ __forceinline__ void cp_async16(uint32_t dst, const void* src) {
    asm volatile("cp.async.cg.shared.global [%0], [%1], 16;" :: "r"(dst), "l"(src));
}
#define CP_COMMIT() asm volatile("cp.async.commit_group;" ::: "memory")
#define CP_WAIT0()  asm volatile("cp.async.wait_group 0;" ::: "memory")
#define CP_WAIT1()  asm volatile("cp.async.wait_group 1;" ::: "memory")

__device__ __forceinline__ void ldsm4(uint32_t* r, uint32_t addr) {
    asm volatile("ldmatrix.sync.aligned.m8n8.x4.shared.b16 {%0,%1,%2,%3}, [%4];"
        : "=r"(r[0]), "=r"(r[1]), "=r"(r[2]), "=r"(r[3]) : "r"(addr));
}
__device__ __forceinline__ void ldsm4t(uint32_t* r, uint32_t addr) {
    asm volatile("ldmatrix.sync.aligned.m8n8.x4.trans.shared.b16 {%0,%1,%2,%3}, [%4];"
        : "=r"(r[0]), "=r"(r[1]), "=r"(r[2]), "=r"(r[3]) : "r"(addr));
}
__device__ __forceinline__ void mmaF32(float* d, const uint32_t* a, uint32_t b0, uint32_t b1) {
    asm volatile("mma.sync.aligned.m16n8k16.row.col.f32.f16.f16.f32 "
        "{%0,%1,%2,%3}, {%4,%5,%6,%7}, {%8,%9}, {%0,%1,%2,%3};"
        : "+f"(d[0]), "+f"(d[1]), "+f"(d[2]), "+f"(d[3])
        : "r"(a[0]), "r"(a[1]), "r"(a[2]), "r"(a[3]), "r"(b0), "r"(b1));
}

__device__ __forceinline__ uint32_t packh(__half a, __half b) {
    __half2 t = __halves2half2(a, b);
    return *(uint32_t*)&t;
}

// ================= scratch =================
__device__ float g_q [S_LEN * DMODEL];
__device__ float g_k [S_LEN * NKVH * HDIM];
__device__ float g_h [S_LEN * DMODEL];

#define NQKV (DMODEL + 2 * NKVH * HDIM)
__device__ __half g_wqkvT[NQKV * DMODEL];
__device__ __half g_woT[DMODEL * DMODEL];
__device__ __half g_gwT[DFFN * DMODEL];
__device__ __half g_uwT[DFFN * DMODEL];
__device__ __half g_dwT[DMODEL * DFFN];

__device__ __half g_xn[S_LEN * DMODEL];
__device__ __half g_at[S_LEN * DMODEL];
__device__ __half g_x2[S_LEN * DMODEL];
__device__ __half g_ga[S_LEN * DFFN];
__device__ __half g_gate[S_LEN * DFFN];

// attention operands: all single fp16
__device__ __half g_qh[S_LEN * DMODEL];
__device__ __half g_kh[S_LEN * NKVH * HDIM];
__device__ __half g_vh[S_LEN * NKVH * HDIM];

// ================= RMSNorm -> single fp16 =================
__global__ __launch_bounds__(256) void rmsnorm_h_kernel(
    const float* __restrict__ x, const float* __restrict__ w, __half* __restrict__ y)
{
    int row = blockIdx.x;
    const float* xr = x + (size_t)row * DMODEL;

    float4 vals[4];
    float ss = 0.f;
#pragma unroll
    for (int it = 0; it < 4; it++) {
        int idx = (threadIdx.x + it * 256) * 4;
        float4 v = *(const float4*)(xr + idx);
        vals[it] = v;
        ss += v.x*v.x + v.y*v.y + v.z*v.z + v.w*v.w;
    }
#pragma unroll
    for (int o = 16; o; o >>= 1) ss += __shfl_xor_sync(0xffffffffu, ss, o);

    __shared__ float red[8];
    if ((threadIdx.x & 31) == 0) red[threadIdx.x >> 5] = ss;
    __syncthreads();
    float tot = 0.f;
#pragma unroll
    for (int i = 0; i < 8; i++) tot += red[i];
    float inv = rsqrtf(tot * (1.f / DMODEL) + 1e-5f);

#pragma unroll
    for (int it = 0; it < 4; it++) {
        int idx = (threadIdx.x + it * 256) * 4;
        float4 v  = vals[it];
        float4 wv = *(const float4*)(w + idx);
        uint2 hv;
        hv.x = packh(__float2half_rn(v.x * inv * wv.x), __float2half_rn(v.y * inv * wv.y));
        hv.y = packh(__float2half_rn(v.z * inv * wv.z), __float2half_rn(v.w * inv * wv.w));
        *(uint2*)(y + (size_t)row * DMODEL + idx) = hv;
    }
}

// ================= RoPE + L2-norm -> single fp16 =================
__global__ __launch_bounds__(256) void rope_l2_h_kernel(
    const float* __restrict__ in, __half* __restrict__ outh,
    int nheads, const float* __restrict__ cosb, const float* __restrict__ sinb, float scale)
{
    int wid  = (blockIdx.x * 256 + threadIdx.x) >> 5;
    int lane = threadIdx.x & 31;
    int s  = wid / nheads;
    int hh = wid % nheads;
    size_t base = (size_t)s * nheads * HDIM + hh * HDIM + lane * 4;
    float4 vv = *(const float4*)(in + base);

    float c0 = cosb[s * 64 + lane * 2],     s0 = sinb[s * 64 + lane * 2];
    float c1 = cosb[s * 64 + lane * 2 + 1], s1 = sinb[s * 64 + lane * 2 + 1];
    float o0 = vv.x * c0 - vv.y * s0;
    float o1 = vv.x * s0 + vv.y * c0;
    float o2 = vv.z * c1 - vv.w * s1;
    float o3 = vv.z * s1 + vv.w * c1;

    float ss = o0*o0 + o1*o1 + o2*o2 + o3*o3;
#pragma unroll
    for (int o = 16; o; o >>= 1) ss += __shfl_xor_sync(0xffffffffu, ss, o);
    float rr = rsqrtf(ss * (1.f / HDIM) + 1e-5f) * scale;
    o0 *= rr; o1 *= rr; o2 *= rr; o3 *= rr;

    uint2 hv;
    hv.x = packh(__float2half_rn(o0), __float2half_rn(o1));
    hv.y = packh(__float2half_rn(o2), __float2half_rn(o3));
    *(uint2*)(outh + base) = hv;
}

// ================= transpose to fp16: in[K,N] fp32 -> [N,K] fp16 =================
__global__ __launch_bounds__(256) void transpose_h_kernel(
    const float* __restrict__ in, __half* __restrict__ hi, int K, int N)
{
    __shared__ float s[64][65];
    int r0 = blockIdx.y * 64, c0 = blockIdx.x * 64;
#pragma unroll
    for (int i = 0; i < 8; i++) {
        int idx = threadIdx.x + i * 256;
        int lr = idx >> 5, p = idx & 31;
        float2 v = *(const float2*)(in + (size_t)(r0 + lr) * N + c0 + 2 * p);
        s[lr][2 * p]     = v.x;
        s[lr][2 * p + 1] = v.y;
    }
    __syncthreads();
#pragma unroll
    for (int i = 0; i < 8; i++) {
        int idx = threadIdx.x + i * 256;
        int lr = idx >> 5, p = idx & 31;
        uint32_t hv = packh(__float2half_rn(s[2 * p][lr]), __float2half_rn(s[2 * p + 1][lr]));
        *(uint32_t*)(hi + (size_t)(c0 + lr) * K + (r0 + 2 * p)) = hv;
    }
}

// ================= HMMA GEMM: C = A(fp16) x B(fp16)^T, fp32 acc =================
// CTA 128x128, K-chunk 128, 3-stage ring. 8 warps @ 64x32.
#define TCG_STAGE_BYTES 65536
#define TCG_NSTAGE 3
#define TCG_SMEM (TCG_NSTAGE * TCG_STAGE_BYTES)

__global__ __launch_bounds__(256, 1) void tc_gemm_kernel(
    const __half* __restrict__ A, const __half* __restrict__ B,
    float* __restrict__ C, const float* __restrict__ addend,
    __half* __restrict__ outH,
    const __half* __restrict__ gateMul,
    float* __restrict__ kDest, __half* __restrict__ vH, int qkvMode,
    int M, int N, int K)
{
    extern __shared__ char sm[];
    uint32_t sbase = smem_u32(sm);
    int tid = threadIdx.x, lane = tid & 31, wid = tid >> 5;
    int warp_m = wid & 1, warp_n = wid >> 1;
    int by = blockIdx.x, bx = blockIdx.y;   // M-block fastest

    const __half* srcs[2] = {
        A + (size_t)(by * 128) * K,
        B + (size_t)(bx * 128) * K };

    int nchunk = K >> 7;

    auto load_stage = [&](int stg, int c) {
        uint32_t dst0 = sbase + stg * TCG_STAGE_BYTES;
        int kc = c << 7;
#pragma unroll
        for (int i = 0; i < 16; i++) {
            int u = i * 256 + tid;
            int tile = u >> 11, w = u & 2047;
            int row = w >> 4, c16 = w & 15;
            uint32_t dst = dst0 + tile * 32768 + row * 256 + ((c16 ^ (row & 7)) << 4);
            cp_async16(dst, srcs[tile] + (size_t)row * K + kc + c16 * 8);
        }
    };

    load_stage(0, 0); CP_COMMIT();
    if (nchunk > 1) load_stage(1, 1);
    CP_COMMIT();

    float acc[4][4][4];
#pragma unroll
    for (int a = 0; a < 4; a++)
#pragma unroll
        for (int b = 0; b < 4; b++)
#pragma unroll
            for (int f = 0; f < 4; f++) acc[a][b][f] = 0.f;

    int a_r   = warp_m * 64 + (lane & 15);
    int a_kh  = lane >> 4;
    int b_r   = warp_n * 32 + (lane & 7) + ((lane >> 4) << 3);
    int b_kh  = (lane >> 3) & 1;

    for (int c = 0; c < nchunk; c++) {
        CP_WAIT1();
        __syncthreads();
        if (c + 2 < nchunk) load_stage((c + 2) % TCG_NSTAGE, c + 2);
        CP_COMMIT();

        uint32_t st = sbase + (c % TCG_NSTAGE) * TCG_STAGE_BYTES;
#pragma unroll
        for (int kk = 0; kk < 8; kk++) {
            int c16 = kk * 2;
            uint32_t ah[4][4], bh[2][4];
#pragma unroll
            for (int mb = 0; mb < 4; mb++) {
                int r = a_r + mb * 16;
                uint32_t off = r * 256 + (((c16 + a_kh) ^ (r & 7)) << 4);
                ldsm4(ah[mb], st + off);
            }
#pragma unroll
            for (int nb = 0; nb < 2; nb++) {
                int r = b_r + nb * 16;
                uint32_t off = r * 256 + (((c16 + b_kh) ^ (r & 7)) << 4);
                ldsm4(bh[nb], st + 32768 + off);
            }
#pragma unroll
            for (int mb = 0; mb < 4; mb++)
#pragma unroll
                for (int nb = 0; nb < 4; nb++) {
                    uint32_t b0 = bh[nb >> 1][(nb & 1) * 2], b1 = bh[nb >> 1][(nb & 1) * 2 + 1];
                    mmaF32(acc[mb][nb], ah[mb], b0, b1);
                }
        }
        __syncthreads();
    }

#pragma unroll
    for (int mb = 0; mb < 4; mb++) {
        int mrow = by * 128 + warp_m * 64 + mb * 16 + (lane >> 2);
#pragma unroll
        for (int nb = 0; nb < 4; nb++) {
            int ncol = bx * 128 + warp_n * 32 + nb * 8 + (lane & 3) * 2;
            float2 r0 = make_float2(acc[mb][nb][0], acc[mb][nb][1]);
            float2 r1 = make_float2(acc[mb][nb][2], acc[mb][nb][3]);

            if (qkvMode) {
                if (ncol < DMODEL) {
                    size_t i0 = (size_t)mrow * DMODEL + ncol;
                    size_t i1 = (size_t)(mrow + 8) * DMODEL + ncol;
                    *(float2*)(C + i0) = r0;
                    *(float2*)(C + i1) = r1;
                } else if (ncol < DMODEL + NKVH * HDIM) {
                    int cc = ncol - DMODEL;
                    size_t i0 = (size_t)mrow * (NKVH * HDIM) + cc;
                    size_t i1 = (size_t)(mrow + 8) * (NKVH * HDIM) + cc;
                    *(float2*)(kDest + i0) = r0;
                    *(float2*)(kDest + i1) = r1;
                } else {
                    int cc = ncol - DMODEL - NKVH * HDIM;
                    size_t i0 = (size_t)mrow * (NKVH * HDIM) + cc;
                    size_t i1 = (size_t)(mrow + 8) * (NKVH * HDIM) + cc;
                    *(uint32_t*)(vH + i0) = packh(__float2half_rn(r0.x), __float2half_rn(r0.y));
                    *(uint32_t*)(vH + i1) = packh(__float2half_rn(r1.x), __float2half_rn(r1.y));
                }
                continue;
            }

            size_t i0 = (size_t)mrow * N + ncol;
            size_t i1 = (size_t)(mrow + 8) * N + ncol;
            if (addend) {
                float2 a0 = *(const float2*)(addend + i0);
                float2 a1 = *(const float2*)(addend + i1);
                r0.x += a0.x; r0.y += a0.y;
                r1.x += a1.x; r1.y += a1.y;
            }
            if (gateMul) {
                float2 g0 = __half22float2(*(const __half2*)(gateMul + i0));
                float2 g1 = __half22float2(*(const __half2*)(gateMul + i1));
                r0.x *= g0.x / (1.f + __expf(-g0.x));
                r0.y *= g0.y / (1.f + __expf(-g0.y));
                r1.x *= g1.x / (1.f + __expf(-g1.x));
                r1.y *= g1.y / (1.f + __expf(-g1.y));
            }
            if (C) {
                *(float2*)(C + i0) = r0;
                *(float2*)(C + i1) = r1;
            }
            if (outH) {
                *(uint32_t*)(outH + i0) = packh(__float2half_rn(r0.x), __float2half_rn(r0.y));
                *(uint32_t*)(outH + i1) = packh(__float2half_rn(r1.x), __float2half_rn(r1.y));
            }
        }
    }
}

// ================= HMMA causal flash attention: pure fp16 operands, fp32 acc =================
// smem: Q 16KB + 2 stages x (K 16KB + V 16KB) = 80KB -> 2 CTAs/SM.
#define FA_STAGE_OFF 16384
#define FA_STAGE_BYTES 32768
#define FA_SMEM (FA_STAGE_OFF + 2 * FA_STAGE_BYTES)   // 80KB

__global__ __launch_bounds__(128, 2) void flash_attn_kernel(
    const __half* __restrict__ qh,
    const __half* __restrict__ kh, const __half* __restrict__ vh,
    __half* __restrict__ o)
{
    extern __shared__ char sm[];
    uint32_t sbase = smem_u32(sm);
    int qb = blockIdx.x, h = blockIdx.y, kvh = h >> 2;
    int tid = threadIdx.x, lane = tid & 31, w = tid >> 5;

#pragma unroll
    for (int i = 0; i < 8; i++) {
        int u = tid + i * 128;
        int row = u >> 4, c16 = u & 15;
        uint32_t dst = sbase + row * 256 + ((c16 ^ (row & 7)) << 4);
        cp_async16(dst, qh + (size_t)(qb * 64 + row) * DMODEL + h * HDIM + c16 * 8);
    }

    auto load_kv = [&](int stg, int kb) {
        uint32_t dst0 = sbase + FA_STAGE_OFF + stg * FA_STAGE_BYTES;
        const __half* srcs[2] = { kh, vh };
#pragma unroll
        for (int b = 0; b < 2; b++) {
            const __half* s = srcs[b];
#pragma unroll
            for (int i = 0; i < 8; i++) {
                int u = tid + i * 128;
                int row = u >> 4, c16 = u & 15;
                uint32_t dst = dst0 + b * 16384 + row * 256 + ((c16 ^ (row & 7)) << 4);
                cp_async16(dst, s + (size_t)(kb * 64 + row) * (NKVH * HDIM) + kvh * HDIM + c16 * 8);
            }
        }
    };

    load_kv(0, 0); CP_COMMIT();
    if (qb >= 1) load_kv(1, 1);
    CP_COMMIT();

    float O[16][4];
#pragma unroll
    for (int i = 0; i < 16; i++)
#pragma unroll
        for (int f = 0; f < 4; f++) O[i][f] = 0.f;
    float m_lo = -1e30f, m_hi = -1e30f, l_lo = 0.f, l_hi = 0.f;

    int r_loc = w * 16 + (lane >> 2);

    for (int kb = 0; kb <= qb; kb++) {
        CP_WAIT1();
        __syncthreads();
        uint32_t kbase = sbase + FA_STAGE_OFF + (kb & 1) * FA_STAGE_BYTES;

        float S[8][4];
#pragma unroll
        for (int i = 0; i < 8; i++)
#pragma unroll
            for (int f = 0; f < 4; f++) S[i][f] = 0.f;

#pragma unroll
        for (int kk = 0; kk < 8; kk++) {
            uint32_t aq[4];
            int ar = w * 16 + (lane & 15);
            int ac = kk * 2 + (lane >> 4);
            ldsm4(aq, sbase + ar * 256 + ((ac ^ (ar & 7)) << 4));
#pragma unroll
            for (int nblk = 0; nblk < 4; nblk++) {
                int br = nblk * 16 + (lane & 7) + ((lane >> 4) << 3);
                int bc = kk * 2 + ((lane >> 3) & 1);
                uint32_t boff = br * 256 + ((bc ^ (br & 7)) << 4);
                uint32_t bh4[4];
                ldsm4(bh4, kbase + boff);
                mmaF32(S[2*nblk],   aq, bh4[0], bh4[1]);
                mmaF32(S[2*nblk+1], aq, bh4[2], bh4[3]);
            }
        }

        if (kb == qb) {
#pragma unroll
            for (int nt = 0; nt < 8; nt++) {
                int c = nt * 8 + (lane & 3) * 2;
                if (c     > r_loc)     S[nt][0] = -1e30f;
                if (c + 1 > r_loc)     S[nt][1] = -1e30f;
                if (c     > r_loc + 8) S[nt][2] = -1e30f;
                if (c + 1 > r_loc + 8) S[nt][3] = -1e30f;
            }
        }

        float rm_lo = -1e30f, rm_hi = -1e30f;
#pragma unroll
        for (int nt = 0; nt < 8; nt++) {
            rm_lo = fmaxf(rm_lo, fmaxf(S[nt][0], S[nt][1]));
            rm_hi = fmaxf(rm_hi, fmaxf(S[nt][2], S[nt][3]));
        }
        rm_lo = fmaxf(rm_lo, __shfl_xor_sync(0xffffffffu, rm_lo, 1));
        rm_lo = fmaxf(rm_lo, __shfl_xor_sync(0xffffffffu, rm_lo, 2));
        rm_hi = fmaxf(rm_hi, __shfl_xor_sync(0xffffffffu, rm_hi, 1));
        rm_hi = fmaxf(rm_hi, __shfl_xor_sync(0xffffffffu, rm_hi, 2));
        float mn_lo = fmaxf(m_lo, rm_lo), mn_hi = fmaxf(m_hi, rm_hi);
        float corr_lo = __expf(m_lo - mn_lo), corr_hi = __expf(m_hi - mn_hi);

        uint32_t ph[8][2];
        float sum_lo = 0.f, sum_hi = 0.f;
#pragma unroll
        for (int nt = 0; nt < 8; nt++) {
            float p0 = __expf(S[nt][0] - mn_lo);
            float p1 = __expf(S[nt][1] - mn_lo);
            float p2 = __expf(S[nt][2] - mn_hi);
            float p3 = __expf(S[nt][3] - mn_hi);
            sum_lo += p0 + p1; sum_hi += p2 + p3;
            ph[nt][0] = packh(__float2half_rn(p0), __float2half_rn(p1));
            ph[nt][1] = packh(__float2half_rn(p2), __float2half_rn(p3));
        }
        sum_lo += __shfl_xor_sync(0xffffffffu, sum_lo, 1);
        sum_lo += __shfl_xor_sync(0xffffffffu, sum_lo, 2);
        sum_hi += __shfl_xor_sync(0xffffffffu, sum_hi, 1);
        sum_hi += __shfl_xor_sync(0xffffffffu, sum_hi, 2);
        l_lo = l_lo * corr_lo + sum_lo;
        l_hi = l_hi * corr_hi + sum_hi;
        m_lo = mn_lo; m_hi = mn_hi;
#pragma unroll
        for (int ot = 0; ot < 16; ot++) {
            O[ot][0] *= corr_lo; O[ot][1] *= corr_lo;
            O[ot][2] *= corr_hi; O[ot][3] *= corr_hi;
        }

        uint32_t vbase = kbase + 16384;
#pragma unroll
        for (int kt = 0; kt < 4; kt++) {
            uint32_t aH[4] = { ph[2*kt][0], ph[2*kt][1], ph[2*kt+1][0], ph[2*kt+1][1] };
            int krow = kt * 16 + (lane & 7) + ((lane >> 3) & 1) * 8;
#pragma unroll
            for (int ob = 0; ob < 8; ob++) {
                int cu = ob * 2 + (lane >> 4);
                uint32_t off = krow * 256 + ((cu ^ (krow & 7)) << 4);
                uint32_t bvh[4];
                ldsm4t(bvh, vbase + off);
                mmaF32(O[2*ob],   aH, bvh[0], bvh[1]);
                mmaF32(O[2*ob+1], aH, bvh[2], bvh[3]);
            }
        }

        __syncthreads();
        if (kb + 2 <= qb) load_kv(kb & 1, kb + 2);
        CP_COMMIT();
    }

    float il_lo = 1.f / l_lo, il_hi = 1.f / l_hi;
    int row0 = qb * 64 + r_loc;
#pragma unroll
    for (int ot = 0; ot < 16; ot++) {
        int col = h * HDIM + ot * 8 + (lane & 3) * 2;
        size_t i0 = (size_t)row0 * DMODEL + col;
        size_t i1 = (size_t)(row0 + 8) * DMODEL + col;
        *(uint32_t*)(o + i0) = packh(__float2half_rn(O[ot][0] * il_lo), __float2half_rn(O[ot][1] * il_lo));
        *(uint32_t*)(o + i1) = packh(__float2half_rn(O[ot][2] * il_hi), __float2half_rn(O[ot][3] * il_hi));
    }
}

// ================= host launcher =================
extern "C" void kernel_launch(void* const* d_in, const int* in_sizes, int n_in,
                              void* d_out, int out_size)
{
    const float* hidden = (const float*)d_in[0];
    const float* cosb  = (const float*)d_in[2];
    const float* sinb  = (const float*)d_in[3];
    const float* ln1   = (const float*)d_in[4];
    const float* wq    = (const float*)d_in[5];
    const float* wk    = (const float*)d_in[6];
    const float* wv    = (const float*)d_in[7];
    const float* wo    = (const float*)d_in[8];
    const float* ln2   = (const float*)d_in[9];
    const float* gatew = (const float*)d_in[10];
    const float* upw   = (const float*)d_in[11];
    const float* downw = (const float*)d_in[12];
    float* out = (float*)d_out;

    float *q, *k, *h;
    cudaGetSymbolAddress((void**)&q, g_q);
    cudaGetSymbolAddress((void**)&k, g_k);
    cudaGetSymbolAddress((void**)&h, g_h);

    __half *qkvT,*woT,*gwT,*uwT,*dwT;
    cudaGetSymbolAddress((void**)&qkvT, g_wqkvT);
    cudaGetSymbolAddress((void**)&woT, g_woT);
    cudaGetSymbolAddress((void**)&gwT, g_gwT);
    cudaGetSymbolAddress((void**)&uwT, g_uwT);
    cudaGetSymbolAddress((void**)&dwT, g_dwT);

    __half *xn,*at,*x2,*ga,*gateH,*qhp,*khp,*vhp;
    cudaGetSymbolAddress((void**)&xn, g_xn);
    cudaGetSymbolAddress((void**)&at, g_at);
    cudaGetSymbolAddress((void**)&x2, g_x2);
    cudaGetSymbolAddress((void**)&ga, g_ga);
    cudaGetSymbolAddress((void**)&gateH, g_gate);
    cudaGetSymbolAddress((void**)&qhp, g_qh);
    cudaGetSymbolAddress((void**)&khp, g_kh);
    cudaGetSymbolAddress((void**)&vhp, g_vh);

    cudaFuncSetAttribute(tc_gemm_kernel, cudaFuncAttributeMaxDynamicSharedMemorySize, TCG_SMEM);
    cudaFuncSetAttribute(flash_attn_kernel, cudaFuncAttributeMaxDynamicSharedMemorySize, FA_SMEM);

    static cudaStream_t s2 = nullptr;
    static cudaEvent_t evFork = nullptr, evJoin = nullptr;
    if (!s2) {
        cudaStreamCreateWithFlags(&s2, cudaStreamNonBlocking);
        cudaEventCreateWithFlags(&evFork, cudaEventDisableTiming);
        cudaEventCreateWithFlags(&evJoin, cudaEventDisableTiming);
    }

    // ---- main stream: QKV weight prep + rmsnorm ----
    rmsnorm_h_kernel<<<S_LEN, 256>>>(hidden, ln1, xn);
    transpose_h_kernel<<<dim3(DMODEL/64, DMODEL/64), 256>>>(wq, qkvT, DMODEL, DMODEL);
    transpose_h_kernel<<<dim3(NKVH*HDIM/64, DMODEL/64), 256>>>(wk, qkvT + (size_t)DMODEL*DMODEL, DMODEL, NKVH*HDIM);
    transpose_h_kernel<<<dim3(NKVH*HDIM/64, DMODEL/64), 256>>>(wv, qkvT + (size_t)(DMODEL+NKVH*HDIM)*DMODEL, DMODEL, NKVH*HDIM);

    // ---- fork: wo/gate/up/down transposes on side stream ----
    cudaEventRecord(evFork, 0);
    cudaStreamWaitEvent(s2, evFork, 0);
    transpose_h_kernel<<<dim3(DMODEL/64, DMODEL/64), 256, 0, s2>>>(wo, woT, DMODEL, DMODEL);
    transpose_h_kernel<<<dim3(DFFN/64, DMODEL/64), 256, 0, s2>>>(gatew, gwT, DMODEL, DFFN);
    transpose_h_kernel<<<dim3(DFFN/64, DMODEL/64), 256, 0, s2>>>(upw, uwT, DMODEL, DFFN);
    transpose_h_kernel<<<dim3(DMODEL/64, DFFN/64), 256, 0, s2>>>(downw, dwT, DFFN, DMODEL);
    cudaEventRecord(evJoin, s2);

    // ---- main chain: QKV -> rope -> attention ----
    tc_gemm_kernel<<<dim3(S_LEN/128, NQKV/128), 256, TCG_SMEM>>>(
        xn, qkvT, q, nullptr, nullptr, nullptr, k, vhp, 1, S_LEN, NQKV, DMODEL);

    const float qscale = 0.08838834764831845f;
    rope_l2_h_kernel<<<S_LEN * NHEADS / 8, 256>>>(q, qhp, NHEADS, cosb, sinb, qscale);
    rope_l2_h_kernel<<<S_LEN * NKVH  / 8, 256>>>(k, khp, NKVH,  cosb, sinb, 1.f);

    flash_attn_kernel<<<dim3(S_LEN / 64, NHEADS), 128, FA_SMEM>>>(qhp, khp, vhp, at);

    // ---- join: weight prep must be done before wo GEMM ----
    cudaStreamWaitEvent(0, evJoin, 0);

    tc_gemm_kernel<<<dim3(S_LEN/128, DMODEL/128), 256, TCG_SMEM>>>(
        at, woT, h, hidden, nullptr, nullptr, nullptr, nullptr, 0, S_LEN, DMODEL, DMODEL);

    rmsnorm_h_kernel<<<S_LEN, 256>>>(h, ln2, x2);

    tc_gemm_kernel<<<dim3(S_LEN/128, DFFN/128), 256, TCG_SMEM>>>(
        x2, gwT, nullptr, nullptr, gateH, nullptr, nullptr, nullptr, 0, S_LEN, DFFN, DMODEL);
    tc_gemm_kernel<<<dim3(S_LEN/128, DFFN/128), 256, TCG_SMEM>>>(
        x2, uwT, nullptr, nullptr, ga, gateH, nullptr, nullptr, 0, S_LEN, DFFN, DMODEL);

    tc_gemm_kernel<<<dim3(S_LEN/128, DMODEL/128), 256, TCG_SMEM>>>(
        ga, dwT, out, h, nullptr, nullptr, nullptr, nullptr, 0, S_LEN, DMODEL, DFFN);
}

// round 15
// speedup vs baseline: 2.7673x; 1.1019x over previous
#include <cuda_runtime.h>
#include <cuda_fp16.h>
#include <math.h>
#include <stdint.h>

#define S_LEN  2048
#define DMODEL 4096
#define NHEADS 32
#define NKVH   8
#define HDIM   128
#define DFFN   16384

// ================= low-level helpers =================
__device__ __forceinline__ uint32_t smem_u32(const void* p) {
    uint32_t a;
    asm("{ .reg .u64 t; cvta.to.shared.u64 t, %1; cvt.u32.u64 %0, t; }" : "=r"(a) : "l"(p));
    return a;
}
__device__ __forceinline__ void cp_async16(uint32_t dst, const void* src) {
    asm volatile("cp.async.cg.shared.global [%0], [%1], 16;" :: "r"(dst), "l"(src));
}
#define CP_COMMIT() asm volatile("cp.async.commit_group;" ::: "memory")
#define CP_WAIT0()  asm volatile("cp.async.wait_group 0;" ::: "memory")
#define CP_WAIT1()  asm volatile("cp.async.wait_group 1;" ::: "memory")

__device__ __forceinline__ void ldsm4(uint32_t* r, uint32_t addr) {
    asm volatile("ldmatrix.sync.aligned.m8n8.x4.shared.b16 {%0,%1,%2,%3}, [%4];"
        : "=r"(r[0]), "=r"(r[1]), "=r"(r[2]), "=r"(r[3]) : "r"(addr));
}
__device__ __forceinline__ void ldsm4t(uint32_t* r, uint32_t addr) {
    asm volatile("ldmatrix.sync.aligned.m8n8.x4.trans.shared.b16 {%0,%1,%2,%3}, [%4];"
        : "=r"(r[0]), "=r"(r[1]), "=r"(r[2]), "=r"(r[3]) : "r"(addr));
}
__device__ __forceinline__ void mmaF32(float* d, const uint32_t* a, uint32_t b0, uint32_t b1) {
    asm volatile("mma.sync.aligned.m16n8k16.row.col.f32.f16.f16.f32 "
        "{%0,%1,%2,%3}, {%4,%5,%6,%7}, {%8,%9}, {%0,%1,%2,%3};"
        : "+f"(d[0]), "+f"(d[1]), "+f"(d[2]), "+f"(d[3])
        : "r"(a[0]), "r"(a[1]), "r"(a[2]), "r"(a[3]), "r"(b0), "r"(b1));
}

__device__ __forceinline__ uint32_t packh(__half a, __half b) {
    __half2 t = __halves2half2(a, b);
    return *(uint32_t*)&t;
}

// ================= scratch =================
__device__ float g_q [S_LEN * DMODEL];
__device__ float g_k [S_LEN * NKVH * HDIM];
__device__ float g_h [S_LEN * DMODEL];

#define NQKV (DMODEL + 2 * NKVH * HDIM)
__device__ __half g_wqkvT[NQKV * DMODEL];
__device__ __half g_woT[DMODEL * DMODEL];
__device__ __half g_gwT[DFFN * DMODEL];
__device__ __half g_uwT[DFFN * DMODEL];
__device__ __half g_dwT[DMODEL * DFFN];

__device__ __half g_xn[S_LEN * DMODEL];
__device__ __half g_at[S_LEN * DMODEL];
__device__ __half g_x2[S_LEN * DMODEL];
__device__ __half g_ga[S_LEN * DFFN];
__device__ __half g_gate[S_LEN * DFFN];

// attention operands: all single fp16
__device__ __half g_qh[S_LEN * DMODEL];
__device__ __half g_kh[S_LEN * NKVH * HDIM];
__device__ __half g_vh[S_LEN * NKVH * HDIM];

// ================= RMSNorm -> single fp16 =================
__global__ __launch_bounds__(256) void rmsnorm_h_kernel(
    const float* __restrict__ x, const float* __restrict__ w, __half* __restrict__ y)
{
    int row = blockIdx.x;
    const float* xr = x + (size_t)row * DMODEL;

    float4 vals[4];
    float ss = 0.f;
#pragma unroll
    for (int it = 0; it < 4; it++) {
        int idx = (threadIdx.x + it * 256) * 4;
        float4 v = *(const float4*)(xr + idx);
        vals[it] = v;
        ss += v.x*v.x + v.y*v.y + v.z*v.z + v.w*v.w;
    }
#pragma unroll
    for (int o = 16; o; o >>= 1) ss += __shfl_xor_sync(0xffffffffu, ss, o);

    __shared__ float red[8];
    if ((threadIdx.x & 31) == 0) red[threadIdx.x >> 5] = ss;
    __syncthreads();
    float tot = 0.f;
#pragma unroll
    for (int i = 0; i < 8; i++) tot += red[i];
    float inv = rsqrtf(tot * (1.f / DMODEL) + 1e-5f);

#pragma unroll
    for (int it = 0; it < 4; it++) {
        int idx = (threadIdx.x + it * 256) * 4;
        float4 v  = vals[it];
        float4 wv = *(const float4*)(w + idx);
        uint2 hv;
        hv.x = packh(__float2half_rn(v.x * inv * wv.x), __float2half_rn(v.y * inv * wv.y));
        hv.y = packh(__float2half_rn(v.z * inv * wv.z), __float2half_rn(v.w * inv * wv.w));
        *(uint2*)(y + (size_t)row * DMODEL + idx) = hv;
    }
}

// ================= RoPE + L2-norm -> single fp16 =================
__global__ __launch_bounds__(256) void rope_l2_h_kernel(
    const float* __restrict__ in, __half* __restrict__ outh,
    int nheads, const float* __restrict__ cosb, const float* __restrict__ sinb, float scale)
{
    int wid  = (blockIdx.x * 256 + threadIdx.x) >> 5;
    int lane = threadIdx.x & 31;
    int s  = wid / nheads;
    int hh = wid % nheads;
    size_t base = (size_t)s * nheads * HDIM + hh * HDIM + lane * 4;
    float4 vv = *(const float4*)(in + base);

    float c0 = cosb[s * 64 + lane * 2],     s0 = sinb[s * 64 + lane * 2];
    float c1 = cosb[s * 64 + lane * 2 + 1], s1 = sinb[s * 64 + lane * 2 + 1];
    float o0 = vv.x * c0 - vv.y * s0;
    float o1 = vv.x * s0 + vv.y * c0;
    float o2 = vv.z * c1 - vv.w * s1;
    float o3 = vv.z * s1 + vv.w * c1;

    float ss = o0*o0 + o1*o1 + o2*o2 + o3*o3;
#pragma unroll
    for (int o = 16; o; o >>= 1) ss += __shfl_xor_sync(0xffffffffu, ss, o);
    float rr = rsqrtf(ss * (1.f / HDIM) + 1e-5f) * scale;
    o0 *= rr; o1 *= rr; o2 *= rr; o3 *= rr;

    uint2 hv;
    hv.x = packh(__float2half_rn(o0), __float2half_rn(o1));
    hv.y = packh(__float2half_rn(o2), __float2half_rn(o3));
    *(uint2*)(outh + base) = hv;
}

// ================= transpose to fp16: in[K,N] fp32 -> [N,K] fp16 =================
__global__ __launch_bounds__(256) void transpose_h_kernel(
    const float* __restrict__ in, __half* __restrict__ hi, int K, int N)
{
    __shared__ float s[64][65];
    int r0 = blockIdx.y * 64, c0 = blockIdx.x * 64;
#pragma unroll
    for (int i = 0; i < 8; i++) {
        int idx = threadIdx.x + i * 256;
        int lr = idx >> 5, p = idx & 31;
        float2 v = *(const float2*)(in + (size_t)(r0 + lr) * N + c0 + 2 * p);
        s[lr][2 * p]     = v.x;
        s[lr][2 * p + 1] = v.y;
    }
    __syncthreads();
#pragma unroll
    for (int i = 0; i < 8; i++) {
        int idx = threadIdx.x + i * 256;
        int lr = idx >> 5, p = idx & 31;
        uint32_t hv = packh(__float2half_rn(s[2 * p][lr]), __float2half_rn(s[2 * p + 1][lr]));
        *(uint32_t*)(hi + (size_t)(c0 + lr) * K + (r0 + 2 * p)) = hv;
    }
}

// ================= HMMA GEMM: C = A(fp16) x B(fp16)^T, fp32 acc =================
// CTA 256x128, K-chunk 128, 2-stage ring (2 x 96KB). 8 warps in 4x2, 64x64 each.
#define TCG_STAGE_BYTES 98304
#define TCG_SMEM (2 * TCG_STAGE_BYTES)

__global__ __launch_bounds__(256, 1) void tc_gemm_kernel(
    const __half* __restrict__ A, const __half* __restrict__ B,
    float* __restrict__ C, const float* __restrict__ addend,
    __half* __restrict__ outH,
    const __half* __restrict__ gateMul,
    float* __restrict__ kDest, __half* __restrict__ vH, int qkvMode,
    int M, int N, int K)
{
    extern __shared__ char sm[];
    uint32_t sbase = smem_u32(sm);
    int tid = threadIdx.x, lane = tid & 31, wid = tid >> 5;
    int warp_m = wid & 3, warp_n = wid >> 2;     // 4 x 2 warps, 64x64 each
    int by = blockIdx.x, bx = blockIdx.y;        // M-block fastest

    const __half* srcA = A + (size_t)(by * 256) * K;
    const __half* srcB = B + (size_t)(bx * 128) * K;

    int nchunk = K >> 7;

    // stage: A 256 rows x 256B (64KB) at +0; B 128 rows x 256B (32KB) at +65536
    auto load_stage = [&](int stg, int c) {
        uint32_t dst0 = sbase + stg * TCG_STAGE_BYTES;
        int kc = c << 7;
#pragma unroll
        for (int i = 0; i < 24; i++) {
            int u = i * 256 + tid;
            uint32_t dst; const __half* src;
            if (u < 4096) {                       // A: 4096 16B-units
                int row = u >> 4, c16 = u & 15;
                dst = dst0 + row * 256 + ((c16 ^ (row & 7)) << 4);
                src = srcA + (size_t)row * K + kc + c16 * 8;
            } else {                              // B: 2048 units
                int w2 = u - 4096;
                int row = w2 >> 4, c16 = w2 & 15;
                dst = dst0 + 65536 + row * 256 + ((c16 ^ (row & 7)) << 4);
                src = srcB + (size_t)row * K + kc + c16 * 8;
            }
            cp_async16(dst, src);
        }
    };

    load_stage(0, 0); CP_COMMIT();

    float acc[4][8][4];
#pragma unroll
    for (int a = 0; a < 4; a++)
#pragma unroll
        for (int b = 0; b < 8; b++)
#pragma unroll
            for (int f = 0; f < 4; f++) acc[a][b][f] = 0.f;

    int a_r   = warp_m * 64 + (lane & 15);
    int a_kh  = lane >> 4;
    int b_r   = warp_n * 64 + (lane & 7) + ((lane >> 4) << 3);
    int b_kh  = (lane >> 3) & 1;

    for (int c = 0; c < nchunk; c++) {
        if (c + 1 < nchunk) { load_stage((c + 1) & 1, c + 1); CP_COMMIT(); CP_WAIT1(); }
        else                { CP_WAIT0(); }
        __syncthreads();

        uint32_t st = sbase + (c & 1) * TCG_STAGE_BYTES;
#pragma unroll
        for (int kk = 0; kk < 8; kk++) {
            int c16 = kk * 2;
            uint32_t ah[4][4], bh[4][4];
#pragma unroll
            for (int mb = 0; mb < 4; mb++) {
                int r = a_r + mb * 16;
                uint32_t off = r * 256 + (((c16 + a_kh) ^ (r & 7)) << 4);
                ldsm4(ah[mb], st + off);
            }
#pragma unroll
            for (int nb = 0; nb < 4; nb++) {
                int r = b_r + nb * 16;
                uint32_t off = r * 256 + (((c16 + b_kh) ^ (r & 7)) << 4);
                ldsm4(bh[nb], st + 65536 + off);
            }
#pragma unroll
            for (int mb = 0; mb < 4; mb++)
#pragma unroll
                for (int j = 0; j < 8; j++) {
                    uint32_t b0 = bh[j >> 1][(j & 1) * 2], b1 = bh[j >> 1][(j & 1) * 2 + 1];
                    mmaF32(acc[mb][j], ah[mb], b0, b1);
                }
        }
        __syncthreads();
    }

#pragma unroll
    for (int mb = 0; mb < 4; mb++) {
        int mrow = by * 256 + warp_m * 64 + mb * 16 + (lane >> 2);
#pragma unroll
        for (int j = 0; j < 8; j++) {
            int ncol = bx * 128 + warp_n * 64 + j * 8 + (lane & 3) * 2;
            float2 r0 = make_float2(acc[mb][j][0], acc[mb][j][1]);
            float2 r1 = make_float2(acc[mb][j][2], acc[mb][j][3]);

            if (qkvMode) {
                if (ncol < DMODEL) {
                    size_t i0 = (size_t)mrow * DMODEL + ncol;
                    size_t i1 = (size_t)(mrow + 8) * DMODEL + ncol;
                    *(float2*)(C + i0) = r0;
                    *(float2*)(C + i1) = r1;
                } else if (ncol < DMODEL + NKVH * HDIM) {
                    int cc = ncol - DMODEL;
                    size_t i0 = (size_t)mrow * (NKVH * HDIM) + cc;
                    size_t i1 = (size_t)(mrow + 8) * (NKVH * HDIM) + cc;
                    *(float2*)(kDest + i0) = r0;
                    *(float2*)(kDest + i1) = r1;
                } else {
                    int cc = ncol - DMODEL - NKVH * HDIM;
                    size_t i0 = (size_t)mrow * (NKVH * HDIM) + cc;
                    size_t i1 = (size_t)(mrow + 8) * (NKVH * HDIM) + cc;
                    *(uint32_t*)(vH + i0) = packh(__float2half_rn(r0.x), __float2half_rn(r0.y));
                    *(uint32_t*)(vH + i1) = packh(__float2half_rn(r1.x), __float2half_rn(r1.y));
                }
                continue;
            }

            size_t i0 = (size_t)mrow * N + ncol;
            size_t i1 = (size_t)(mrow + 8) * N + ncol;
            if (addend) {
                float2 a0 = *(const float2*)(addend + i0);
                float2 a1 = *(const float2*)(addend + i1);
                r0.x += a0.x; r0.y += a0.y;
                r1.x += a1.x; r1.y += a1.y;
            }
            if (gateMul) {
                float2 g0 = __half22float2(*(const __half2*)(gateMul + i0));
                float2 g1 = __half22float2(*(const __half2*)(gateMul + i1));
                r0.x *= g0.x / (1.f + __expf(-g0.x));
                r0.y *= g0.y / (1.f + __expf(-g0.y));
                r1.x *= g1.x / (1.f + __expf(-g1.x));
                r1.y *= g1.y / (1.f + __expf(-g1.y));
            }
            if (C) {
                *(float2*)(C + i0) = r0;
                *(float2*)(C + i1) = r1;
            }
            if (outH) {
                *(uint32_t*)(outH + i0) = packh(__float2half_rn(r0.x), __float2half_rn(r0.y));
                *(uint32_t*)(outH + i1) = packh(__float2half_rn(r1.x), __float2half_rn(r1.y));
            }
        }
    }
}

// ================= HMMA causal flash attention: pure fp16 operands, fp32 acc =================
#define FA_STAGE_OFF 16384
#define FA_STAGE_BYTES 32768
#define FA_SMEM (FA_STAGE_OFF + 2 * FA_STAGE_BYTES)   // 80KB

__global__ __launch_bounds__(128, 2) void flash_attn_kernel(
    const __half* __restrict__ qh,
    const __half* __restrict__ kh, const __half* __restrict__ vh,
    __half* __restrict__ o)
{
    extern __shared__ char sm[];
    uint32_t sbase = smem_u32(sm);
    int qb = blockIdx.x, h = blockIdx.y, kvh = h >> 2;
    int tid = threadIdx.x, lane = tid & 31, w = tid >> 5;

#pragma unroll
    for (int i = 0; i < 8; i++) {
        int u = tid + i * 128;
        int row = u >> 4, c16 = u & 15;
        uint32_t dst = sbase + row * 256 + ((c16 ^ (row & 7)) << 4);
        cp_async16(dst, qh + (size_t)(qb * 64 + row) * DMODEL + h * HDIM + c16 * 8);
    }

    auto load_kv = [&](int stg, int kb) {
        uint32_t dst0 = sbase + FA_STAGE_OFF + stg * FA_STAGE_BYTES;
        const __half* srcs[2] = { kh, vh };
#pragma unroll
        for (int b = 0; b < 2; b++) {
            const __half* s = srcs[b];
#pragma unroll
            for (int i = 0; i < 8; i++) {
                int u = tid + i * 128;
                int row = u >> 4, c16 = u & 15;
                uint32_t dst = dst0 + b * 16384 + row * 256 + ((c16 ^ (row & 7)) << 4);
                cp_async16(dst, s + (size_t)(kb * 64 + row) * (NKVH * HDIM) + kvh * HDIM + c16 * 8);
            }
        }
    };

    load_kv(0, 0); CP_COMMIT();
    if (qb >= 1) load_kv(1, 1);
    CP_COMMIT();

    float O[16][4];
#pragma unroll
    for (int i = 0; i < 16; i++)
#pragma unroll
        for (int f = 0; f < 4; f++) O[i][f] = 0.f;
    float m_lo = -1e30f, m_hi = -1e30f, l_lo = 0.f, l_hi = 0.f;

    int r_loc = w * 16 + (lane >> 2);

    for (int kb = 0; kb <= qb; kb++) {
        CP_WAIT1();
        __syncthreads();
        uint32_t kbase = sbase + FA_STAGE_OFF + (kb & 1) * FA_STAGE_BYTES;

        float S[8][4];
#pragma unroll
        for (int i = 0; i < 8; i++)
#pragma unroll
            for (int f = 0; f < 4; f++) S[i][f] = 0.f;

#pragma unroll
        for (int kk = 0; kk < 8; kk++) {
            uint32_t aq[4];
            int ar = w * 16 + (lane & 15);
            int ac = kk * 2 + (lane >> 4);
            ldsm4(aq, sbase + ar * 256 + ((ac ^ (ar & 7)) << 4));
#pragma unroll
            for (int nblk = 0; nblk < 4; nblk++) {
                int br = nblk * 16 + (lane & 7) + ((lane >> 4) << 3);
                int bc = kk * 2 + ((lane >> 3) & 1);
                uint32_t boff = br * 256 + ((bc ^ (br & 7)) << 4);
                uint32_t bh4[4];
                ldsm4(bh4, kbase + boff);
                mmaF32(S[2*nblk],   aq, bh4[0], bh4[1]);
                mmaF32(S[2*nblk+1], aq, bh4[2], bh4[3]);
            }
        }

        if (kb == qb) {
#pragma unroll
            for (int nt = 0; nt < 8; nt++) {
                int c = nt * 8 + (lane & 3) * 2;
                if (c     > r_loc)     S[nt][0] = -1e30f;
                if (c + 1 > r_loc)     S[nt][1] = -1e30f;
                if (c     > r_loc + 8) S[nt][2] = -1e30f;
                if (c + 1 > r_loc + 8) S[nt][3] = -1e30f;
            }
        }

        float rm_lo = -1e30f, rm_hi = -1e30f;
#pragma unroll
        for (int nt = 0; nt < 8; nt++) {
            rm_lo = fmaxf(rm_lo, fmaxf(S[nt][0], S[nt][1]));
            rm_hi = fmaxf(rm_hi, fmaxf(S[nt][2], S[nt][3]));
        }
        rm_lo = fmaxf(rm_lo, __shfl_xor_sync(0xffffffffu, rm_lo, 1));
        rm_lo = fmaxf(rm_lo, __shfl_xor_sync(0xffffffffu, rm_lo, 2));
        rm_hi = fmaxf(rm_hi, __shfl_xor_sync(0xffffffffu, rm_hi, 1));
        rm_hi = fmaxf(rm_hi, __shfl_xor_sync(0xffffffffu, rm_hi, 2));
        float mn_lo = fmaxf(m_lo, rm_lo), mn_hi = fmaxf(m_hi, rm_hi);
        float corr_lo = __expf(m_lo - mn_lo), corr_hi = __expf(m_hi - mn_hi);

        uint32_t ph[8][2];
        float sum_lo = 0.f, sum_hi = 0.f;
#pragma unroll
        for (int nt = 0; nt < 8; nt++) {
            float p0 = __expf(S[nt][0] - mn_lo);
            float p1 = __expf(S[nt][1] - mn_lo);
            float p2 = __expf(S[nt][2] - mn_hi);
            float p3 = __expf(S[nt][3] - mn_hi);
            sum_lo += p0 + p1; sum_hi += p2 + p3;
            ph[nt][0] = packh(__float2half_rn(p0), __float2half_rn(p1));
            ph[nt][1] = packh(__float2half_rn(p2), __float2half_rn(p3));
        }
        sum_lo += __shfl_xor_sync(0xffffffffu, sum_lo, 1);
        sum_lo += __shfl_xor_sync(0xffffffffu, sum_lo, 2);
        sum_hi += __shfl_xor_sync(0xffffffffu, sum_hi, 1);
        sum_hi += __shfl_xor_sync(0xffffffffu, sum_hi, 2);
        l_lo = l_lo * corr_lo + sum_lo;
        l_hi = l_hi * corr_hi + sum_hi;
        m_lo = mn_lo; m_hi = mn_hi;
#pragma unroll
        for (int ot = 0; ot < 16; ot++) {
            O[ot][0] *= corr_lo; O[ot][1] *= corr_lo;
            O[ot][2] *= corr_hi; O[ot][3] *= corr_hi;
        }

        uint32_t vbase = kbase + 16384;
#pragma unroll
        for (int kt = 0; kt < 4; kt++) {
            uint32_t aH[4] = { ph[2*kt][0], ph[2*kt][1], ph[2*kt+1][0], ph[2*kt+1][1] };
            int krow = kt * 16 + (lane & 7) + ((lane >> 3) & 1) * 8;
#pragma unroll
            for (int ob = 0; ob < 8; ob++) {
                int cu = ob * 2 + (lane >> 4);
                uint32_t off = krow * 256 + ((cu ^ (krow & 7)) << 4);
                uint32_t bvh[4];
                ldsm4t(bvh, vbase + off);
                mmaF32(O[2*ob],   aH, bvh[0], bvh[1]);
                mmaF32(O[2*ob+1], aH, bvh[2], bvh[3]);
            }
        }

        __syncthreads();
        if (kb + 2 <= qb) load_kv(kb & 1, kb + 2);
        CP_COMMIT();
    }

    float il_lo = 1.f / l_lo, il_hi = 1.f / l_hi;
    int row0 = qb * 64 + r_loc;
#pragma unroll
    for (int ot = 0; ot < 16; ot++) {
        int col = h * HDIM + ot * 8 + (lane & 3) * 2;
        size_t i0 = (size_t)row0 * DMODEL + col;
        size_t i1 = (size_t)(row0 + 8) * DMODEL + col;
        *(uint32_t*)(o + i0) = packh(__float2half_rn(O[ot][0] * il_lo), __float2half_rn(O[ot][1] * il_lo));
        *(uint32_t*)(o + i1) = packh(__float2half_rn(O[ot][2] * il_hi), __float2half_rn(O[ot][3] * il_hi));
    }
}

// ================= host launcher =================
extern "C" void kernel_launch(void* const* d_in, const int* in_sizes, int n_in,
                              void* d_out, int out_size)
{
    const float* hidden = (const float*)d_in[0];
    const float* cosb  = (const float*)d_in[2];
    const float* sinb  = (const float*)d_in[3];
    const float* ln1   = (const float*)d_in[4];
    const float* wq    = (const float*)d_in[5];
    const float* wk    = (const float*)d_in[6];
    const float* wv    = (const float*)d_in[7];
    const float* wo    = (const float*)d_in[8];
    const float* ln2   = (const float*)d_in[9];
    const float* gatew = (const float*)d_in[10];
    const float* upw   = (const float*)d_in[11];
    const float* downw = (const float*)d_in[12];
    float* out = (float*)d_out;

    float *q, *k, *h;
    cudaGetSymbolAddress((void**)&q, g_q);
    cudaGetSymbolAddress((void**)&k, g_k);
    cudaGetSymbolAddress((void**)&h, g_h);

    __half *qkvT,*woT,*gwT,*uwT,*dwT;
    cudaGetSymbolAddress((void**)&qkvT, g_wqkvT);
    cudaGetSymbolAddress((void**)&woT, g_woT);
    cudaGetSymbolAddress((void**)&gwT, g_gwT);
    cudaGetSymbolAddress((void**)&uwT, g_uwT);
    cudaGetSymbolAddress((void**)&dwT, g_dwT);

    __half *xn,*at,*x2,*ga,*gateH,*qhp,*khp,*vhp;
    cudaGetSymbolAddress((void**)&xn, g_xn);
    cudaGetSymbolAddress((void**)&at, g_at);
    cudaGetSymbolAddress((void**)&x2, g_x2);
    cudaGetSymbolAddress((void**)&ga, g_ga);
    cudaGetSymbolAddress((void**)&gateH, g_gate);
    cudaGetSymbolAddress((void**)&qhp, g_qh);
    cudaGetSymbolAddress((void**)&khp, g_kh);
    cudaGetSymbolAddress((void**)&vhp, g_vh);

    cudaFuncSetAttribute(tc_gemm_kernel, cudaFuncAttributeMaxDynamicSharedMemorySize, TCG_SMEM);
    cudaFuncSetAttribute(flash_attn_kernel, cudaFuncAttributeMaxDynamicSharedMemorySize, FA_SMEM);

    static cudaStream_t s2 = nullptr;
    static cudaEvent_t evFork = nullptr, evJoin = nullptr;
    if (!s2) {
        cudaStreamCreateWithFlags(&s2, cudaStreamNonBlocking);
        cudaEventCreateWithFlags(&evFork, cudaEventDisableTiming);
        cudaEventCreateWithFlags(&evJoin, cudaEventDisableTiming);
    }

    // ---- main stream: QKV weight prep + rmsnorm ----
    rmsnorm_h_kernel<<<S_LEN, 256>>>(hidden, ln1, xn);
    transpose_h_kernel<<<dim3(DMODEL/64, DMODEL/64), 256>>>(wq, qkvT, DMODEL, DMODEL);
    transpose_h_kernel<<<dim3(NKVH*HDIM/64, DMODEL/64), 256>>>(wk, qkvT + (size_t)DMODEL*DMODEL, DMODEL, NKVH*HDIM);
    transpose_h_kernel<<<dim3(NKVH*HDIM/64, DMODEL/64), 256>>>(wv, qkvT + (size_t)(DMODEL+NKVH*HDIM)*DMODEL, DMODEL, NKVH*HDIM);

    // ---- fork: wo/gate/up/down transposes on side stream ----
    cudaEventRecord(evFork, 0);
    cudaStreamWaitEvent(s2, evFork, 0);
    transpose_h_kernel<<<dim3(DMODEL/64, DMODEL/64), 256, 0, s2>>>(wo, woT, DMODEL, DMODEL);
    transpose_h_kernel<<<dim3(DFFN/64, DMODEL/64), 256, 0, s2>>>(gatew, gwT, DMODEL, DFFN);
    transpose_h_kernel<<<dim3(DFFN/64, DMODEL/64), 256, 0, s2>>>(upw, uwT, DMODEL, DFFN);
    transpose_h_kernel<<<dim3(DMODEL/64, DFFN/64), 256, 0, s2>>>(downw, dwT, DFFN, DMODEL);
    cudaEventRecord(evJoin, s2);

    // ---- main chain: QKV -> rope -> attention ----
    tc_gemm_kernel<<<dim3(S_LEN/256, NQKV/128), 256, TCG_SMEM>>>(
        xn, qkvT, q, nullptr, nullptr, nullptr, k, vhp, 1, S_LEN, NQKV, DMODEL);

    const float qscale = 0.08838834764831845f;
    rope_l2_h_kernel<<<S_LEN * NHEADS / 8, 256>>>(q, qhp, NHEADS, cosb, sinb, qscale);
    rope_l2_h_kernel<<<S_LEN * NKVH  / 8, 256>>>(k, khp, NKVH,  cosb, sinb, 1.f);

    flash_attn_kernel<<<dim3(S_LEN / 64, NHEADS), 128, FA_SMEM>>>(qhp, khp, vhp, at);

    // ---- join: weight prep must be done before wo GEMM ----
    cudaStreamWaitEvent(0, evJoin, 0);

    tc_gemm_kernel<<<dim3(S_LEN/256, DMODEL/128), 256, TCG_SMEM>>>(
        at, woT, h, hidden, nullptr, nullptr, nullptr, nullptr, 0, S_LEN, DMODEL, DMODEL);

    rmsnorm_h_kernel<<<S_LEN, 256>>>(h, ln2, x2);

    tc_gemm_kernel<<<dim3(S_LEN/256, DFFN/128), 256, TCG_SMEM>>>(
        x2, gwT, nullptr, nullptr, gateH, nullptr, nullptr, nullptr, 0, S_LEN, DFFN, DMODEL);
    tc_gemm_kernel<<<dim3(S_LEN/256, DFFN/128), 256, TCG_SMEM>>>(
        x2, uwT, nullptr, nullptr, ga, gateH, nullptr, nullptr, 0, S_LEN, DFFN, DMODEL);

    tc_gemm_kernel<<<dim3(S_LEN/256, DMODEL/128), 256, TCG_SMEM>>>(
        ga, dwT, out, h, nullptr, nullptr, nullptr, nullptr, 0, S_LEN, DMODEL, DFFN);
}

// round 16
// speedup vs baseline: 2.7943x; 1.0098x over previous
#include <cuda_runtime.h>
#include <cuda_fp16.h>
#include <math.h>
#include <stdint.h>

#define S_LEN  2048
#define DMODEL 4096
#define NHEADS 32
#define NKVH   8
#define HDIM   128
#define DFFN   16384

// ================= low-level helpers =================
__device__ __forceinline__ uint32_t smem_u32(const void* p) {
    uint32_t a;
    asm("{ .reg .u64 t; cvta.to.shared.u64 t, %1; cvt.u32.u64 %0, t; }" : "=r"(a) : "l"(p));
    return a;
}
__device__ __forceinline__ void cp_async16(uint32_t dst, const void* src) {
    asm volatile("cp.async.cg.shared.global [%0], [%1], 16;" :: "r"(dst), "l"(src));
}
#define CP_COMMIT() asm volatile("cp.async.commit_group;" ::: "memory")
#define CP_WAIT0()  asm volatile("cp.async.wait_group 0;" ::: "memory")
#define CP_WAIT1()  asm volatile("cp.async.wait_group 1;" ::: "memory")

__device__ __forceinline__ void ldsm4(uint32_t* r, uint32_t addr) {
    asm volatile("ldmatrix.sync.aligned.m8n8.x4.shared.b16 {%0,%1,%2,%3}, [%4];"
        : "=r"(r[0]), "=r"(r[1]), "=r"(r[2]), "=r"(r[3]) : "r"(addr));
}
__device__ __forceinline__ void ldsm4t(uint32_t* r, uint32_t addr) {
    asm volatile("ldmatrix.sync.aligned.m8n8.x4.trans.shared.b16 {%0,%1,%2,%3}, [%4];"
        : "=r"(r[0]), "=r"(r[1]), "=r"(r[2]), "=r"(r[3]) : "r"(addr));
}
__device__ __forceinline__ void mmaF32(float* d, const uint32_t* a, uint32_t b0, uint32_t b1) {
    asm volatile("mma.sync.aligned.m16n8k16.row.col.f32.f16.f16.f32 "
        "{%0,%1,%2,%3}, {%4,%5,%6,%7}, {%8,%9}, {%0,%1,%2,%3};"
        : "+f"(d[0]), "+f"(d[1]), "+f"(d[2]), "+f"(d[3])
        : "r"(a[0]), "r"(a[1]), "r"(a[2]), "r"(a[3]), "r"(b0), "r"(b1));
}

__device__ __forceinline__ uint32_t packh(__half a, __half b) {
    __half2 t = __halves2half2(a, b);
    return *(uint32_t*)&t;
}

// ================= scratch =================
__device__ float g_h [S_LEN * DMODEL];

#define NQKV (DMODEL + 2 * NKVH * HDIM)
__device__ __half g_wqkvT[NQKV * DMODEL];
__device__ __half g_woT[DMODEL * DMODEL];
__device__ __half g_gwT[DFFN * DMODEL];
__device__ __half g_uwT[DFFN * DMODEL];
__device__ __half g_dwT[DMODEL * DFFN];

__device__ __half g_xn[S_LEN * DMODEL];
__device__ __half g_at[S_LEN * DMODEL];
__device__ __half g_x2[S_LEN * DMODEL];
__device__ __half g_ga[S_LEN * DFFN];
__device__ __half g_gate[S_LEN * DFFN];

// attention operands: single fp16; QKV GEMM writes raw, rope runs in-place on q/k
__device__ __half g_qh[S_LEN * DMODEL];
__device__ __half g_kh[S_LEN * NKVH * HDIM];
__device__ __half g_vh[S_LEN * NKVH * HDIM];

// ================= RMSNorm -> single fp16 =================
__global__ __launch_bounds__(256) void rmsnorm_h_kernel(
    const float* __restrict__ x, const float* __restrict__ w, __half* __restrict__ y)
{
    int row = blockIdx.x;
    const float* xr = x + (size_t)row * DMODEL;

    float4 vals[4];
    float ss = 0.f;
#pragma unroll
    for (int it = 0; it < 4; it++) {
        int idx = (threadIdx.x + it * 256) * 4;
        float4 v = *(const float4*)(xr + idx);
        vals[it] = v;
        ss += v.x*v.x + v.y*v.y + v.z*v.z + v.w*v.w;
    }
#pragma unroll
    for (int o = 16; o; o >>= 1) ss += __shfl_xor_sync(0xffffffffu, ss, o);

    __shared__ float red[8];
    if ((threadIdx.x & 31) == 0) red[threadIdx.x >> 5] = ss;
    __syncthreads();
    float tot = 0.f;
#pragma unroll
    for (int i = 0; i < 8; i++) tot += red[i];
    float inv = rsqrtf(tot * (1.f / DMODEL) + 1e-5f);

#pragma unroll
    for (int it = 0; it < 4; it++) {
        int idx = (threadIdx.x + it * 256) * 4;
        float4 v  = vals[it];
        float4 wv = *(const float4*)(w + idx);
        uint2 hv;
        hv.x = packh(__float2half_rn(v.x * inv * wv.x), __float2half_rn(v.y * inv * wv.y));
        hv.y = packh(__float2half_rn(v.z * inv * wv.z), __float2half_rn(v.w * inv * wv.w));
        *(uint2*)(y + (size_t)row * DMODEL + idx) = hv;
    }
}

// ================= RoPE + L2-norm, in-place on fp16 buffer =================
__global__ __launch_bounds__(256) void rope_l2_h_kernel(
    __half* __restrict__ buf, int nheads,
    const float* __restrict__ cosb, const float* __restrict__ sinb, float scale)
{
    int wid  = (blockIdx.x * 256 + threadIdx.x) >> 5;
    int lane = threadIdx.x & 31;
    int s  = wid / nheads;
    int hh = wid % nheads;
    size_t base = (size_t)s * nheads * HDIM + hh * HDIM + lane * 4;
    uint2 hv = *(uint2*)(buf + base);
    float2 v01 = __half22float2(*(__half2*)&hv.x);
    float2 v23 = __half22float2(*(__half2*)&hv.y);

    float c0 = cosb[s * 64 + lane * 2],     s0 = sinb[s * 64 + lane * 2];
    float c1 = cosb[s * 64 + lane * 2 + 1], s1 = sinb[s * 64 + lane * 2 + 1];
    float o0 = v01.x * c0 - v01.y * s0;
    float o1 = v01.x * s0 + v01.y * c0;
    float o2 = v23.x * c1 - v23.y * s1;
    float o3 = v23.x * s1 + v23.y * c1;

    float ss = o0*o0 + o1*o1 + o2*o2 + o3*o3;
#pragma unroll
    for (int o = 16; o; o >>= 1) ss += __shfl_xor_sync(0xffffffffu, ss, o);
    float rr = rsqrtf(ss * (1.f / HDIM) + 1e-5f) * scale;
    o0 *= rr; o1 *= rr; o2 *= rr; o3 *= rr;

    hv.x = packh(__float2half_rn(o0), __float2half_rn(o1));
    hv.y = packh(__float2half_rn(o2), __float2half_rn(o3));
    *(uint2*)(buf + base) = hv;
}

// ================= transpose to fp16: in[K,N] fp32 -> [N,K] fp16 =================
__global__ __launch_bounds__(256) void transpose_h_kernel(
    const float* __restrict__ in, __half* __restrict__ hi, int K, int N)
{
    __shared__ float s[64][65];
    int r0 = blockIdx.y * 64, c0 = blockIdx.x * 64;
#pragma unroll
    for (int i = 0; i < 8; i++) {
        int idx = threadIdx.x + i * 256;
        int lr = idx >> 5, p = idx & 31;
        float2 v = *(const float2*)(in + (size_t)(r0 + lr) * N + c0 + 2 * p);
        s[lr][2 * p]     = v.x;
        s[lr][2 * p + 1] = v.y;
    }
    __syncthreads();
#pragma unroll
    for (int i = 0; i < 8; i++) {
        int idx = threadIdx.x + i * 256;
        int lr = idx >> 5, p = idx & 31;
        uint32_t hv = packh(__float2half_rn(s[2 * p][lr]), __float2half_rn(s[2 * p + 1][lr]));
        *(uint32_t*)(hi + (size_t)(c0 + lr) * K + (r0 + 2 * p)) = hv;
    }
}

// ================= HMMA GEMM: C = A(fp16) x B(fp16)^T, fp32 acc =================
// CTA 256x128, K-chunk 128, 2-stage ring (2 x 96KB). 8 warps in 4x2, 64x64 each.
#define TCG_STAGE_BYTES 98304
#define TCG_SMEM (2 * TCG_STAGE_BYTES)

__global__ __launch_bounds__(256, 1) void tc_gemm_kernel(
    const __half* __restrict__ A, const __half* __restrict__ B,
    float* __restrict__ C, const float* __restrict__ addend,
    __half* __restrict__ outH,
    const __half* __restrict__ gateMul,
    __half* __restrict__ qDest, __half* __restrict__ kDest, __half* __restrict__ vDest, int qkvMode,
    int M, int N, int K)
{
    extern __shared__ char sm[];
    uint32_t sbase = smem_u32(sm);
    int tid = threadIdx.x, lane = tid & 31, wid = tid >> 5;
    int warp_m = wid & 3, warp_n = wid >> 2;
    int by = blockIdx.x, bx = blockIdx.y;   // M-block fastest

    const __half* srcA = A + (size_t)(by * 256) * K;
    const __half* srcB = B + (size_t)(bx * 128) * K;

    int nchunk = K >> 7;

    auto load_stage = [&](int stg, int c) {
        uint32_t dst0 = sbase + stg * TCG_STAGE_BYTES;
        int kc = c << 7;
#pragma unroll
        for (int i = 0; i < 24; i++) {
            int u = i * 256 + tid;
            uint32_t dst; const __half* src;
            if (u < 4096) {
                int row = u >> 4, c16 = u & 15;
                dst = dst0 + row * 256 + ((c16 ^ (row & 7)) << 4);
                src = srcA + (size_t)row * K + kc + c16 * 8;
            } else {
                int w2 = u - 4096;
                int row = w2 >> 4, c16 = w2 & 15;
                dst = dst0 + 65536 + row * 256 + ((c16 ^ (row & 7)) << 4);
                src = srcB + (size_t)row * K + kc + c16 * 8;
            }
            cp_async16(dst, src);
        }
    };

    load_stage(0, 0); CP_COMMIT();

    float acc[4][8][4];
#pragma unroll
    for (int a = 0; a < 4; a++)
#pragma unroll
        for (int b = 0; b < 8; b++)
#pragma unroll
            for (int f = 0; f < 4; f++) acc[a][b][f] = 0.f;

    int a_r   = warp_m * 64 + (lane & 15);
    int a_kh  = lane >> 4;
    int b_r   = warp_n * 64 + (lane & 7) + ((lane >> 4) << 3);
    int b_kh  = (lane >> 3) & 1;

    for (int c = 0; c < nchunk; c++) {
        if (c + 1 < nchunk) { load_stage((c + 1) & 1, c + 1); CP_COMMIT(); CP_WAIT1(); }
        else                { CP_WAIT0(); }
        __syncthreads();

        uint32_t st = sbase + (c & 1) * TCG_STAGE_BYTES;
#pragma unroll
        for (int kk = 0; kk < 8; kk++) {
            int c16 = kk * 2;
            uint32_t ah[4][4], bh[4][4];
#pragma unroll
            for (int mb = 0; mb < 4; mb++) {
                int r = a_r + mb * 16;
                uint32_t off = r * 256 + (((c16 + a_kh) ^ (r & 7)) << 4);
                ldsm4(ah[mb], st + off);
            }
#pragma unroll
            for (int nb = 0; nb < 4; nb++) {
                int r = b_r + nb * 16;
                uint32_t off = r * 256 + (((c16 + b_kh) ^ (r & 7)) << 4);
                ldsm4(bh[nb], st + 65536 + off);
            }
#pragma unroll
            for (int mb = 0; mb < 4; mb++)
#pragma unroll
                for (int j = 0; j < 8; j++) {
                    uint32_t b0 = bh[j >> 1][(j & 1) * 2], b1 = bh[j >> 1][(j & 1) * 2 + 1];
                    mmaF32(acc[mb][j], ah[mb], b0, b1);
                }
        }
        __syncthreads();
    }

#pragma unroll
    for (int mb = 0; mb < 4; mb++) {
        int mrow = by * 256 + warp_m * 64 + mb * 16 + (lane >> 2);
#pragma unroll
        for (int j = 0; j < 8; j++) {
            int ncol = bx * 128 + warp_n * 64 + j * 8 + (lane & 3) * 2;
            float2 r0 = make_float2(acc[mb][j][0], acc[mb][j][1]);
            float2 r1 = make_float2(acc[mb][j][2], acc[mb][j][3]);

            if (qkvMode) {
                __half* dst; int cc; int stride;
                if (ncol < DMODEL) { dst = qDest; cc = ncol; stride = DMODEL; }
                else if (ncol < DMODEL + NKVH * HDIM) { dst = kDest; cc = ncol - DMODEL; stride = NKVH * HDIM; }
                else { dst = vDest; cc = ncol - DMODEL - NKVH * HDIM; stride = NKVH * HDIM; }
                size_t i0 = (size_t)mrow * stride + cc;
                size_t i1 = (size_t)(mrow + 8) * stride + cc;
                *(uint32_t*)(dst + i0) = packh(__float2half_rn(r0.x), __float2half_rn(r0.y));
                *(uint32_t*)(dst + i1) = packh(__float2half_rn(r1.x), __float2half_rn(r1.y));
                continue;
            }

            size_t i0 = (size_t)mrow * N + ncol;
            size_t i1 = (size_t)(mrow + 8) * N + ncol;
            if (addend) {
                float2 a0 = *(const float2*)(addend + i0);
                float2 a1 = *(const float2*)(addend + i1);
                r0.x += a0.x; r0.y += a0.y;
                r1.x += a1.x; r1.y += a1.y;
            }
            if (gateMul) {
                float2 g0 = __half22float2(*(const __half2*)(gateMul + i0));
                float2 g1 = __half22float2(*(const __half2*)(gateMul + i1));
                r0.x *= g0.x / (1.f + __expf(-g0.x));
                r0.y *= g0.y / (1.f + __expf(-g0.y));
                r1.x *= g1.x / (1.f + __expf(-g1.x));
                r1.y *= g1.y / (1.f + __expf(-g1.y));
            }
            if (C) {
                *(float2*)(C + i0) = r0;
                *(float2*)(C + i1) = r1;
            }
            if (outH) {
                *(uint32_t*)(outH + i0) = packh(__float2half_rn(r0.x), __float2half_rn(r0.y));
                *(uint32_t*)(outH + i1) = packh(__float2half_rn(r1.x), __float2half_rn(r1.y));
            }
        }
    }
}

// ================= HMMA causal flash attention: fp16 operands, fp32 acc =================
// LPT scheduling: heavy (large-qb) tiles launch first.
#define FA_STAGE_OFF 16384
#define FA_STAGE_BYTES 32768
#define FA_SMEM (FA_STAGE_OFF + 2 * FA_STAGE_BYTES)   // 80KB

__global__ __launch_bounds__(128, 2) void flash_attn_kernel(
    const __half* __restrict__ qh,
    const __half* __restrict__ kh, const __half* __restrict__ vh,
    __half* __restrict__ o)
{
    extern __shared__ char sm[];
    uint32_t sbase = smem_u32(sm);
    int qb = gridDim.x - 1 - blockIdx.x;   // heavy tiles first (LPT packing)
    int h = blockIdx.y, kvh = h >> 2;
    int tid = threadIdx.x, lane = tid & 31, w = tid >> 5;

#pragma unroll
    for (int i = 0; i < 8; i++) {
        int u = tid + i * 128;
        int row = u >> 4, c16 = u & 15;
        uint32_t dst = sbase + row * 256 + ((c16 ^ (row & 7)) << 4);
        cp_async16(dst, qh + (size_t)(qb * 64 + row) * DMODEL + h * HDIM + c16 * 8);
    }

    auto load_kv = [&](int stg, int kb) {
        uint32_t dst0 = sbase + FA_STAGE_OFF + stg * FA_STAGE_BYTES;
        const __half* srcs[2] = { kh, vh };
#pragma unroll
        for (int b = 0; b < 2; b++) {
            const __half* s = srcs[b];
#pragma unroll
            for (int i = 0; i < 8; i++) {
                int u = tid + i * 128;
                int row = u >> 4, c16 = u & 15;
                uint32_t dst = dst0 + b * 16384 + row * 256 + ((c16 ^ (row & 7)) << 4);
                cp_async16(dst, s + (size_t)(kb * 64 + row) * (NKVH * HDIM) + kvh * HDIM + c16 * 8);
            }
        }
    };

    load_kv(0, 0); CP_COMMIT();
    if (qb >= 1) load_kv(1, 1);
    CP_COMMIT();

    float O[16][4];
#pragma unroll
    for (int i = 0; i < 16; i++)
#pragma unroll
        for (int f = 0; f < 4; f++) O[i][f] = 0.f;
    float m_lo = -1e30f, m_hi = -1e30f, l_lo = 0.f, l_hi = 0.f;

    int r_loc = w * 16 + (lane >> 2);

    for (int kb = 0; kb <= qb; kb++) {
        CP_WAIT1();
        __syncthreads();
        uint32_t kbase = sbase + FA_STAGE_OFF + (kb & 1) * FA_STAGE_BYTES;

        float S[8][4];
#pragma unroll
        for (int i = 0; i < 8; i++)
#pragma unroll
            for (int f = 0; f < 4; f++) S[i][f] = 0.f;

#pragma unroll
        for (int kk = 0; kk < 8; kk++) {
            uint32_t aq[4];
            int ar = w * 16 + (lane & 15);
            int ac = kk * 2 + (lane >> 4);
            ldsm4(aq, sbase + ar * 256 + ((ac ^ (ar & 7)) << 4));
#pragma unroll
            for (int nblk = 0; nblk < 4; nblk++) {
                int br = nblk * 16 + (lane & 7) + ((lane >> 4) << 3);
                int bc = kk * 2 + ((lane >> 3) & 1);
                uint32_t boff = br * 256 + ((bc ^ (br & 7)) << 4);
                uint32_t bh4[4];
                ldsm4(bh4, kbase + boff);
                mmaF32(S[2*nblk],   aq, bh4[0], bh4[1]);
                mmaF32(S[2*nblk+1], aq, bh4[2], bh4[3]);
            }
        }

        if (kb == qb) {
#pragma unroll
            for (int nt = 0; nt < 8; nt++) {
                int c = nt * 8 + (lane & 3) * 2;
                if (c     > r_loc)     S[nt][0] = -1e30f;
                if (c + 1 > r_loc)     S[nt][1] = -1e30f;
                if (c     > r_loc + 8) S[nt][2] = -1e30f;
                if (c + 1 > r_loc + 8) S[nt][3] = -1e30f;
            }
        }

        float rm_lo = -1e30f, rm_hi = -1e30f;
#pragma unroll
        for (int nt = 0; nt < 8; nt++) {
            rm_lo = fmaxf(rm_lo, fmaxf(S[nt][0], S[nt][1]));
            rm_hi = fmaxf(rm_hi, fmaxf(S[nt][2], S[nt][3]));
        }
        rm_lo = fmaxf(rm_lo, __shfl_xor_sync(0xffffffffu, rm_lo, 1));
        rm_lo = fmaxf(rm_lo, __shfl_xor_sync(0xffffffffu, rm_lo, 2));
        rm_hi = fmaxf(rm_hi, __shfl_xor_sync(0xffffffffu, rm_hi, 1));
        rm_hi = fmaxf(rm_hi, __shfl_xor_sync(0xffffffffu, rm_hi, 2));
        float mn_lo = fmaxf(m_lo, rm_lo), mn_hi = fmaxf(m_hi, rm_hi);
        float corr_lo = __expf(m_lo - mn_lo), corr_hi = __expf(m_hi - mn_hi);

        uint32_t ph[8][2];
        float sum_lo = 0.f, sum_hi = 0.f;
#pragma unroll
        for (int nt = 0; nt < 8; nt++) {
            float p0 = __expf(S[nt][0] - mn_lo);
            float p1 = __expf(S[nt][1] - mn_lo);
            float p2 = __expf(S[nt][2] - mn_hi);
            float p3 = __expf(S[nt][3] - mn_hi);
            sum_lo += p0 + p1; sum_hi += p2 + p3;
            ph[nt][0] = packh(__float2half_rn(p0), __float2half_rn(p1));
            ph[nt][1] = packh(__float2half_rn(p2), __float2half_rn(p3));
        }
        sum_lo += __shfl_xor_sync(0xffffffffu, sum_lo, 1);
        sum_lo += __shfl_xor_sync(0xffffffffu, sum_lo, 2);
        sum_hi += __shfl_xor_sync(0xffffffffu, sum_hi, 1);
        sum_hi += __shfl_xor_sync(0xffffffffu, sum_hi, 2);
        l_lo = l_lo * corr_lo + sum_lo;
        l_hi = l_hi * corr_hi + sum_hi;
        m_lo = mn_lo; m_hi = mn_hi;
#pragma unroll
        for (int ot = 0; ot < 16; ot++) {
            O[ot][0] *= corr_lo; O[ot][1] *= corr_lo;
            O[ot][2] *= corr_hi; O[ot][3] *= corr_hi;
        }

        uint32_t vbase = kbase + 16384;
#pragma unroll
        for (int kt = 0; kt < 4; kt++) {
            uint32_t aH[4] = { ph[2*kt][0], ph[2*kt][1], ph[2*kt+1][0], ph[2*kt+1][1] };
            int krow = kt * 16 + (lane & 7) + ((lane >> 3) & 1) * 8;
#pragma unroll
            for (int ob = 0; ob < 8; ob++) {
                int cu = ob * 2 + (lane >> 4);
                uint32_t off = krow * 256 + ((cu ^ (krow & 7)) << 4);
                uint32_t bvh[4];
                ldsm4t(bvh, vbase + off);
                mmaF32(O[2*ob],   aH, bvh[0], bvh[1]);
                mmaF32(O[2*ob+1], aH, bvh[2], bvh[3]);
            }
        }

        __syncthreads();
        if (kb + 2 <= qb) load_kv(kb & 1, kb + 2);
        CP_COMMIT();
    }

    float il_lo = 1.f / l_lo, il_hi = 1.f / l_hi;
    int row0 = qb * 64 + r_loc;
#pragma unroll
    for (int ot = 0; ot < 16; ot++) {
        int col = h * HDIM + ot * 8 + (lane & 3) * 2;
        size_t i0 = (size_t)row0 * DMODEL + col;
        size_t i1 = (size_t)(row0 + 8) * DMODEL + col;
        *(uint32_t*)(o + i0) = packh(__float2half_rn(O[ot][0] * il_lo), __float2half_rn(O[ot][1] * il_lo));
        *(uint32_t*)(o + i1) = packh(__float2half_rn(O[ot][2] * il_hi), __float2half_rn(O[ot][3] * il_hi));
    }
}

// ================= host launcher =================
extern "C" void kernel_launch(void* const* d_in, const int* in_sizes, int n_in,
                              void* d_out, int out_size)
{
    const float* hidden = (const float*)d_in[0];
    const float* cosb  = (const float*)d_in[2];
    const float* sinb  = (const float*)d_in[3];
    const float* ln1   = (const float*)d_in[4];
    const float* wq    = (const float*)d_in[5];
    const float* wk    = (const float*)d_in[6];
    const float* wv    = (const float*)d_in[7];
    const float* wo    = (const float*)d_in[8];
    const float* ln2   = (const float*)d_in[9];
    const float* gatew = (const float*)d_in[10];
    const float* upw   = (const float*)d_in[11];
    const float* downw = (const float*)d_in[12];
    float* out = (float*)d_out;

    float* h;
    cudaGetSymbolAddress((void**)&h, g_h);

    __half *qkvT,*woT,*gwT,*uwT,*dwT;
    cudaGetSymbolAddress((void**)&qkvT, g_wqkvT);
    cudaGetSymbolAddress((void**)&woT, g_woT);
    cudaGetSymbolAddress((void**)&gwT, g_gwT);
    cudaGetSymbolAddress((void**)&uwT, g_uwT);
    cudaGetSymbolAddress((void**)&dwT, g_dwT);

    __half *xn,*at,*x2,*ga,*gateH,*qhp,*khp,*vhp;
    cudaGetSymbolAddress((void**)&xn, g_xn);
    cudaGetSymbolAddress((void**)&at, g_at);
    cudaGetSymbolAddress((void**)&x2, g_x2);
    cudaGetSymbolAddress((void**)&ga, g_ga);
    cudaGetSymbolAddress((void**)&gateH, g_gate);
    cudaGetSymbolAddress((void**)&qhp, g_qh);
    cudaGetSymbolAddress((void**)&khp, g_kh);
    cudaGetSymbolAddress((void**)&vhp, g_vh);

    cudaFuncSetAttribute(tc_gemm_kernel, cudaFuncAttributeMaxDynamicSharedMemorySize, TCG_SMEM);
    cudaFuncSetAttribute(flash_attn_kernel, cudaFuncAttributeMaxDynamicSharedMemorySize, FA_SMEM);

    static cudaStream_t s2 = nullptr;
    static cudaEvent_t evFork = nullptr, evNorm = nullptr, evJoin = nullptr;
    if (!s2) {
        cudaStreamCreateWithFlags(&s2, cudaStreamNonBlocking);
        cudaEventCreateWithFlags(&evFork, cudaEventDisableTiming);
        cudaEventCreateWithFlags(&evNorm, cudaEventDisableTiming);
        cudaEventCreateWithFlags(&evJoin, cudaEventDisableTiming);
    }

    // ---- fork: rmsnorm1 + FFN-weight transposes on side stream ----
    cudaEventRecord(evFork, 0);
    cudaStreamWaitEvent(s2, evFork, 0);
    rmsnorm_h_kernel<<<S_LEN, 256, 0, s2>>>(hidden, ln1, xn);
    cudaEventRecord(evNorm, s2);
    transpose_h_kernel<<<dim3(DMODEL/64, DMODEL/64), 256, 0, s2>>>(wo, woT, DMODEL, DMODEL);
    transpose_h_kernel<<<dim3(DFFN/64, DMODEL/64), 256, 0, s2>>>(gatew, gwT, DMODEL, DFFN);
    transpose_h_kernel<<<dim3(DFFN/64, DMODEL/64), 256, 0, s2>>>(upw, uwT, DMODEL, DFFN);
    transpose_h_kernel<<<dim3(DMODEL/64, DFFN/64), 256, 0, s2>>>(downw, dwT, DFFN, DMODEL);
    cudaEventRecord(evJoin, s2);

    // ---- main: QKV weight transposes (parallel to rmsnorm) ----
    transpose_h_kernel<<<dim3(DMODEL/64, DMODEL/64), 256>>>(wq, qkvT, DMODEL, DMODEL);
    transpose_h_kernel<<<dim3(NKVH*HDIM/64, DMODEL/64), 256>>>(wk, qkvT + (size_t)DMODEL*DMODEL, DMODEL, NKVH*HDIM);
    transpose_h_kernel<<<dim3(NKVH*HDIM/64, DMODEL/64), 256>>>(wv, qkvT + (size_t)(DMODEL+NKVH*HDIM)*DMODEL, DMODEL, NKVH*HDIM);
    cudaStreamWaitEvent(0, evNorm, 0);

    // ---- main chain: QKV (fp16 out) -> rope in-place -> attention ----
    tc_gemm_kernel<<<dim3(S_LEN/256, NQKV/128), 256, TCG_SMEM>>>(
        xn, qkvT, nullptr, nullptr, nullptr, nullptr, qhp, khp, vhp, 1, S_LEN, NQKV, DMODEL);

    const float qscale = 0.08838834764831845f;
    rope_l2_h_kernel<<<S_LEN * NHEADS / 8, 256>>>(qhp, NHEADS, cosb, sinb, qscale);
    rope_l2_h_kernel<<<S_LEN * NKVH  / 8, 256>>>(khp, NKVH,  cosb, sinb, 1.f);

    flash_attn_kernel<<<dim3(S_LEN / 64, NHEADS), 128, FA_SMEM>>>(qhp, khp, vhp, at);

    // ---- join: weight prep must be done before wo GEMM ----
    cudaStreamWaitEvent(0, evJoin, 0);

    tc_gemm_kernel<<<dim3(S_LEN/256, DMODEL/128), 256, TCG_SMEM>>>(
        at, woT, h, hidden, nullptr, nullptr, nullptr, nullptr, nullptr, 0, S_LEN, DMODEL, DMODEL);

    rmsnorm_h_kernel<<<S_LEN, 256>>>(h, ln2, x2);

    tc_gemm_kernel<<<dim3(S_LEN/256, DFFN/128), 256, TCG_SMEM>>>(
        x2, gwT, nullptr, nullptr, gateH, nullptr, nullptr, nullptr, nullptr, 0, S_LEN, DFFN, DMODEL);
    tc_gemm_kernel<<<dim3(S_LEN/256, DFFN/128), 256, TCG_SMEM>>>(
        x2, uwT, nullptr, nullptr, ga, gateH, nullptr, nullptr, nullptr, 0, S_LEN, DFFN, DMODEL);

    tc_gemm_kernel<<<dim3(S_LEN/256, DMODEL/128), 256, TCG_SMEM>>>(
        ga, dwT, out, h, nullptr, nullptr, nullptr, nullptr, nullptr, 0, S_LEN, DMODEL, DFFN);
}

// round 17
// speedup vs baseline: 2.8742x; 1.0286x over previous
#include <cuda_runtime.h>
#include <cuda_fp16.h>
#include <math.h>
#include <stdint.h>

#define S_LEN  2048
#define DMODEL 4096
#define NHEADS 32
#define NKVH   8
#define HDIM   128
#define DFFN   16384

// ================= low-level helpers =================
__device__ __forceinline__ uint32_t smem_u32(const void* p) {
    uint32_t a;
    asm("{ .reg .u64 t; cvta.to.shared.u64 t, %1; cvt.u32.u64 %0, t; }" : "=r"(a) : "l"(p));
    return a;
}
__device__ __forceinline__ void cp_async16(uint32_t dst, const void* src) {
    asm volatile("cp.async.cg.shared.global [%0], [%1], 16;" :: "r"(dst), "l"(src));
}
#define CP_COMMIT() asm volatile("cp.async.commit_group;" ::: "memory")
#define CP_WAIT0()  asm volatile("cp.async.wait_group 0;" ::: "memory")
#define CP_WAIT1()  asm volatile("cp.async.wait_group 1;" ::: "memory")

__device__ __forceinline__ void ldsm4(uint32_t* r, uint32_t addr) {
    asm volatile("ldmatrix.sync.aligned.m8n8.x4.shared.b16 {%0,%1,%2,%3}, [%4];"
        : "=r"(r[0]), "=r"(r[1]), "=r"(r[2]), "=r"(r[3]) : "r"(addr));
}
__device__ __forceinline__ void ldsm4t(uint32_t* r, uint32_t addr) {
    asm volatile("ldmatrix.sync.aligned.m8n8.x4.trans.shared.b16 {%0,%1,%2,%3}, [%4];"
        : "=r"(r[0]), "=r"(r[1]), "=r"(r[2]), "=r"(r[3]) : "r"(addr));
}
__device__ __forceinline__ void mmaF32(float* d, const uint32_t* a, uint32_t b0, uint32_t b1) {
    asm volatile("mma.sync.aligned.m16n8k16.row.col.f32.f16.f16.f32 "
        "{%0,%1,%2,%3}, {%4,%5,%6,%7}, {%8,%9}, {%0,%1,%2,%3};"
        : "+f"(d[0]), "+f"(d[1]), "+f"(d[2]), "+f"(d[3])
        : "r"(a[0]), "r"(a[1]), "r"(a[2]), "r"(a[3]), "r"(b0), "r"(b1));
}

__device__ __forceinline__ uint32_t packh(__half a, __half b) {
    __half2 t = __halves2half2(a, b);
    return *(uint32_t*)&t;
}

// ================= scratch =================
__device__ float g_h [S_LEN * DMODEL];

#define NQKV (DMODEL + 2 * NKVH * HDIM)
__device__ __half g_wqkvT[NQKV * DMODEL];
__device__ __half g_woT[DMODEL * DMODEL];
__device__ __half g_fwT[2 * DFFN * DMODEL];    // interleaved gate/up: row 2j = gate_j, 2j+1 = up_j
__device__ __half g_dwT[DMODEL * DFFN];

__device__ __half g_xn[S_LEN * DMODEL];
__device__ __half g_at[S_LEN * DMODEL];
__device__ __half g_x2[S_LEN * DMODEL];
__device__ __half g_ga[S_LEN * DFFN];

// attention operands: single fp16; QKV GEMM writes raw, rope runs in-place on q/k
__device__ __half g_qh[S_LEN * DMODEL];
__device__ __half g_kh[S_LEN * NKVH * HDIM];
__device__ __half g_vh[S_LEN * NKVH * HDIM];

// ================= RMSNorm -> single fp16 =================
__global__ __launch_bounds__(256) void rmsnorm_h_kernel(
    const float* __restrict__ x, const float* __restrict__ w, __half* __restrict__ y)
{
    int row = blockIdx.x;
    const float* xr = x + (size_t)row * DMODEL;

    float4 vals[4];
    float ss = 0.f;
#pragma unroll
    for (int it = 0; it < 4; it++) {
        int idx = (threadIdx.x + it * 256) * 4;
        float4 v = *(const float4*)(xr + idx);
        vals[it] = v;
        ss += v.x*v.x + v.y*v.y + v.z*v.z + v.w*v.w;
    }
#pragma unroll
    for (int o = 16; o; o >>= 1) ss += __shfl_xor_sync(0xffffffffu, ss, o);

    __shared__ float red[8];
    if ((threadIdx.x & 31) == 0) red[threadIdx.x >> 5] = ss;
    __syncthreads();
    float tot = 0.f;
#pragma unroll
    for (int i = 0; i < 8; i++) tot += red[i];
    float inv = rsqrtf(tot * (1.f / DMODEL) + 1e-5f);

#pragma unroll
    for (int it = 0; it < 4; it++) {
        int idx = (threadIdx.x + it * 256) * 4;
        float4 v  = vals[it];
        float4 wv = *(const float4*)(w + idx);
        uint2 hv;
        hv.x = packh(__float2half_rn(v.x * inv * wv.x), __float2half_rn(v.y * inv * wv.y));
        hv.y = packh(__float2half_rn(v.z * inv * wv.z), __float2half_rn(v.w * inv * wv.w));
        *(uint2*)(y + (size_t)row * DMODEL + idx) = hv;
    }
}

// ================= RoPE + L2-norm, in-place on fp16 buffer =================
__global__ __launch_bounds__(256) void rope_l2_h_kernel(
    __half* __restrict__ buf, int nheads,
    const float* __restrict__ cosb, const float* __restrict__ sinb, float scale)
{
    int wid  = (blockIdx.x * 256 + threadIdx.x) >> 5;
    int lane = threadIdx.x & 31;
    int s  = wid / nheads;
    int hh = wid % nheads;
    size_t base = (size_t)s * nheads * HDIM + hh * HDIM + lane * 4;
    uint2 hv = *(uint2*)(buf + base);
    float2 v01 = __half22float2(*(__half2*)&hv.x);
    float2 v23 = __half22float2(*(__half2*)&hv.y);

    float c0 = cosb[s * 64 + lane * 2],     s0 = sinb[s * 64 + lane * 2];
    float c1 = cosb[s * 64 + lane * 2 + 1], s1 = sinb[s * 64 + lane * 2 + 1];
    float o0 = v01.x * c0 - v01.y * s0;
    float o1 = v01.x * s0 + v01.y * c0;
    float o2 = v23.x * c1 - v23.y * s1;
    float o3 = v23.x * s1 + v23.y * c1;

    float ss = o0*o0 + o1*o1 + o2*o2 + o3*o3;
#pragma unroll
    for (int o = 16; o; o >>= 1) ss += __shfl_xor_sync(0xffffffffu, ss, o);
    float rr = rsqrtf(ss * (1.f / HDIM) + 1e-5f) * scale;
    o0 *= rr; o1 *= rr; o2 *= rr; o3 *= rr;

    hv.x = packh(__float2half_rn(o0), __float2half_rn(o1));
    hv.y = packh(__float2half_rn(o2), __float2half_rn(o3));
    *(uint2*)(buf + base) = hv;
}

// ================= transpose to fp16: in[K,N] fp32 -> fp16 rows (c0+lr)*rowMul+rowAdd =================
__global__ __launch_bounds__(256) void transpose_h_kernel(
    const float* __restrict__ in, __half* __restrict__ hi, int K, int N,
    int rowMul, int rowAdd)
{
    __shared__ float s[64][65];
    int r0 = blockIdx.y * 64, c0 = blockIdx.x * 64;
#pragma unroll
    for (int i = 0; i < 8; i++) {
        int idx = threadIdx.x + i * 256;
        int lr = idx >> 5, p = idx & 31;
        float2 v = *(const float2*)(in + (size_t)(r0 + lr) * N + c0 + 2 * p);
        s[lr][2 * p]     = v.x;
        s[lr][2 * p + 1] = v.y;
    }
    __syncthreads();
#pragma unroll
    for (int i = 0; i < 8; i++) {
        int idx = threadIdx.x + i * 256;
        int lr = idx >> 5, p = idx & 31;
        uint32_t hv = packh(__float2half_rn(s[2 * p][lr]), __float2half_rn(s[2 * p + 1][lr]));
        size_t orow = (size_t)(c0 + lr) * rowMul + rowAdd;
        *(uint32_t*)(hi + orow * K + (r0 + 2 * p)) = hv;
    }
}

// ================= HMMA GEMM: C = A(fp16) x B(fp16)^T, fp32 acc =================
// CTA 256x128, K-chunk 128, 2-stage ring. 8 warps in 4x2, 64x64 each.
// Modes: fp32 C (+addend), fp16 outH, qkv-routed, fused-swiglu (interleaved gate/up -> fusedOut).
#define TCG_STAGE_BYTES 98304
#define TCG_SMEM (2 * TCG_STAGE_BYTES)

__global__ __launch_bounds__(256, 1) void tc_gemm_kernel(
    const __half* __restrict__ A, const __half* __restrict__ B,
    float* __restrict__ C, const float* __restrict__ addend,
    __half* __restrict__ outH,
    __half* __restrict__ fusedOut,
    __half* __restrict__ qDest, __half* __restrict__ kDest, __half* __restrict__ vDest, int qkvMode,
    int M, int N, int K)
{
    extern __shared__ char sm[];
    uint32_t sbase = smem_u32(sm);
    int tid = threadIdx.x, lane = tid & 31, wid = tid >> 5;
    int warp_m = wid & 3, warp_n = wid >> 2;
    int by = blockIdx.x, bx = blockIdx.y;   // M-block fastest

    const __half* srcA = A + (size_t)(by * 256) * K;
    const __half* srcB = B + (size_t)(bx * 128) * K;

    int nchunk = K >> 7;

    auto load_stage = [&](int stg, int c) {
        uint32_t dst0 = sbase + stg * TCG_STAGE_BYTES;
        int kc = c << 7;
#pragma unroll
        for (int i = 0; i < 24; i++) {
            int u = i * 256 + tid;
            uint32_t dst; const __half* src;
            if (u < 4096) {
                int row = u >> 4, c16 = u & 15;
                dst = dst0 + row * 256 + ((c16 ^ (row & 7)) << 4);
                src = srcA + (size_t)row * K + kc + c16 * 8;
            } else {
                int w2 = u - 4096;
                int row = w2 >> 4, c16 = w2 & 15;
                dst = dst0 + 65536 + row * 256 + ((c16 ^ (row & 7)) << 4);
                src = srcB + (size_t)row * K + kc + c16 * 8;
            }
            cp_async16(dst, src);
        }
    };

    load_stage(0, 0); CP_COMMIT();

    float acc[4][8][4];
#pragma unroll
    for (int a = 0; a < 4; a++)
#pragma unroll
        for (int b = 0; b < 8; b++)
#pragma unroll
            for (int f = 0; f < 4; f++) acc[a][b][f] = 0.f;

    int a_r   = warp_m * 64 + (lane & 15);
    int a_kh  = lane >> 4;
    int b_r   = warp_n * 64 + (lane & 7) + ((lane >> 4) << 3);
    int b_kh  = (lane >> 3) & 1;

    for (int c = 0; c < nchunk; c++) {
        if (c + 1 < nchunk) { load_stage((c + 1) & 1, c + 1); CP_COMMIT(); CP_WAIT1(); }
        else                { CP_WAIT0(); }
        __syncthreads();

        uint32_t st = sbase + (c & 1) * TCG_STAGE_BYTES;
#pragma unroll
        for (int kk = 0; kk < 8; kk++) {
            int c16 = kk * 2;
            uint32_t ah[4][4], bh[4][4];
#pragma unroll
            for (int mb = 0; mb < 4; mb++) {
                int r = a_r + mb * 16;
                uint32_t off = r * 256 + (((c16 + a_kh) ^ (r & 7)) << 4);
                ldsm4(ah[mb], st + off);
            }
#pragma unroll
            for (int nb = 0; nb < 4; nb++) {
                int r = b_r + nb * 16;
                uint32_t off = r * 256 + (((c16 + b_kh) ^ (r & 7)) << 4);
                ldsm4(bh[nb], st + 65536 + off);
            }
#pragma unroll
            for (int mb = 0; mb < 4; mb++)
#pragma unroll
                for (int j = 0; j < 8; j++) {
                    uint32_t b0 = bh[j >> 1][(j & 1) * 2], b1 = bh[j >> 1][(j & 1) * 2 + 1];
                    mmaF32(acc[mb][j], ah[mb], b0, b1);
                }
        }
        __syncthreads();
    }

#pragma unroll
    for (int mb = 0; mb < 4; mb++) {
        int mrow = by * 256 + warp_m * 64 + mb * 16 + (lane >> 2);
#pragma unroll
        for (int j = 0; j < 8; j++) {
            int ncol = bx * 128 + warp_n * 64 + j * 8 + (lane & 3) * 2;
            float2 r0 = make_float2(acc[mb][j][0], acc[mb][j][1]);
            float2 r1 = make_float2(acc[mb][j][2], acc[mb][j][3]);

            if (fusedOut) {
                // interleaved gate/up: r.x = gate, r.y = up for output col ncol/2
                int oc = ncol >> 1;
                float a0 = r0.x / (1.f + __expf(-r0.x)) * r0.y;
                float a1 = r1.x / (1.f + __expf(-r1.x)) * r1.y;
                fusedOut[(size_t)mrow * DFFN + oc]       = __float2half_rn(a0);
                fusedOut[(size_t)(mrow + 8) * DFFN + oc] = __float2half_rn(a1);
                continue;
            }

            if (qkvMode) {
                __half* dst; int cc; int stride;
                if (ncol < DMODEL) { dst = qDest; cc = ncol; stride = DMODEL; }
                else if (ncol < DMODEL + NKVH * HDIM) { dst = kDest; cc = ncol - DMODEL; stride = NKVH * HDIM; }
                else { dst = vDest; cc = ncol - DMODEL - NKVH * HDIM; stride = NKVH * HDIM; }
                size_t i0 = (size_t)mrow * stride + cc;
                size_t i1 = (size_t)(mrow + 8) * stride + cc;
                *(uint32_t*)(dst + i0) = packh(__float2half_rn(r0.x), __float2half_rn(r0.y));
                *(uint32_t*)(dst + i1) = packh(__float2half_rn(r1.x), __float2half_rn(r1.y));
                continue;
            }

            size_t i0 = (size_t)mrow * N + ncol;
            size_t i1 = (size_t)(mrow + 8) * N + ncol;
            if (addend) {
                float2 a0 = *(const float2*)(addend + i0);
                float2 a1 = *(const float2*)(addend + i1);
                r0.x += a0.x; r0.y += a0.y;
                r1.x += a1.x; r1.y += a1.y;
            }
            if (C) {
                *(float2*)(C + i0) = r0;
                *(float2*)(C + i1) = r1;
            }
            if (outH) {
                *(uint32_t*)(outH + i0) = packh(__float2half_rn(r0.x), __float2half_rn(r0.y));
                *(uint32_t*)(outH + i1) = packh(__float2half_rn(r1.x), __float2half_rn(r1.y));
            }
        }
    }
}

// ================= HMMA causal flash attention: fp16 operands, fp32 acc =================
// LPT scheduling: heavy (large-qb) tiles launch first.
#define FA_STAGE_OFF 16384
#define FA_STAGE_BYTES 32768
#define FA_SMEM (FA_STAGE_OFF + 2 * FA_STAGE_BYTES)   // 80KB

__global__ __launch_bounds__(128, 2) void flash_attn_kernel(
    const __half* __restrict__ qh,
    const __half* __restrict__ kh, const __half* __restrict__ vh,
    __half* __restrict__ o)
{
    extern __shared__ char sm[];
    uint32_t sbase = smem_u32(sm);
    int qb = gridDim.x - 1 - blockIdx.x;
    int h = blockIdx.y, kvh = h >> 2;
    int tid = threadIdx.x, lane = tid & 31, w = tid >> 5;

#pragma unroll
    for (int i = 0; i < 8; i++) {
        int u = tid + i * 128;
        int row = u >> 4, c16 = u & 15;
        uint32_t dst = sbase + row * 256 + ((c16 ^ (row & 7)) << 4);
        cp_async16(dst, qh + (size_t)(qb * 64 + row) * DMODEL + h * HDIM + c16 * 8);
    }

    auto load_kv = [&](int stg, int kb) {
        uint32_t dst0 = sbase + FA_STAGE_OFF + stg * FA_STAGE_BYTES;
        const __half* srcs[2] = { kh, vh };
#pragma unroll
        for (int b = 0; b < 2; b++) {
            const __half* s = srcs[b];
#pragma unroll
            for (int i = 0; i < 8; i++) {
                int u = tid + i * 128;
                int row = u >> 4, c16 = u & 15;
                uint32_t dst = dst0 + b * 16384 + row * 256 + ((c16 ^ (row & 7)) << 4);
                cp_async16(dst, s + (size_t)(kb * 64 + row) * (NKVH * HDIM) + kvh * HDIM + c16 * 8);
            }
        }
    };

    load_kv(0, 0); CP_COMMIT();
    if (qb >= 1) load_kv(1, 1);
    CP_COMMIT();

    float O[16][4];
#pragma unroll
    for (int i = 0; i < 16; i++)
#pragma unroll
        for (int f = 0; f < 4; f++) O[i][f] = 0.f;
    float m_lo = -1e30f, m_hi = -1e30f, l_lo = 0.f, l_hi = 0.f;

    int r_loc = w * 16 + (lane >> 2);

    for (int kb = 0; kb <= qb; kb++) {
        CP_WAIT1();
        __syncthreads();
        uint32_t kbase = sbase + FA_STAGE_OFF + (kb & 1) * FA_STAGE_BYTES;

        float S[8][4];
#pragma unroll
        for (int i = 0; i < 8; i++)
#pragma unroll
            for (int f = 0; f < 4; f++) S[i][f] = 0.f;

#pragma unroll
        for (int kk = 0; kk < 8; kk++) {
            uint32_t aq[4];
            int ar = w * 16 + (lane & 15);
            int ac = kk * 2 + (lane >> 4);
            ldsm4(aq, sbase + ar * 256 + ((ac ^ (ar & 7)) << 4));
#pragma unroll
            for (int nblk = 0; nblk < 4; nblk++) {
                int br = nblk * 16 + (lane & 7) + ((lane >> 4) << 3);
                int bc = kk * 2 + ((lane >> 3) & 1);
                uint32_t boff = br * 256 + ((bc ^ (br & 7)) << 4);
                uint32_t bh4[4];
                ldsm4(bh4, kbase + boff);
                mmaF32(S[2*nblk],   aq, bh4[0], bh4[1]);
                mmaF32(S[2*nblk+1], aq, bh4[2], bh4[3]);
            }
        }

        if (kb == qb) {
#pragma unroll
            for (int nt = 0; nt < 8; nt++) {
                int c = nt * 8 + (lane & 3) * 2;
                if (c     > r_loc)     S[nt][0] = -1e30f;
                if (c + 1 > r_loc)     S[nt][1] = -1e30f;
                if (c     > r_loc + 8) S[nt][2] = -1e30f;
                if (c + 1 > r_loc + 8) S[nt][3] = -1e30f;
            }
        }

        float rm_lo = -1e30f, rm_hi = -1e30f;
#pragma unroll
        for (int nt = 0; nt < 8; nt++) {
            rm_lo = fmaxf(rm_lo, fmaxf(S[nt][0], S[nt][1]));
            rm_hi = fmaxf(rm_hi, fmaxf(S[nt][2], S[nt][3]));
        }
        rm_lo = fmaxf(rm_lo, __shfl_xor_sync(0xffffffffu, rm_lo, 1));
        rm_lo = fmaxf(rm_lo, __shfl_xor_sync(0xffffffffu, rm_lo, 2));
        rm_hi = fmaxf(rm_hi, __shfl_xor_sync(0xffffffffu, rm_hi, 1));
        rm_hi = fmaxf(rm_hi, __shfl_xor_sync(0xffffffffu, rm_hi, 2));
        float mn_lo = fmaxf(m_lo, rm_lo), mn_hi = fmaxf(m_hi, rm_hi);
        float corr_lo = __expf(m_lo - mn_lo), corr_hi = __expf(m_hi - mn_hi);

        uint32_t ph[8][2];
        float sum_lo = 0.f, sum_hi = 0.f;
#pragma unroll
        for (int nt = 0; nt < 8; nt++) {
            float p0 = __expf(S[nt][0] - mn_lo);
            float p1 = __expf(S[nt][1] - mn_lo);
            float p2 = __expf(S[nt][2] - mn_hi);
            float p3 = __expf(S[nt][3] - mn_hi);
            sum_lo += p0 + p1; sum_hi += p2 + p3;
            ph[nt][0] = packh(__float2half_rn(p0), __float2half_rn(p1));
            ph[nt][1] = packh(__float2half_rn(p2), __float2half_rn(p3));
        }
        sum_lo += __shfl_xor_sync(0xffffffffu, sum_lo, 1);
        sum_lo += __shfl_xor_sync(0xffffffffu, sum_lo, 2);
        sum_hi += __shfl_xor_sync(0xffffffffu, sum_hi, 1);
        sum_hi += __shfl_xor_sync(0xffffffffu, sum_hi, 2);
        l_lo = l_lo * corr_lo + sum_lo;
        l_hi = l_hi * corr_hi + sum_hi;
        m_lo = mn_lo; m_hi = mn_hi;
#pragma unroll
        for (int ot = 0; ot < 16; ot++) {
            O[ot][0] *= corr_lo; O[ot][1] *= corr_lo;
            O[ot][2] *= corr_hi; O[ot][3] *= corr_hi;
        }

        uint32_t vbase = kbase + 16384;
#pragma unroll
        for (int kt = 0; kt < 4; kt++) {
            uint32_t aH[4] = { ph[2*kt][0], ph[2*kt][1], ph[2*kt+1][0], ph[2*kt+1][1] };
            int krow = kt * 16 + (lane & 7) + ((lane >> 3) & 1) * 8;
#pragma unroll
            for (int ob = 0; ob < 8; ob++) {
                int cu = ob * 2 + (lane >> 4);
                uint32_t off = krow * 256 + ((cu ^ (krow & 7)) << 4);
                uint32_t bvh[4];
                ldsm4t(bvh, vbase + off);
                mmaF32(O[2*ob],   aH, bvh[0], bvh[1]);
                mmaF32(O[2*ob+1], aH, bvh[2], bvh[3]);
            }
        }

        __syncthreads();
        if (kb + 2 <= qb) load_kv(kb & 1, kb + 2);
        CP_COMMIT();
    }

    float il_lo = 1.f / l_lo, il_hi = 1.f / l_hi;
    int row0 = qb * 64 + r_loc;
#pragma unroll
    for (int ot = 0; ot < 16; ot++) {
        int col = h * HDIM + ot * 8 + (lane & 3) * 2;
        size_t i0 = (size_t)row0 * DMODEL + col;
        size_t i1 = (size_t)(row0 + 8) * DMODEL + col;
        *(uint32_t*)(o + i0) = packh(__float2half_rn(O[ot][0] * il_lo), __float2half_rn(O[ot][1] * il_lo));
        *(uint32_t*)(o + i1) = packh(__float2half_rn(O[ot][2] * il_hi), __float2half_rn(O[ot][3] * il_hi));
    }
}

// ================= host launcher =================
extern "C" void kernel_launch(void* const* d_in, const int* in_sizes, int n_in,
                              void* d_out, int out_size)
{
    const float* hidden = (const float*)d_in[0];
    const float* cosb  = (const float*)d_in[2];
    const float* sinb  = (const float*)d_in[3];
    const float* ln1   = (const float*)d_in[4];
    const float* wq    = (const float*)d_in[5];
    const float* wk    = (const float*)d_in[6];
    const float* wv    = (const float*)d_in[7];
    const float* wo    = (const float*)d_in[8];
    const float* ln2   = (const float*)d_in[9];
    const float* gatew = (const float*)d_in[10];
    const float* upw   = (const float*)d_in[11];
    const float* downw = (const float*)d_in[12];
    float* out = (float*)d_out;

    float* h;
    cudaGetSymbolAddress((void**)&h, g_h);

    __half *qkvT,*woT,*fwT,*dwT;
    cudaGetSymbolAddress((void**)&qkvT, g_wqkvT);
    cudaGetSymbolAddress((void**)&woT, g_woT);
    cudaGetSymbolAddress((void**)&fwT, g_fwT);
    cudaGetSymbolAddress((void**)&dwT, g_dwT);

    __half *xn,*at,*x2,*ga,*qhp,*khp,*vhp;
    cudaGetSymbolAddress((void**)&xn, g_xn);
    cudaGetSymbolAddress((void**)&at, g_at);
    cudaGetSymbolAddress((void**)&x2, g_x2);
    cudaGetSymbolAddress((void**)&ga, g_ga);
    cudaGetSymbolAddress((void**)&qhp, g_qh);
    cudaGetSymbolAddress((void**)&khp, g_kh);
    cudaGetSymbolAddress((void**)&vhp, g_vh);

    cudaFuncSetAttribute(tc_gemm_kernel, cudaFuncAttributeMaxDynamicSharedMemorySize, TCG_SMEM);
    cudaFuncSetAttribute(flash_attn_kernel, cudaFuncAttributeMaxDynamicSharedMemorySize, FA_SMEM);

    static cudaStream_t s2 = nullptr;
    static cudaEvent_t evFork = nullptr, evNorm = nullptr, evJoin = nullptr;
    if (!s2) {
        cudaStreamCreateWithFlags(&s2, cudaStreamNonBlocking);
        cudaEventCreateWithFlags(&evFork, cudaEventDisableTiming);
        cudaEventCreateWithFlags(&evNorm, cudaEventDisableTiming);
        cudaEventCreateWithFlags(&evJoin, cudaEventDisableTiming);
    }

    // ---- fork: rmsnorm1 + FFN-weight transposes on side stream ----
    cudaEventRecord(evFork, 0);
    cudaStreamWaitEvent(s2, evFork, 0);
    rmsnorm_h_kernel<<<S_LEN, 256, 0, s2>>>(hidden, ln1, xn);
    cudaEventRecord(evNorm, s2);
    transpose_h_kernel<<<dim3(DMODEL/64, DMODEL/64), 256, 0, s2>>>(wo, woT, DMODEL, DMODEL, 1, 0);
    transpose_h_kernel<<<dim3(DFFN/64, DMODEL/64), 256, 0, s2>>>(gatew, fwT, DMODEL, DFFN, 2, 0);
    transpose_h_kernel<<<dim3(DFFN/64, DMODEL/64), 256, 0, s2>>>(upw, fwT, DMODEL, DFFN, 2, 1);
    transpose_h_kernel<<<dim3(DMODEL/64, DFFN/64), 256, 0, s2>>>(downw, dwT, DFFN, DMODEL, 1, 0);
    cudaEventRecord(evJoin, s2);

    // ---- main: QKV weight transposes (parallel to rmsnorm) ----
    transpose_h_kernel<<<dim3(DMODEL/64, DMODEL/64), 256>>>(wq, qkvT, DMODEL, DMODEL, 1, 0);
    transpose_h_kernel<<<dim3(NKVH*HDIM/64, DMODEL/64), 256>>>(wk, qkvT + (size_t)DMODEL*DMODEL, DMODEL, NKVH*HDIM, 1, 0);
    transpose_h_kernel<<<dim3(NKVH*HDIM/64, DMODEL/64), 256>>>(wv, qkvT + (size_t)(DMODEL+NKVH*HDIM)*DMODEL, DMODEL, NKVH*HDIM, 1, 0);
    cudaStreamWaitEvent(0, evNorm, 0);

    // ---- main chain: QKV (fp16 out) -> rope in-place -> attention ----
    tc_gemm_kernel<<<dim3(S_LEN/256, NQKV/128), 256, TCG_SMEM>>>(
        xn, qkvT, nullptr, nullptr, nullptr, nullptr, qhp, khp, vhp, 1, S_LEN, NQKV, DMODEL);

    const float qscale = 0.08838834764831845f;
    rope_l2_h_kernel<<<S_LEN * NHEADS / 8, 256>>>(qhp, NHEADS, cosb, sinb, qscale);
    rope_l2_h_kernel<<<S_LEN * NKVH  / 8, 256>>>(khp, NKVH,  cosb, sinb, 1.f);

    flash_attn_kernel<<<dim3(S_LEN / 64, NHEADS), 128, FA_SMEM>>>(qhp, khp, vhp, at);

    // ---- join: weight prep must be done before wo GEMM ----
    cudaStreamWaitEvent(0, evJoin, 0);

    tc_gemm_kernel<<<dim3(S_LEN/256, DMODEL/128), 256, TCG_SMEM>>>(
        at, woT, h, hidden, nullptr, nullptr, nullptr, nullptr, nullptr, 0, S_LEN, DMODEL, DMODEL);

    rmsnorm_h_kernel<<<S_LEN, 256>>>(h, ln2, x2);

    // fused gate/up GEMM (N = 2*DFFN interleaved) with local SwiGLU epilogue
    tc_gemm_kernel<<<dim3(S_LEN/256, 2*DFFN/128), 256, TCG_SMEM>>>(
        x2, fwT, nullptr, nullptr, nullptr, ga, nullptr, nullptr, nullptr, 0, S_LEN, 2*DFFN, DMODEL);

    tc_gemm_kernel<<<dim3(S_LEN/256, DMODEL/128), 256, TCG_SMEM>>>(
        ga, dwT, out, h, nullptr, nullptr, nullptr, nullptr, nullptr, 0, S_LEN, DMODEL, DFFN);
}